// round 2
// baseline (speedup 1.0000x reference)
#include <cuda_runtime.h>
#include <math.h>

// Problem constants
#define BB 16
#define CC 12
#define CONDC 4
#define HH 128
#define WW 128
#define HID 64
#define STEP 23
#define HW (HH*WW)            // 16384
#define XOUT_SIZE (BB*CC*HW)  // 3145728

// Scratch (device globals — no cudaMalloc allowed)
__device__ float g_h1[BB*HID*HW];      // 64 MB
__device__ float g_h2[BB*HID*HW];      // 64 MB
__device__ float g_W1t[144*HID];       // [k=ic*9+kh*3+kw][oc]
__device__ float g_W2t[HID*HID];       // [ic][oc]
__device__ float g_W3t[CC*576*24];     // [c][k][s padded to 24]
__device__ float g_lad[BB*32];         // per-(image, tile) logdet partials

// ---------------------------------------------------------------------------
// Weight transposes: make every smem weight stage a linear float4 copy.
// ---------------------------------------------------------------------------
__global__ void k_trans(const float* __restrict__ W1,
                        const float* __restrict__ W2,
                        const float* __restrict__ W3) {
    int i = blockIdx.x * 256 + threadIdx.x;
    if (i < 144*64) {
        int k = i >> 6, oc = i & 63;
        g_W1t[i] = W1[oc*144 + k];
    }
    int j = i - 144*64;
    if (j >= 0 && j < 64*64) {
        int ic = j >> 6, oc = j & 63;
        g_W2t[j] = W2[oc*64 + ic];
    }
    int m = j - 64*64;
    if (m >= 0 && m < CC*576*24) {
        int c = m / 13824; int r = m - c*13824;
        int k = r / 24;    int s = r - k*24;
        g_W3t[m] = (s < 23) ? W3[(c*23 + s)*576 + k] : 0.f;
    }
}

// ---------------------------------------------------------------------------
// conv1 (16 -> 64, 3x3, pad 1) + ReLU.  Input z = [mask*x (12ch), cond (4ch)]
// built on the fly.  16x32 pixel tile per block, 2 px/thread, 2 oc halves.
// ---------------------------------------------------------------------------
__global__ void __launch_bounds__(256) k_conv1(const float* __restrict__ x,
                                               const float* __restrict__ cond,
                                               const float* __restrict__ b1) {
    extern __shared__ float sm[];
    float* sIn = sm;          // 16 * 612 (18x34 halo tile)
    float* sW  = sm + 9792;   // 144 * 64

    int b = blockIdx.y;
    int tile = blockIdx.x;
    int r0 = (tile >> 2) << 4;
    int c0 = (tile & 3) << 5;
    int t = threadIdx.x;

    // stage weights (linear copy)
    {
        const float4* src = (const float4*)g_W1t;
        float4* dst = (float4*)sW;
        for (int i = t; i < 9216/4; i += 256) dst[i] = src[i];
    }
    // stage input tile with halo; masked x for ch<12, conditioning for ch>=12
    for (int i = t; i < 16*612; i += 256) {
        int ch = i / 612; int rem = i - ch*612;
        int lr = rem / 34; int lc = rem - lr*34;
        int gr = r0 + lr - 1, gc = c0 + lc - 1;
        float v = 0.f;
        if ((unsigned)gr < 128u && (unsigned)gc < 128u) {
            if (ch < 12)
                v = ((gr + gc) & 1) ? x[(((b*12 + ch) << 7) + gr)*128 + gc] : 0.f;
            else
                v = cond[(((b*4 + (ch-12)) << 7) + gr)*128 + gc];
        }
        sIn[i] = v;
    }
    __syncthreads();

    int r = t >> 4, cx = (t & 15) << 1;
    int gr = r0 + r, gc = c0 + cx;

    #pragma unroll
    for (int half = 0; half < 2; half++) {
        float a0[32], a1[32];
        #pragma unroll
        for (int s = 0; s < 32; s++) { float bb = b1[half*32 + s]; a0[s] = bb; a1[s] = bb; }
        for (int ic = 0; ic < 16; ic++) {
            #pragma unroll
            for (int kh = 0; kh < 3; kh++) {
                const float* inr = &sIn[ic*612 + (r + kh)*34 + cx];
                #pragma unroll
                for (int kw = 0; kw < 3; kw++) {
                    float v0 = inr[kw];
                    float v1 = inr[kw + 1];
                    const float4* wr = (const float4*)&sW[((ic*3 + kh)*3 + kw)*64 + half*32];
                    #pragma unroll
                    for (int q = 0; q < 8; q++) {
                        float4 w = wr[q];
                        a0[q*4+0] = fmaf(w.x, v0, a0[q*4+0]); a1[q*4+0] = fmaf(w.x, v1, a1[q*4+0]);
                        a0[q*4+1] = fmaf(w.y, v0, a0[q*4+1]); a1[q*4+1] = fmaf(w.y, v1, a1[q*4+1]);
                        a0[q*4+2] = fmaf(w.z, v0, a0[q*4+2]); a1[q*4+2] = fmaf(w.z, v1, a1[q*4+2]);
                        a0[q*4+3] = fmaf(w.w, v0, a0[q*4+3]); a1[q*4+3] = fmaf(w.w, v1, a1[q*4+3]);
                    }
                }
            }
        }
        #pragma unroll
        for (int s = 0; s < 32; s++) {
            int oc = half*32 + s;
            float2 o; o.x = fmaxf(a0[s], 0.f); o.y = fmaxf(a1[s], 0.f);
            *(float2*)&g_h1[(((b*64 + oc) << 7) + gr)*128 + gc] = o;
        }
    }
}

// ---------------------------------------------------------------------------
// conv2 (64 -> 64, 1x1) + ReLU.  One pixel per thread, 64 accumulators.
// ---------------------------------------------------------------------------
__global__ void __launch_bounds__(256) k_conv2(const float* __restrict__ b2) {
    __shared__ float sW[64*64];
    __shared__ float sB[64];
    int t = threadIdx.x;
    for (int i = t; i < 4096/4; i += 256) ((float4*)sW)[i] = ((const float4*)g_W2t)[i];
    if (t < 64) sB[t] = b2[t];
    __syncthreads();

    int pix = blockIdx.x * 256 + t;
    int b = pix >> 14; int p = pix & 16383;
    const float* in = g_h1 + ((size_t)b << 20) + p;

    float acc[64];
    #pragma unroll
    for (int oc = 0; oc < 64; oc++) acc[oc] = sB[oc];

    #pragma unroll 4
    for (int ic = 0; ic < 64; ic++) {
        float v = in[ic << 14];
        const float4* wr = (const float4*)&sW[ic*64];
        #pragma unroll
        for (int q = 0; q < 16; q++) {
            float4 w = wr[q];
            acc[q*4+0] = fmaf(w.x, v, acc[q*4+0]);
            acc[q*4+1] = fmaf(w.y, v, acc[q*4+1]);
            acc[q*4+2] = fmaf(w.z, v, acc[q*4+2]);
            acc[q*4+3] = fmaf(w.w, v, acc[q*4+3]);
        }
    }
    float* outp = g_h2 + ((size_t)b << 20) + p;
    #pragma unroll
    for (int oc = 0; oc < 64; oc++) outp[oc << 14] = fmaxf(acc[oc], 0.f);
}

// ---------------------------------------------------------------------------
// Rational-quadratic spline, 8 bins, tails linear outside [-3, 3].
// p[0..7]=uw, p[8..15]=uh, p[16..22]=ud.  Register-resident scan selects the
// bin without dynamic indexing (no local-memory spills).
// ---------------------------------------------------------------------------
__device__ __forceinline__ float rqs_eval(const float* p, float xa, float& lad) {
    bool inside = (xa >= -3.f) && (xa <= 3.f);
    float xc = fminf(fmaxf(xa, -3.f), 3.f);

    float mw = p[0], mh = p[8];
    #pragma unroll
    for (int k = 1; k < 8; k++) { mw = fmaxf(mw, p[k]); mh = fmaxf(mh, p[8+k]); }
    float ew[8], eh[8]; float sw = 0.f, sh = 0.f;
    #pragma unroll
    for (int k = 0; k < 8; k++) {
        ew[k] = expf(p[k] - mw);   sw += ew[k];
        eh[k] = expf(p[8+k] - mh); sh += eh[k];
    }
    float rw = (1.f - 0.008f) / sw;   // (1 - MBW*K)/sum
    float rh = (1.f - 0.008f) / sh;

    float sp[7];
    #pragma unroll
    for (int k = 0; k < 7; k++) {
        float u = p[16 + k];
        sp[k] = (u > 15.f) ? u : log1pf(expf(u));
    }

    // scan knots; select bin = largest k in [0,7] with xc >= cw[k]
    float cw = -3.f, ch = -3.f, cumw = 0.f, cumh = 0.f, dprev = 1.f;
    float icw = -3.f, iw = 1.f, ich = -3.f, ih = 1.f, id0 = 1.f, id1 = 1.f;
    #pragma unroll
    for (int k = 0; k < 8; k++) {
        cumw += 0.001f + ew[k]*rw;             // MBW + scaled softmax
        cumh += 0.001f + eh[k]*rh;
        float cwn = (k == 7) ? 3.f : fmaf(6.f, cumw, -3.f);
        float chn = (k == 7) ? 3.f : fmaf(6.f, cumh, -3.f);
        float dn  = (k == 7) ? 1.f : (0.001f + sp[k]);   // d[k+1]; d[0]=d[8]=1
        if (xc >= cw) { icw = cw; iw = cwn - cw; ich = ch; ih = chn - ch; id0 = dprev; id1 = dn; }
        cw = cwn; ch = chn; dprev = dn;
    }

    float riw   = 1.f / iw;
    float delta = ih * riw;
    float theta = (xc - icw) * riw;
    float omt = 1.f - theta;
    float t1  = theta * omt;
    float th2 = theta * theta;
    float num = ih * (delta*th2 + id0*t1);
    float den = delta + (id0 + id1 - 2.f*delta)*t1;
    float y   = ich + num / den;
    float dnum = delta*delta*(id1*th2 + 2.f*delta*t1 + id0*omt*omt);
    float l = logf(dnum) - 2.f*logf(den);

    lad = inside ? l : 0.f;
    return inside ? y : xa;
}

// ---------------------------------------------------------------------------
// conv3 (64 -> 276, 3x3, pad 1) fused with RQS + output write + logdet partial.
// Block: 16x32 pixel tile, all 64 input ch staged (156KB) + per-c weights
// (55KB).  Thread: 2 adjacent pixels, 23 accumulators, 12 channel groups.
// ---------------------------------------------------------------------------
__global__ void __launch_bounds__(256, 1) k_conv3_rqs(const float* __restrict__ x,
                                                      const float* __restrict__ b3,
                                                      float* __restrict__ out) {
    extern __shared__ float sm[];
    float* sIn = sm;            // 64 * 612
    float* sW  = sm + 39168;    // 576 * 24

    int b = blockIdx.y;
    int tile = blockIdx.x;
    int r0 = (tile >> 2) << 4;
    int c0 = (tile & 3) << 5;
    int t = threadIdx.x;

    for (int i = t; i < 64*612; i += 256) {
        int ch = i / 612; int rem = i - ch*612;
        int lr = rem / 34; int lc = rem - lr*34;
        int gr = r0 + lr - 1, gc = c0 + lc - 1;
        float v = 0.f;
        if ((unsigned)gr < 128u && (unsigned)gc < 128u)
            v = g_h2[(((size_t)(b*64 + ch)) << 14) + (gr << 7) + gc];
        sIn[i] = v;
    }

    int r = t >> 4, cx = (t & 15) << 1;
    int gr = r0 + r, gc = c0 + cx;
    int par0 = (gr + gc) & 1;    // 1 => frozen (mask=1) at first pixel
    float ladsum = 0.f;

    for (int c = 0; c < 12; c++) {
        __syncthreads();
        {
            const float4* src = (const float4*)&g_W3t[c*13824];
            float4* dst = (float4*)sW;
            for (int i = t; i < 3456; i += 256) dst[i] = src[i];
        }
        __syncthreads();

        float a0[23], a1[23];
        #pragma unroll
        for (int s = 0; s < 23; s++) { float bb = b3[c*23 + s]; a0[s] = bb; a1[s] = bb; }

        for (int ic = 0; ic < 64; ic++) {
            #pragma unroll
            for (int kh = 0; kh < 3; kh++) {
                const float* inr = &sIn[ic*612 + (r + kh)*34 + cx];
                #pragma unroll
                for (int kw = 0; kw < 3; kw++) {
                    float v0 = inr[kw];
                    float v1 = inr[kw + 1];
                    const float4* wr = (const float4*)&sW[((ic*3 + kh)*3 + kw)*24];
                    #pragma unroll
                    for (int q = 0; q < 6; q++) {
                        float4 w = wr[q];
                        int s4 = q*4;
                        a0[s4] = fmaf(w.x, v0, a0[s4]); a1[s4] = fmaf(w.x, v1, a1[s4]);
                        if (s4+1 < 23) { a0[s4+1] = fmaf(w.y, v0, a0[s4+1]); a1[s4+1] = fmaf(w.y, v1, a1[s4+1]); }
                        if (s4+2 < 23) { a0[s4+2] = fmaf(w.z, v0, a0[s4+2]); a1[s4+2] = fmaf(w.z, v1, a1[s4+2]); }
                        if (s4+3 < 23) { a0[s4+3] = fmaf(w.w, v0, a0[s4+3]); a1[s4+3] = fmaf(w.w, v1, a1[s4+3]); }
                    }
                }
            }
        }

        // RQS epilogue for this channel, both pixels
        size_t xbase = (((size_t)(b*12 + c)) << 14) + (gr << 7) + gc;
        float xv0 = x[xbase], xv1 = x[xbase + 1];
        float xa0 = par0 ? 0.f : xv0;   // active value (even parity)
        float xf0 = par0 ? xv0 : 0.f;   // frozen value (odd parity)
        float xa1 = par0 ? xv1 : 0.f;   // neighbor has opposite parity
        float xf1 = par0 ? 0.f : xv1;

        float lad0, lad1;
        float y0 = rqs_eval(a0, xa0, lad0);
        float y1 = rqs_eval(a1, xa1, lad1);
        out[xbase]     = xf0 + y0;
        out[xbase + 1] = xf1 + y1;
        ladsum += lad0 + lad1;
    }

    // deterministic block reduction of logdet partials (reuse smem)
    __syncthreads();
    sm[t] = ladsum;
    __syncthreads();
    for (int off = 128; off > 0; off >>= 1) {
        if (t < off) sm[t] += sm[t + off];
        __syncthreads();
    }
    if (t == 0) g_lad[b*32 + tile] = sm[0];
}

// ---------------------------------------------------------------------------
// Final logdet reduction: 32 tile-partials per image + input logdet.
// ---------------------------------------------------------------------------
__global__ void k_red(const float* __restrict__ logdet_in, float* __restrict__ out) {
    int b = blockIdx.x, lane = threadIdx.x;
    float v = g_lad[b*32 + lane];
    #pragma unroll
    for (int o = 16; o > 0; o >>= 1) v += __shfl_down_sync(0xffffffffu, v, o);
    if (lane == 0) out[XOUT_SIZE + b] = logdet_in[b] + v;
}

// ---------------------------------------------------------------------------
extern "C" void kernel_launch(void* const* d_in, const int* in_sizes, int n_in,
                              void* d_out, int out_size) {
    const float* x      = (const float*)d_in[0];
    const float* logdet = (const float*)d_in[1];
    const float* cond   = (const float*)d_in[2];
    const float* W1     = (const float*)d_in[3];
    const float* b1     = (const float*)d_in[4];
    const float* W2     = (const float*)d_in[5];
    const float* b2     = (const float*)d_in[6];
    const float* W3     = (const float*)d_in[7];
    const float* b3     = (const float*)d_in[8];
    float* out = (float*)d_out;

    const int smem1 = (9792 + 9216) * 4;      // 76,032 B
    const int smem3 = (39168 + 13824) * 4;    // 211,968 B
    cudaFuncSetAttribute(k_conv1, cudaFuncAttributeMaxDynamicSharedMemorySize, smem1);
    cudaFuncSetAttribute(k_conv3_rqs, cudaFuncAttributeMaxDynamicSharedMemorySize, smem3);

    k_trans<<<700, 256>>>(W1, W2, W3);
    k_conv1<<<dim3(32, 16), 256, smem1>>>(x, cond, b1);
    k_conv2<<<1024, 256>>>(b2);
    k_conv3_rqs<<<dim3(32, 16), 256, smem3>>>(x, b3, out);
    k_red<<<16, 32>>>(logdet, out);
}

// round 4
// speedup vs baseline: 2.7201x; 2.7201x over previous
#include <cuda_runtime.h>
#include <math.h>
#include <stdint.h>

// Problem constants
#define XOUT_SIZE (16*12*128*128)

// Scratch (device globals — no cudaMalloc allowed)
__device__ __align__(16) float g_h1[16*64*128*128];   // conv1 out [b][ch][h][w]
__device__ __align__(16) float g_h2[16*128*128*64];   // conv2 out [b][h][w][ch] (tf32-rounded)
__device__ float g_W1t[144*64];                       // [k][oc]
__device__ float g_W2t[64*64];                        // [ic][oc]
__device__ __align__(16) float g_W3B[18*4*36*64];     // fragment layout [st][kk][nt][lane*2+j]
__device__ float g_lad[16*128];                       // per-(image,row) logdet partials

// ---------------------------------------------------------------------------
// helpers
// ---------------------------------------------------------------------------
__device__ __forceinline__ uint32_t s2u(const void* p){
    uint32_t a;
    asm("{ .reg .u64 t; cvta.to.shared.u64 t, %1; cvt.u32.u64 %0, t; }" : "=r"(a) : "l"(p));
    return a;
}
__device__ __forceinline__ void cp16(uint32_t dst, const void* src, uint32_t sz){
    asm volatile("cp.async.cg.shared.global [%0], [%1], 16, %2;"
                 :: "r"(dst), "l"(src), "r"(sz) : "memory");
}
#define CP_COMMIT() asm volatile("cp.async.commit_group;" ::: "memory")

__device__ __forceinline__ float rna(float v){
    uint32_t o;
    asm("cvt.rna.tf32.f32 %0, %1;" : "=r"(o) : "f"(v));
    return __uint_as_float(o);
}

__device__ __forceinline__ void mma_tf32(float* d, uint32_t a0, uint32_t a1,
                                         uint32_t a2, uint32_t a3,
                                         uint32_t b0, uint32_t b1){
    asm volatile(
        "mma.sync.aligned.m16n8k8.row.col.f32.tf32.tf32.f32 "
        "{%0,%1,%2,%3}, {%4,%5,%6,%7}, {%8,%9}, {%0,%1,%2,%3};"
        : "+f"(d[0]), "+f"(d[1]), "+f"(d[2]), "+f"(d[3])
        : "r"(a0), "r"(a1), "r"(a2), "r"(a3), "r"(b0), "r"(b1));
}

// ---------------------------------------------------------------------------
// Weight transposes. W3 is packed directly into the m16n8k8 B-fragment
// layout: for stage st (tap=st>>1, ih=st&1), k-step kk (0..3), n-tile nt
// (0..35), lane l, j in {0,1}:
//   value = W3[n = nt*8 + (l>>2)][ic = ih*32 + kk*8 + (l&3) + 4*j][tap]
// ---------------------------------------------------------------------------
__global__ void k_trans(const float* __restrict__ W1,
                        const float* __restrict__ W2,
                        const float* __restrict__ W3) {
    int i = blockIdx.x * 256 + threadIdx.x;
    if (i < 144*64) {
        int k = i >> 6, oc = i & 63;
        g_W1t[i] = W1[oc*144 + k];
    }
    int j = i - 144*64;
    if (j >= 0 && j < 64*64) {
        int ic = j >> 6, oc = j & 63;
        g_W2t[j] = W2[oc*64 + ic];
    }
    int m = j - 64*64;
    if (m >= 0 && m < 18*4*36*64) {
        int st  = m / 9216;  int r1 = m - st*9216;
        int kk  = r1 / 2304; int r2 = r1 - kk*2304;
        int nt  = r2 >> 6;   int l2 = r2 & 63;
        int lane = l2 >> 1,  jj = l2 & 1;
        int n   = nt*8 + (lane >> 2);
        int k32 = kk*8 + (lane & 3) + 4*jj;
        int tap = st >> 1, ih = st & 1;
        int ic  = ih*32 + k32;
        int c   = n / 24, s = n - c*24;
        float v = 0.f;
        if (s < 23)
            v = rna(W3[(c*23 + s)*576 + ic*9 + tap]);
        g_W3B[m] = v;
    }
}

// ---------------------------------------------------------------------------
// conv1 (16 -> 64, 3x3, pad 1) + ReLU (validated in R1)
// ---------------------------------------------------------------------------
__global__ void __launch_bounds__(256) k_conv1(const float* __restrict__ x,
                                               const float* __restrict__ cond,
                                               const float* __restrict__ b1) {
    extern __shared__ float sm[];
    float* sIn = sm;          // 16 * 612 (18x34 halo tile)
    float* sW  = sm + 9792;   // 144 * 64

    int b = blockIdx.y;
    int tile = blockIdx.x;
    int r0 = (tile >> 2) << 4;
    int c0 = (tile & 3) << 5;
    int t = threadIdx.x;

    {
        const float4* src = (const float4*)g_W1t;
        float4* dst = (float4*)sW;
        for (int i = t; i < 9216/4; i += 256) dst[i] = src[i];
    }
    for (int i = t; i < 16*612; i += 256) {
        int ch = i / 612; int rem = i - ch*612;
        int lr = rem / 34; int lc = rem - lr*34;
        int gr = r0 + lr - 1, gc = c0 + lc - 1;
        float v = 0.f;
        if ((unsigned)gr < 128u && (unsigned)gc < 128u) {
            if (ch < 12)
                v = ((gr + gc) & 1) ? x[(((b*12 + ch) << 7) + gr)*128 + gc] : 0.f;
            else
                v = cond[(((b*4 + (ch-12)) << 7) + gr)*128 + gc];
        }
        sIn[i] = v;
    }
    __syncthreads();

    int r = t >> 4, cx = (t & 15) << 1;
    int gr = r0 + r, gc = c0 + cx;

    #pragma unroll
    for (int half = 0; half < 2; half++) {
        float a0[32], a1[32];
        #pragma unroll
        for (int s = 0; s < 32; s++) { float bb = b1[half*32 + s]; a0[s] = bb; a1[s] = bb; }
        for (int ic = 0; ic < 16; ic++) {
            #pragma unroll
            for (int kh = 0; kh < 3; kh++) {
                const float* inr = &sIn[ic*612 + (r + kh)*34 + cx];
                #pragma unroll
                for (int kw = 0; kw < 3; kw++) {
                    float v0 = inr[kw];
                    float v1 = inr[kw + 1];
                    const float4* wr = (const float4*)&sW[((ic*3 + kh)*3 + kw)*64 + half*32];
                    #pragma unroll
                    for (int q = 0; q < 8; q++) {
                        float4 w = wr[q];
                        a0[q*4+0] = fmaf(w.x, v0, a0[q*4+0]); a1[q*4+0] = fmaf(w.x, v1, a1[q*4+0]);
                        a0[q*4+1] = fmaf(w.y, v0, a0[q*4+1]); a1[q*4+1] = fmaf(w.y, v1, a1[q*4+1]);
                        a0[q*4+2] = fmaf(w.z, v0, a0[q*4+2]); a1[q*4+2] = fmaf(w.z, v1, a1[q*4+2]);
                        a0[q*4+3] = fmaf(w.w, v0, a0[q*4+3]); a1[q*4+3] = fmaf(w.w, v1, a1[q*4+3]);
                    }
                }
            }
        }
        #pragma unroll
        for (int s = 0; s < 32; s++) {
            int oc = half*32 + s;
            float2 o; o.x = fmaxf(a0[s], 0.f); o.y = fmaxf(a1[s], 0.f);
            *(float2*)&g_h1[(((b*64 + oc) << 7) + gr)*128 + gc] = o;
        }
    }
}

// ---------------------------------------------------------------------------
// conv2 (64 -> 64, 1x1) + ReLU -> transposed [b][pix][ch] layout, tf32-rounded
// ---------------------------------------------------------------------------
__global__ void __launch_bounds__(256) k_conv2(const float* __restrict__ b2) {
    __shared__ float sW[64*64];
    __shared__ float sB[64];
    int t = threadIdx.x;
    for (int i = t; i < 4096/4; i += 256) ((float4*)sW)[i] = ((const float4*)g_W2t)[i];
    if (t < 64) sB[t] = b2[t];
    __syncthreads();

    int pix = blockIdx.x * 256 + t;
    int b = pix >> 14; int p = pix & 16383;
    const float* in = g_h1 + ((size_t)b << 20) + p;

    float acc[64];
    #pragma unroll
    for (int oc = 0; oc < 64; oc++) acc[oc] = sB[oc];

    #pragma unroll 4
    for (int ic = 0; ic < 64; ic++) {
        float v = in[ic << 14];
        const float4* wr = (const float4*)&sW[ic*64];
        #pragma unroll
        for (int q = 0; q < 16; q++) {
            float4 w = wr[q];
            acc[q*4+0] = fmaf(w.x, v, acc[q*4+0]);
            acc[q*4+1] = fmaf(w.y, v, acc[q*4+1]);
            acc[q*4+2] = fmaf(w.z, v, acc[q*4+2]);
            acc[q*4+3] = fmaf(w.w, v, acc[q*4+3]);
        }
    }
    float4* outp = (float4*)(g_h2 + (size_t)pix * 64);
    #pragma unroll
    for (int q = 0; q < 16; q++) {
        float4 o;
        o.x = rna(fmaxf(acc[q*4+0], 0.f)); o.y = rna(fmaxf(acc[q*4+1], 0.f));
        o.z = rna(fmaxf(acc[q*4+2], 0.f)); o.w = rna(fmaxf(acc[q*4+3], 0.f));
        outp[q] = o;
    }
}

// ---------------------------------------------------------------------------
// RQS spline (register-resident 8-bin scan) — validated in R1
// ---------------------------------------------------------------------------
__device__ __forceinline__ float rqs_eval(const float* p, float xa, float& lad) {
    bool inside = (xa >= -3.f) && (xa <= 3.f);
    float xc = fminf(fmaxf(xa, -3.f), 3.f);

    float mw = p[0], mh = p[8];
    #pragma unroll
    for (int k = 1; k < 8; k++) { mw = fmaxf(mw, p[k]); mh = fmaxf(mh, p[8+k]); }
    float ew[8], eh[8]; float sw = 0.f, sh = 0.f;
    #pragma unroll
    for (int k = 0; k < 8; k++) {
        ew[k] = expf(p[k] - mw);   sw += ew[k];
        eh[k] = expf(p[8+k] - mh); sh += eh[k];
    }
    float rw = (1.f - 0.008f) / sw;
    float rh = (1.f - 0.008f) / sh;

    float sp[7];
    #pragma unroll
    for (int k = 0; k < 7; k++) {
        float u = p[16 + k];
        sp[k] = (u > 15.f) ? u : log1pf(expf(u));
    }

    float cw = -3.f, ch = -3.f, cumw = 0.f, cumh = 0.f, dprev = 1.f;
    float icw = -3.f, iw = 1.f, ich = -3.f, ih = 1.f, id0 = 1.f, id1 = 1.f;
    #pragma unroll
    for (int k = 0; k < 8; k++) {
        cumw += 0.001f + ew[k]*rw;
        cumh += 0.001f + eh[k]*rh;
        float cwn = (k == 7) ? 3.f : fmaf(6.f, cumw, -3.f);
        float chn = (k == 7) ? 3.f : fmaf(6.f, cumh, -3.f);
        float dn  = (k == 7) ? 1.f : (0.001f + sp[k]);
        if (xc >= cw) { icw = cw; iw = cwn - cw; ich = ch; ih = chn - ch; id0 = dprev; id1 = dn; }
        cw = cwn; ch = chn; dprev = dn;
    }

    float riw   = 1.f / iw;
    float delta = ih * riw;
    float theta = (xc - icw) * riw;
    float omt = 1.f - theta;
    float t1  = theta * omt;
    float th2 = theta * theta;
    float num = ih * (delta*th2 + id0*t1);
    float den = delta + (id0 + id1 - 2.f*delta)*t1;
    float y   = ich + num / den;
    float dnum = delta*delta*(id1*th2 + 2.f*delta*t1 + id0*omt*omt);
    float l = logf(dnum) - 2.f*logf(den);

    lad = inside ? l : 0.f;
    return inside ? y : xa;
}

// ---------------------------------------------------------------------------
// conv3 via mma.sync tf32 (m16n8k8) + fused RQS epilogue.
// CTA = one image row: M=128 px, N=288, K=576 in 18 stages of 32.
// 512 threads = 16 warps: warp = (px-block 16) x (N-half 144).
// 4-slot cp.async ring: slot = A (128x36 floats, pitch 36) + B (fragment
// layout, 4 ksteps x 36 ntiles x 32 lanes x float2) = 55296 B.
// ---------------------------------------------------------------------------
__device__ __forceinline__ void issue_stage(int st, int t, int b, int gr, uint32_t base){
    int tap = st >> 1, ih = st & 1;
    int kh = tap / 3;
    int dh = kh - 1;
    int dw = (tap - kh*3) - 1;
    uint32_t aslot = base + (uint32_t)(st & 3) * 55296u;
    int grs = gr + dh;
    bool rowok = (unsigned)grs < 128u;
    const float* h2row = g_h2 + ((size_t)(b * 128 + (rowok ? grs : 0)) * 128) * 64;

    // A: 128 px rows x 32 floats (pitch 36 floats = 144 B), shifted by dw
    #pragma unroll
    for (int it = 0; it < 2; it++) {
        int id = it * 512 + t;
        int p = id >> 3, q = id & 7;
        int pw = p + dw;
        bool ok = rowok && ((unsigned)pw < 128u);
        const float* src = h2row + ((ok ? pw : 0) * 64 + ih * 32 + q * 4);
        cp16(aslot + (uint32_t)(p * 144 + q * 16), src, ok ? 16u : 0u);
    }
    // B: linear 36864 B from fragment-packed g_W3B
    const float* wb = g_W3B + (size_t)st * 9216;
    for (int i = t; i < 2304; i += 512)
        cp16(aslot + 18432u + (uint32_t)(i * 16), wb + i * 4, 16u);
    CP_COMMIT();
}

__global__ void __launch_bounds__(512, 1) k_conv3_mma(const float* __restrict__ x,
                                                      const float* __restrict__ b3,
                                                      float* __restrict__ out) {
    extern __shared__ float dyn[];
    __shared__ float s_b3[276];
    __shared__ float s_red[16];

    int b  = blockIdx.y;
    int gr = blockIdx.x;
    int t  = threadIdx.x;
    int w = t >> 5, lane = t & 31;
    int g = lane >> 2, tig = lane & 3;
    int px0 = (w & 7) * 16;
    int hh  = w >> 3;            // N half: 0 or 1

    uint32_t base = s2u(dyn);

    for (int i = t; i < 276; i += 512) s_b3[i] = b3[i];

    float d[72];
    #pragma unroll
    for (int i = 0; i < 72; i++) d[i] = 0.f;

    // prologue: 3 stages in flight
    issue_stage(0, t, b, gr, base);
    issue_stage(1, t, b, gr, base);
    issue_stage(2, t, b, gr, base);

    for (int s = 0; s < 18; s++) {
        if (s < 16)       asm volatile("cp.async.wait_group 2;" ::: "memory");
        else if (s == 16) asm volatile("cp.async.wait_group 1;" ::: "memory");
        else              asm volatile("cp.async.wait_group 0;" ::: "memory");
        __syncthreads();                       // stage s resident; s-1 fully consumed

        if (s < 15) issue_stage(s + 3, t, b, gr, base);

        const float* sA = dyn + (size_t)(s & 3) * 13824;
        const float2* sB = (const float2*)(sA + 4608) + (size_t)hh * 18 * 32 + lane;

        #pragma unroll
        for (int kk = 0; kk < 4; kk++) {
            const float* ar = sA + kk*8;
            uint32_t a0 = __float_as_uint(ar[(px0+g  )*36 + tig    ]);
            uint32_t a1 = __float_as_uint(ar[(px0+g+8)*36 + tig    ]);
            uint32_t a2 = __float_as_uint(ar[(px0+g  )*36 + tig + 4]);
            uint32_t a3 = __float_as_uint(ar[(px0+g+8)*36 + tig + 4]);
            const float2* bp = sB + (size_t)kk * 36 * 32;
            #pragma unroll
            for (int nt = 0; nt < 18; nt++) {
                float2 bb = bp[nt * 32];
                mma_tf32(&d[nt*4], a0, a1, a2, a3,
                         __float_as_uint(bb.x), __float_as_uint(bb.y));
            }
        }
    }

    // store accumulators to smem (pitch 289 floats -> conflict-free spline reads)
    __syncthreads();
    {
        float* sD = dyn;
        int row0 = px0 + g;
        #pragma unroll
        for (int nt = 0; nt < 18; nt++) {
            int col = hh*144 + nt*8 + 2*tig;
            sD[ row0      * 289 + col    ] = d[nt*4+0];
            sD[ row0      * 289 + col + 1] = d[nt*4+1];
            sD[(row0 + 8) * 289 + col    ] = d[nt*4+2];
            sD[(row0 + 8) * 289 + col + 1] = d[nt*4+3];
        }
    }
    __syncthreads();

    // spline: 512 threads, each does one pixel x 3 channels
    float ladsum = 0.f;
    {
        const float* sD = dyn;
        int px = t & 127;
        int cbase = (t >> 7) * 3;
        int par = (gr + px) & 1;    // 1 => frozen
        #pragma unroll
        for (int cc = 0; cc < 3; cc++) {
            int c = cbase + cc;
            float p[23];
            #pragma unroll
            for (int sidx = 0; sidx < 23; sidx++)
                p[sidx] = sD[px*289 + c*24 + sidx] + s_b3[c*23 + sidx];

            size_t xbase = (((size_t)(b*12 + c)) << 14) + ((size_t)gr << 7) + px;
            float xv = x[xbase];
            float xa = par ? 0.f : xv;
            float xf = par ? xv : 0.f;
            float lad;
            float y = rqs_eval(p, xa, lad);
            out[xbase] = xf + y;
            ladsum += lad;
        }
    }
    #pragma unroll
    for (int o = 16; o > 0; o >>= 1)
        ladsum += __shfl_down_sync(0xffffffffu, ladsum, o);
    if (lane == 0) s_red[w] = ladsum;
    __syncthreads();
    if (t == 0) {
        float v = 0.f;
        #pragma unroll
        for (int i = 0; i < 16; i++) v += s_red[i];
        g_lad[b*128 + gr] = v;
    }
}

// ---------------------------------------------------------------------------
// Final logdet reduction: 128 row-partials per image + input logdet.
// ---------------------------------------------------------------------------
__global__ void k_red(const float* __restrict__ logdet_in, float* __restrict__ out) {
    __shared__ float s[4];
    int b = blockIdx.x, t = threadIdx.x;
    float v = g_lad[b*128 + t];
    #pragma unroll
    for (int o = 16; o > 0; o >>= 1) v += __shfl_down_sync(0xffffffffu, v, o);
    if ((t & 31) == 0) s[t >> 5] = v;
    __syncthreads();
    if (t == 0) out[XOUT_SIZE + b] = logdet_in[b] + s[0] + s[1] + s[2] + s[3];
}

// ---------------------------------------------------------------------------
extern "C" void kernel_launch(void* const* d_in, const int* in_sizes, int n_in,
                              void* d_out, int out_size) {
    const float* x      = (const float*)d_in[0];
    const float* logdet = (const float*)d_in[1];
    const float* cond   = (const float*)d_in[2];
    const float* W1     = (const float*)d_in[3];
    const float* b1     = (const float*)d_in[4];
    const float* W2     = (const float*)d_in[5];
    const float* b2     = (const float*)d_in[6];
    const float* W3     = (const float*)d_in[7];
    const float* b3     = (const float*)d_in[8];
    float* out = (float*)d_out;

    const int smem1 = (9792 + 9216) * 4;     // 76,032 B
    const int smem3 = 4 * 55296;             // 221,184 B
    cudaFuncSetAttribute(k_conv1, cudaFuncAttributeMaxDynamicSharedMemorySize, smem1);
    cudaFuncSetAttribute(k_conv3_mma, cudaFuncAttributeMaxDynamicSharedMemorySize, smem3);

    k_trans<<<700, 256>>>(W1, W2, W3);
    k_conv1<<<dim3(32, 16), 256, smem1>>>(x, cond, b1);
    k_conv2<<<1024, 256>>>(b2);
    k_conv3_mma<<<dim3(128, 16), 512, smem3>>>(x, b3, out);
    k_red<<<16, 128>>>(logdet, out);
}

// round 5
// speedup vs baseline: 2.7383x; 1.0067x over previous
#include <cuda_runtime.h>
#include <math.h>
#include <stdint.h>

// Problem constants
#define XOUT_SIZE (16*12*128*128)

// Scratch (device globals — no cudaMalloc allowed)
__device__ __align__(16) float g_h1[16*64*128*128];   // conv1 out [b][ch][h][w]
__device__ __align__(16) float g_h2[16*128*128*64];   // conv2 out [b][h][w][ch] (tf32-rounded)
__device__ float g_W1t[144*64];                       // [k][oc]
__device__ float g_W2t[64*64];                        // [ic][oc]
__device__ __align__(16) float g_W3B[18*4*36*64];     // fragment layout [st][kk][nt][lane*2+j]
__device__ float g_lad[16*128];                       // per-(image,row) logdet partials

// ---------------------------------------------------------------------------
// helpers
// ---------------------------------------------------------------------------
__device__ __forceinline__ uint32_t s2u(const void* p){
    uint32_t a;
    asm("{ .reg .u64 t; cvta.to.shared.u64 t, %1; cvt.u32.u64 %0, t; }" : "=r"(a) : "l"(p));
    return a;
}
__device__ __forceinline__ void cp16(uint32_t dst, const void* src, uint32_t sz){
    asm volatile("cp.async.cg.shared.global [%0], [%1], 16, %2;"
                 :: "r"(dst), "l"(src), "r"(sz) : "memory");
}
#define CP_COMMIT() asm volatile("cp.async.commit_group;" ::: "memory")

__device__ __forceinline__ float rna(float v){
    uint32_t o;
    asm("cvt.rna.tf32.f32 %0, %1;" : "=r"(o) : "f"(v));
    return __uint_as_float(o);
}

__device__ __forceinline__ void mma_tf32(float* d, uint32_t a0, uint32_t a1,
                                         uint32_t a2, uint32_t a3,
                                         uint32_t b0, uint32_t b1){
    asm volatile(
        "mma.sync.aligned.m16n8k8.row.col.f32.tf32.tf32.f32 "
        "{%0,%1,%2,%3}, {%4,%5,%6,%7}, {%8,%9}, {%0,%1,%2,%3};"
        : "+f"(d[0]), "+f"(d[1]), "+f"(d[2]), "+f"(d[3])
        : "r"(a0), "r"(a1), "r"(a2), "r"(a3), "r"(b0), "r"(b1));
}

// ---------------------------------------------------------------------------
// Weight transposes. W3 packed into m16n8k8 B-fragment layout:
// [st][kk][nt][lane*2+j] = W3[n = nt*8 + (lane>>2)][ic = ih*32 + kk*8 + (lane&3) + 4*j][tap]
// ---------------------------------------------------------------------------
__global__ void k_trans(const float* __restrict__ W1,
                        const float* __restrict__ W2,
                        const float* __restrict__ W3) {
    int i = blockIdx.x * 256 + threadIdx.x;
    if (i < 144*64) {
        int k = i >> 6, oc = i & 63;
        g_W1t[i] = W1[oc*144 + k];
    }
    int j = i - 144*64;
    if (j >= 0 && j < 64*64) {
        int ic = j >> 6, oc = j & 63;
        g_W2t[j] = W2[oc*64 + ic];
    }
    int m = j - 64*64;
    if (m >= 0 && m < 18*4*36*64) {
        int st  = m / 9216;  int r1 = m - st*9216;
        int kk  = r1 / 2304; int r2 = r1 - kk*2304;
        int nt  = r2 >> 6;   int l2 = r2 & 63;
        int lane = l2 >> 1,  jj = l2 & 1;
        int n   = nt*8 + (lane >> 2);
        int k32 = kk*8 + (lane & 3) + 4*jj;
        int tap = st >> 1, ih = st & 1;
        int ic  = ih*32 + k32;
        int c   = n / 24, s = n - c*24;
        float v = 0.f;
        if (s < 23)
            v = rna(W3[(c*23 + s)*576 + ic*9 + tap]);
        g_W3B[m] = v;
    }
}

// ---------------------------------------------------------------------------
// conv1 (16 -> 64, 3x3, pad 1) + ReLU (validated in R1)
// ---------------------------------------------------------------------------
__global__ void __launch_bounds__(256) k_conv1(const float* __restrict__ x,
                                               const float* __restrict__ cond,
                                               const float* __restrict__ b1) {
    extern __shared__ float sm[];
    float* sIn = sm;          // 16 * 612 (18x34 halo tile)
    float* sW  = sm + 9792;   // 144 * 64

    int b = blockIdx.y;
    int tile = blockIdx.x;
    int r0 = (tile >> 2) << 4;
    int c0 = (tile & 3) << 5;
    int t = threadIdx.x;

    {
        const float4* src = (const float4*)g_W1t;
        float4* dst = (float4*)sW;
        for (int i = t; i < 9216/4; i += 256) dst[i] = src[i];
    }
    for (int i = t; i < 16*612; i += 256) {
        int ch = i / 612; int rem = i - ch*612;
        int lr = rem / 34; int lc = rem - lr*34;
        int gr = r0 + lr - 1, gc = c0 + lc - 1;
        float v = 0.f;
        if ((unsigned)gr < 128u && (unsigned)gc < 128u) {
            if (ch < 12)
                v = ((gr + gc) & 1) ? x[(((b*12 + ch) << 7) + gr)*128 + gc] : 0.f;
            else
                v = cond[(((b*4 + (ch-12)) << 7) + gr)*128 + gc];
        }
        sIn[i] = v;
    }
    __syncthreads();

    int r = t >> 4, cx = (t & 15) << 1;
    int gr = r0 + r, gc = c0 + cx;

    #pragma unroll
    for (int half = 0; half < 2; half++) {
        float a0[32], a1[32];
        #pragma unroll
        for (int s = 0; s < 32; s++) { float bb = b1[half*32 + s]; a0[s] = bb; a1[s] = bb; }
        for (int ic = 0; ic < 16; ic++) {
            #pragma unroll
            for (int kh = 0; kh < 3; kh++) {
                const float* inr = &sIn[ic*612 + (r + kh)*34 + cx];
                #pragma unroll
                for (int kw = 0; kw < 3; kw++) {
                    float v0 = inr[kw];
                    float v1 = inr[kw + 1];
                    const float4* wr = (const float4*)&sW[((ic*3 + kh)*3 + kw)*64 + half*32];
                    #pragma unroll
                    for (int q = 0; q < 8; q++) {
                        float4 w = wr[q];
                        a0[q*4+0] = fmaf(w.x, v0, a0[q*4+0]); a1[q*4+0] = fmaf(w.x, v1, a1[q*4+0]);
                        a0[q*4+1] = fmaf(w.y, v0, a0[q*4+1]); a1[q*4+1] = fmaf(w.y, v1, a1[q*4+1]);
                        a0[q*4+2] = fmaf(w.z, v0, a0[q*4+2]); a1[q*4+2] = fmaf(w.z, v1, a1[q*4+2]);
                        a0[q*4+3] = fmaf(w.w, v0, a0[q*4+3]); a1[q*4+3] = fmaf(w.w, v1, a1[q*4+3]);
                    }
                }
            }
        }
        #pragma unroll
        for (int s = 0; s < 32; s++) {
            int oc = half*32 + s;
            float2 o; o.x = fmaxf(a0[s], 0.f); o.y = fmaxf(a1[s], 0.f);
            *(float2*)&g_h1[(((b*64 + oc) << 7) + gr)*128 + gc] = o;
        }
    }
}

// ---------------------------------------------------------------------------
// conv2 (64 -> 64, 1x1) + ReLU -> transposed [b][pix][ch] layout, tf32-rounded
// ---------------------------------------------------------------------------
__global__ void __launch_bounds__(256) k_conv2(const float* __restrict__ b2) {
    __shared__ float sW[64*64];
    __shared__ float sB[64];
    int t = threadIdx.x;
    for (int i = t; i < 4096/4; i += 256) ((float4*)sW)[i] = ((const float4*)g_W2t)[i];
    if (t < 64) sB[t] = b2[t];
    __syncthreads();

    int pix = blockIdx.x * 256 + t;
    int b = pix >> 14; int p = pix & 16383;
    const float* in = g_h1 + ((size_t)b << 20) + p;

    float acc[64];
    #pragma unroll
    for (int oc = 0; oc < 64; oc++) acc[oc] = sB[oc];

    #pragma unroll 4
    for (int ic = 0; ic < 64; ic++) {
        float v = in[ic << 14];
        const float4* wr = (const float4*)&sW[ic*64];
        #pragma unroll
        for (int q = 0; q < 16; q++) {
            float4 w = wr[q];
            acc[q*4+0] = fmaf(w.x, v, acc[q*4+0]);
            acc[q*4+1] = fmaf(w.y, v, acc[q*4+1]);
            acc[q*4+2] = fmaf(w.z, v, acc[q*4+2]);
            acc[q*4+3] = fmaf(w.w, v, acc[q*4+3]);
        }
    }
    float4* outp = (float4*)(g_h2 + (size_t)pix * 64);
    #pragma unroll
    for (int q = 0; q < 16; q++) {
        float4 o;
        o.x = rna(fmaxf(acc[q*4+0], 0.f)); o.y = rna(fmaxf(acc[q*4+1], 0.f));
        o.z = rna(fmaxf(acc[q*4+2], 0.f)); o.w = rna(fmaxf(acc[q*4+3], 0.f));
        outp[q] = o;
    }
}

// ---------------------------------------------------------------------------
// RQS spline (register-resident 8-bin scan) — validated in R1
// ---------------------------------------------------------------------------
__device__ __forceinline__ float rqs_eval(const float* p, float xa, float& lad) {
    bool inside = (xa >= -3.f) && (xa <= 3.f);
    float xc = fminf(fmaxf(xa, -3.f), 3.f);

    float mw = p[0], mh = p[8];
    #pragma unroll
    for (int k = 1; k < 8; k++) { mw = fmaxf(mw, p[k]); mh = fmaxf(mh, p[8+k]); }
    float ew[8], eh[8]; float sw = 0.f, sh = 0.f;
    #pragma unroll
    for (int k = 0; k < 8; k++) {
        ew[k] = expf(p[k] - mw);   sw += ew[k];
        eh[k] = expf(p[8+k] - mh); sh += eh[k];
    }
    float rw = (1.f - 0.008f) / sw;
    float rh = (1.f - 0.008f) / sh;

    float sp[7];
    #pragma unroll
    for (int k = 0; k < 7; k++) {
        float u = p[16 + k];
        sp[k] = (u > 15.f) ? u : log1pf(expf(u));
    }

    float cw = -3.f, ch = -3.f, cumw = 0.f, cumh = 0.f, dprev = 1.f;
    float icw = -3.f, iw = 1.f, ich = -3.f, ih = 1.f, id0 = 1.f, id1 = 1.f;
    #pragma unroll
    for (int k = 0; k < 8; k++) {
        cumw += 0.001f + ew[k]*rw;
        cumh += 0.001f + eh[k]*rh;
        float cwn = (k == 7) ? 3.f : fmaf(6.f, cumw, -3.f);
        float chn = (k == 7) ? 3.f : fmaf(6.f, cumh, -3.f);
        float dn  = (k == 7) ? 1.f : (0.001f + sp[k]);
        if (xc >= cw) { icw = cw; iw = cwn - cw; ich = ch; ih = chn - ch; id0 = dprev; id1 = dn; }
        cw = cwn; ch = chn; dprev = dn;
    }

    float riw   = 1.f / iw;
    float delta = ih * riw;
    float theta = (xc - icw) * riw;
    float omt = 1.f - theta;
    float t1  = theta * omt;
    float th2 = theta * theta;
    float num = ih * (delta*th2 + id0*t1);
    float den = delta + (id0 + id1 - 2.f*delta)*t1;
    float y   = ich + num / den;
    float dnum = delta*delta*(id1*th2 + 2.f*delta*t1 + id0*omt*omt);
    float l = logf(dnum) - 2.f*logf(den);

    lad = inside ? l : 0.f;
    return inside ? y : xa;
}

// ---------------------------------------------------------------------------
// conv3 via mma.sync tf32 (m16n8k8) + fused RQS epilogue.
// CTA = one image row: M=128 px, N=288, K=576 in 18 stages of 32.
// 256 threads = 8 warps: warp = (px-block of 32: two m16 tiles) x (N-half 144).
// Each B fragment LDS.64 feeds TWO MMAs -> B smem re-reads halved vs R4.
// 4-slot cp.async ring: slot = A (128x36 floats, pitch 36) + B (fragment
// layout) = 55296 B.
// ---------------------------------------------------------------------------
__device__ __forceinline__ void issue_stage(int st, int t, int b, int gr, uint32_t base){
    int tap = st >> 1, ih = st & 1;
    int kh = tap / 3;
    int dh = kh - 1;
    int dw = (tap - kh*3) - 1;
    uint32_t aslot = base + (uint32_t)(st & 3) * 55296u;
    int grs = gr + dh;
    bool rowok = (unsigned)grs < 128u;
    const float* h2row = g_h2 + ((size_t)(b * 128 + (rowok ? grs : 0)) * 128) * 64;

    // A: 128 px rows x 32 floats (pitch 36 floats = 144 B), shifted by dw
    #pragma unroll
    for (int it = 0; it < 4; it++) {
        int id = it * 256 + t;
        int p = id >> 3, q = id & 7;
        int pw = p + dw;
        bool ok = rowok && ((unsigned)pw < 128u);
        const float* src = h2row + ((ok ? pw : 0) * 64 + ih * 32 + q * 4);
        cp16(aslot + (uint32_t)(p * 144 + q * 16), src, ok ? 16u : 0u);
    }
    // B: linear 36864 B from fragment-packed g_W3B
    const float* wb = g_W3B + (size_t)st * 9216;
    #pragma unroll
    for (int it = 0; it < 9; it++) {
        int i = it * 256 + t;
        cp16(aslot + 18432u + (uint32_t)(i * 16), wb + i * 4, 16u);
    }
    CP_COMMIT();
}

__global__ void __launch_bounds__(256, 1) k_conv3_mma(const float* __restrict__ x,
                                                      const float* __restrict__ b3,
                                                      float* __restrict__ out) {
    extern __shared__ float dyn[];
    __shared__ float s_b3[276];
    __shared__ float s_red[8];

    int b  = blockIdx.y;
    int gr = blockIdx.x;
    int t  = threadIdx.x;
    int w = t >> 5, lane = t & 31;
    int g = lane >> 2, tig = lane & 3;
    int px0 = (w & 3) * 32;      // two m16 tiles: rows px0..px0+31
    int hh  = w >> 2;            // N half: 0 or 1

    uint32_t base = s2u(dyn);

    for (int i = t; i < 276; i += 256) s_b3[i] = b3[i];

    // d[nt*8 + m*4 + j]: nt 0..17, m = tile (0/1), j = frag element
    float d[144];
    #pragma unroll
    for (int i = 0; i < 144; i++) d[i] = 0.f;

    // prologue: 3 stages in flight
    issue_stage(0, t, b, gr, base);
    issue_stage(1, t, b, gr, base);
    issue_stage(2, t, b, gr, base);

    for (int s = 0; s < 18; s++) {
        if (s < 16)       asm volatile("cp.async.wait_group 2;" ::: "memory");
        else if (s == 16) asm volatile("cp.async.wait_group 1;" ::: "memory");
        else              asm volatile("cp.async.wait_group 0;" ::: "memory");
        __syncthreads();                       // stage s resident; s-1 fully consumed

        if (s < 15) issue_stage(s + 3, t, b, gr, base);

        const float* sA = dyn + (size_t)(s & 3) * 13824;
        const float2* sB = (const float2*)(sA + 4608) + (size_t)hh * 18 * 32 + lane;

        #pragma unroll
        for (int kk = 0; kk < 4; kk++) {
            const float* ar = sA + kk*8;
            // tile 0 (rows px0..px0+15) and tile 1 (rows px0+16..px0+31)
            uint32_t a00 = __float_as_uint(ar[(px0+g   )*36 + tig    ]);
            uint32_t a01 = __float_as_uint(ar[(px0+g+ 8)*36 + tig    ]);
            uint32_t a02 = __float_as_uint(ar[(px0+g   )*36 + tig + 4]);
            uint32_t a03 = __float_as_uint(ar[(px0+g+ 8)*36 + tig + 4]);
            uint32_t a10 = __float_as_uint(ar[(px0+g+16)*36 + tig    ]);
            uint32_t a11 = __float_as_uint(ar[(px0+g+24)*36 + tig    ]);
            uint32_t a12 = __float_as_uint(ar[(px0+g+16)*36 + tig + 4]);
            uint32_t a13 = __float_as_uint(ar[(px0+g+24)*36 + tig + 4]);
            const float2* bp = sB + (size_t)kk * 36 * 32;
            #pragma unroll
            for (int nt = 0; nt < 18; nt++) {
                float2 bb = bp[nt * 32];
                uint32_t b0 = __float_as_uint(bb.x), b1 = __float_as_uint(bb.y);
                mma_tf32(&d[nt*8],     a00, a01, a02, a03, b0, b1);
                mma_tf32(&d[nt*8 + 4], a10, a11, a12, a13, b0, b1);
            }
        }
    }

    // store accumulators to smem (pitch 289 floats -> conflict-free spline reads)
    __syncthreads();
    {
        float* sD = dyn;
        #pragma unroll
        for (int m = 0; m < 2; m++) {
            int row0 = px0 + m*16 + g;
            #pragma unroll
            for (int nt = 0; nt < 18; nt++) {
                int col = hh*144 + nt*8 + 2*tig;
                sD[ row0      * 289 + col    ] = d[nt*8 + m*4 + 0];
                sD[ row0      * 289 + col + 1] = d[nt*8 + m*4 + 1];
                sD[(row0 + 8) * 289 + col    ] = d[nt*8 + m*4 + 2];
                sD[(row0 + 8) * 289 + col + 1] = d[nt*8 + m*4 + 3];
            }
        }
    }
    __syncthreads();

    // spline: 256 threads, each does one pixel x 6 channels
    float ladsum = 0.f;
    {
        const float* sD = dyn;
        int px = t & 127;
        int cbase = (t >> 7) * 6;
        int par = (gr + px) & 1;    // 1 => frozen
        #pragma unroll
        for (int cc = 0; cc < 6; cc++) {
            int c = cbase + cc;
            float p[23];
            #pragma unroll
            for (int sidx = 0; sidx < 23; sidx++)
                p[sidx] = sD[px*289 + c*24 + sidx] + s_b3[c*23 + sidx];

            size_t xbase = (((size_t)(b*12 + c)) << 14) + ((size_t)gr << 7) + px;
            float xv = x[xbase];
            float xa = par ? 0.f : xv;
            float xf = par ? xv : 0.f;
            float lad;
            float y = rqs_eval(p, xa, lad);
            out[xbase] = xf + y;
            ladsum += lad;
        }
    }
    #pragma unroll
    for (int o = 16; o > 0; o >>= 1)
        ladsum += __shfl_down_sync(0xffffffffu, ladsum, o);
    if (lane == 0) s_red[w] = ladsum;
    __syncthreads();
    if (t == 0) {
        float v = 0.f;
        #pragma unroll
        for (int i = 0; i < 8; i++) v += s_red[i];
        g_lad[b*128 + gr] = v;
    }
}

// ---------------------------------------------------------------------------
// Final logdet reduction: 128 row-partials per image + input logdet.
// ---------------------------------------------------------------------------
__global__ void k_red(const float* __restrict__ logdet_in, float* __restrict__ out) {
    __shared__ float s[4];
    int b = blockIdx.x, t = threadIdx.x;
    float v = g_lad[b*128 + t];
    #pragma unroll
    for (int o = 16; o > 0; o >>= 1) v += __shfl_down_sync(0xffffffffu, v, o);
    if ((t & 31) == 0) s[t >> 5] = v;
    __syncthreads();
    if (t == 0) out[XOUT_SIZE + b] = logdet_in[b] + s[0] + s[1] + s[2] + s[3];
}

// ---------------------------------------------------------------------------
extern "C" void kernel_launch(void* const* d_in, const int* in_sizes, int n_in,
                              void* d_out, int out_size) {
    const float* x      = (const float*)d_in[0];
    const float* logdet = (const float*)d_in[1];
    const float* cond   = (const float*)d_in[2];
    const float* W1     = (const float*)d_in[3];
    const float* b1     = (const float*)d_in[4];
    const float* W2     = (const float*)d_in[5];
    const float* b2     = (const float*)d_in[6];
    const float* W3     = (const float*)d_in[7];
    const float* b3     = (const float*)d_in[8];
    float* out = (float*)d_out;

    const int smem1 = (9792 + 9216) * 4;     // 76,032 B
    const int smem3 = 4 * 55296;             // 221,184 B
    cudaFuncSetAttribute(k_conv1, cudaFuncAttributeMaxDynamicSharedMemorySize, smem1);
    cudaFuncSetAttribute(k_conv3_mma, cudaFuncAttributeMaxDynamicSharedMemorySize, smem3);

    k_trans<<<700, 256>>>(W1, W2, W3);
    k_conv1<<<dim3(32, 16), 256, smem1>>>(x, cond, b1);
    k_conv2<<<1024, 256>>>(b2);
    k_conv3_mma<<<dim3(128, 16), 256, smem3>>>(x, b3, out);
    k_red<<<16, 128>>>(logdet, out);
}

// round 6
// speedup vs baseline: 3.6965x; 1.3499x over previous
#include <cuda_runtime.h>
#include <cuda_bf16.h>
#include <math.h>
#include <stdint.h>

// Problem constants
#define XOUT_SIZE (16*12*128*128)

// Scratch (device globals — no cudaMalloc allowed)
__device__ __align__(16) float g_h1[16*64*128*128];          // conv1 out [b][ch][h][w]
__device__ __align__(16) __nv_bfloat16 g_h2h[16*128*128*64]; // conv2 out [b][h][w][ch] bf16
__device__ float g_W1t[144*64];                              // [k][oc]
__device__ float g_W2t[64*64];                               // [ic][oc]
__device__ __align__(16) uint32_t g_W3Bh[18*2*36*32*2];      // [st][kk][nt][lane][reg] bf16x2
__device__ float g_lad[16*128];                              // per-(image,row) logdet partials

// ---------------------------------------------------------------------------
// helpers
// ---------------------------------------------------------------------------
__device__ __forceinline__ uint32_t s2u(const void* p){
    uint32_t a;
    asm("{ .reg .u64 t; cvta.to.shared.u64 t, %1; cvt.u32.u64 %0, t; }" : "=r"(a) : "l"(p));
    return a;
}
__device__ __forceinline__ void cp16(uint32_t dst, const void* src, uint32_t sz){
    asm volatile("cp.async.cg.shared.global [%0], [%1], 16, %2;"
                 :: "r"(dst), "l"(src), "r"(sz) : "memory");
}
#define CP_COMMIT() asm volatile("cp.async.commit_group;" ::: "memory")

__device__ __forceinline__ void mma_bf16(float* d, uint32_t a0, uint32_t a1,
                                         uint32_t a2, uint32_t a3,
                                         uint32_t b0, uint32_t b1){
    asm volatile(
        "mma.sync.aligned.m16n8k16.row.col.f32.bf16.bf16.f32 "
        "{%0,%1,%2,%3}, {%4,%5,%6,%7}, {%8,%9}, {%0,%1,%2,%3};"
        : "+f"(d[0]), "+f"(d[1]), "+f"(d[2]), "+f"(d[3])
        : "r"(a0), "r"(a1), "r"(a2), "r"(a3), "r"(b0), "r"(b1));
}

// ---------------------------------------------------------------------------
// Weight transposes. W3 packed into m16n8k16 bf16 B-fragment layout:
// word[st][kk][nt][lane][reg] = bf16x2 of
//   W3[n = nt*8 + (lane>>2)][ic = ih*32 + kk*16 + 2*(lane&3) + reg*8 + {0,1}][tap]
// ---------------------------------------------------------------------------
__global__ void k_trans(const float* __restrict__ W1,
                        const float* __restrict__ W2,
                        const float* __restrict__ W3) {
    int i = blockIdx.x * 256 + threadIdx.x;
    if (i < 144*64) {
        int k = i >> 6, oc = i & 63;
        g_W1t[i] = W1[oc*144 + k];
    }
    int j = i - 144*64;
    if (j >= 0 && j < 64*64) {
        int ic = j >> 6, oc = j & 63;
        g_W2t[j] = W2[oc*64 + ic];
    }
    int m = j - 64*64;
    if (m >= 0 && m < 18*4608) {
        int st  = m / 4608;  int r1 = m - st*4608;
        int kk  = r1 / 2304; int r2 = r1 - kk*2304;
        int nt  = r2 >> 6;   int l2 = r2 & 63;
        int lane = l2 >> 1,  reg = l2 & 1;
        int g = lane >> 2, tig = lane & 3;
        int n   = nt*8 + g;
        int tap = st >> 1, ih = st & 1;
        int ic0 = ih*32 + kk*16 + 2*tig + reg*8;
        int c   = n / 24, s = n - c*24;
        float lo = 0.f, hi = 0.f;
        if (s < 23) {
            lo = W3[(c*23 + s)*576 + ic0*9 + tap];
            hi = W3[(c*23 + s)*576 + (ic0+1)*9 + tap];
        }
        __nv_bfloat162 w = __floats2bfloat162_rn(lo, hi);
        g_W3Bh[m] = *(uint32_t*)&w;
    }
}

// ---------------------------------------------------------------------------
// conv1 (16 -> 64, 3x3, pad 1) + ReLU (validated in R1)
// ---------------------------------------------------------------------------
__global__ void __launch_bounds__(256) k_conv1(const float* __restrict__ x,
                                               const float* __restrict__ cond,
                                               const float* __restrict__ b1) {
    extern __shared__ float sm[];
    float* sIn = sm;          // 16 * 612 (18x34 halo tile)
    float* sW  = sm + 9792;   // 144 * 64

    int b = blockIdx.y;
    int tile = blockIdx.x;
    int r0 = (tile >> 2) << 4;
    int c0 = (tile & 3) << 5;
    int t = threadIdx.x;

    {
        const float4* src = (const float4*)g_W1t;
        float4* dst = (float4*)sW;
        for (int i = t; i < 9216/4; i += 256) dst[i] = src[i];
    }
    for (int i = t; i < 16*612; i += 256) {
        int ch = i / 612; int rem = i - ch*612;
        int lr = rem / 34; int lc = rem - lr*34;
        int gr = r0 + lr - 1, gc = c0 + lc - 1;
        float v = 0.f;
        if ((unsigned)gr < 128u && (unsigned)gc < 128u) {
            if (ch < 12)
                v = ((gr + gc) & 1) ? x[(((b*12 + ch) << 7) + gr)*128 + gc] : 0.f;
            else
                v = cond[(((b*4 + (ch-12)) << 7) + gr)*128 + gc];
        }
        sIn[i] = v;
    }
    __syncthreads();

    int r = t >> 4, cx = (t & 15) << 1;
    int gr = r0 + r, gc = c0 + cx;

    #pragma unroll
    for (int half = 0; half < 2; half++) {
        float a0[32], a1[32];
        #pragma unroll
        for (int s = 0; s < 32; s++) { float bb = b1[half*32 + s]; a0[s] = bb; a1[s] = bb; }
        for (int ic = 0; ic < 16; ic++) {
            #pragma unroll
            for (int kh = 0; kh < 3; kh++) {
                const float* inr = &sIn[ic*612 + (r + kh)*34 + cx];
                #pragma unroll
                for (int kw = 0; kw < 3; kw++) {
                    float v0 = inr[kw];
                    float v1 = inr[kw + 1];
                    const float4* wr = (const float4*)&sW[((ic*3 + kh)*3 + kw)*64 + half*32];
                    #pragma unroll
                    for (int q = 0; q < 8; q++) {
                        float4 w = wr[q];
                        a0[q*4+0] = fmaf(w.x, v0, a0[q*4+0]); a1[q*4+0] = fmaf(w.x, v1, a1[q*4+0]);
                        a0[q*4+1] = fmaf(w.y, v0, a0[q*4+1]); a1[q*4+1] = fmaf(w.y, v1, a1[q*4+1]);
                        a0[q*4+2] = fmaf(w.z, v0, a0[q*4+2]); a1[q*4+2] = fmaf(w.z, v1, a1[q*4+2]);
                        a0[q*4+3] = fmaf(w.w, v0, a0[q*4+3]); a1[q*4+3] = fmaf(w.w, v1, a1[q*4+3]);
                    }
                }
            }
        }
        #pragma unroll
        for (int s = 0; s < 32; s++) {
            int oc = half*32 + s;
            float2 o; o.x = fmaxf(a0[s], 0.f); o.y = fmaxf(a1[s], 0.f);
            *(float2*)&g_h1[(((b*64 + oc) << 7) + gr)*128 + gc] = o;
        }
    }
}

// ---------------------------------------------------------------------------
// conv2 (64 -> 64, 1x1) + ReLU -> transposed [b][pix][ch] layout, bf16
// ---------------------------------------------------------------------------
__global__ void __launch_bounds__(256) k_conv2(const float* __restrict__ b2) {
    __shared__ float sW[64*64];
    __shared__ float sB[64];
    int t = threadIdx.x;
    for (int i = t; i < 4096/4; i += 256) ((float4*)sW)[i] = ((const float4*)g_W2t)[i];
    if (t < 64) sB[t] = b2[t];
    __syncthreads();

    int pix = blockIdx.x * 256 + t;
    int b = pix >> 14; int p = pix & 16383;
    const float* in = g_h1 + ((size_t)b << 20) + p;

    float acc[64];
    #pragma unroll
    for (int oc = 0; oc < 64; oc++) acc[oc] = sB[oc];

    #pragma unroll 4
    for (int ic = 0; ic < 64; ic++) {
        float v = in[ic << 14];
        const float4* wr = (const float4*)&sW[ic*64];
        #pragma unroll
        for (int q = 0; q < 16; q++) {
            float4 w = wr[q];
            acc[q*4+0] = fmaf(w.x, v, acc[q*4+0]);
            acc[q*4+1] = fmaf(w.y, v, acc[q*4+1]);
            acc[q*4+2] = fmaf(w.z, v, acc[q*4+2]);
            acc[q*4+3] = fmaf(w.w, v, acc[q*4+3]);
        }
    }
    __nv_bfloat162* outp = (__nv_bfloat162*)(g_h2h + (size_t)pix * 64);
    #pragma unroll
    for (int q = 0; q < 32; q++) {
        outp[q] = __floats2bfloat162_rn(fmaxf(acc[q*2+0], 0.f),
                                        fmaxf(acc[q*2+1], 0.f));
    }
}

// ---------------------------------------------------------------------------
// RQS spline (register-resident 8-bin scan) — validated in R1
// ---------------------------------------------------------------------------
__device__ __forceinline__ float rqs_eval(const float* p, float xa, float& lad) {
    bool inside = (xa >= -3.f) && (xa <= 3.f);
    float xc = fminf(fmaxf(xa, -3.f), 3.f);

    float mw = p[0], mh = p[8];
    #pragma unroll
    for (int k = 1; k < 8; k++) { mw = fmaxf(mw, p[k]); mh = fmaxf(mh, p[8+k]); }
    float ew[8], eh[8]; float sw = 0.f, sh = 0.f;
    #pragma unroll
    for (int k = 0; k < 8; k++) {
        ew[k] = expf(p[k] - mw);   sw += ew[k];
        eh[k] = expf(p[8+k] - mh); sh += eh[k];
    }
    float rw = (1.f - 0.008f) / sw;
    float rh = (1.f - 0.008f) / sh;

    float sp[7];
    #pragma unroll
    for (int k = 0; k < 7; k++) {
        float u = p[16 + k];
        sp[k] = (u > 15.f) ? u : log1pf(expf(u));
    }

    float cw = -3.f, ch = -3.f, cumw = 0.f, cumh = 0.f, dprev = 1.f;
    float icw = -3.f, iw = 1.f, ich = -3.f, ih = 1.f, id0 = 1.f, id1 = 1.f;
    #pragma unroll
    for (int k = 0; k < 8; k++) {
        cumw += 0.001f + ew[k]*rw;
        cumh += 0.001f + eh[k]*rh;
        float cwn = (k == 7) ? 3.f : fmaf(6.f, cumw, -3.f);
        float chn = (k == 7) ? 3.f : fmaf(6.f, cumh, -3.f);
        float dn  = (k == 7) ? 1.f : (0.001f + sp[k]);
        if (xc >= cw) { icw = cw; iw = cwn - cw; ich = ch; ih = chn - ch; id0 = dprev; id1 = dn; }
        cw = cwn; ch = chn; dprev = dn;
    }

    float riw   = 1.f / iw;
    float delta = ih * riw;
    float theta = (xc - icw) * riw;
    float omt = 1.f - theta;
    float t1  = theta * omt;
    float th2 = theta * theta;
    float num = ih * (delta*th2 + id0*t1);
    float den = delta + (id0 + id1 - 2.f*delta)*t1;
    float y   = ich + num / den;
    float dnum = delta*delta*(id1*th2 + 2.f*delta*t1 + id0*omt*omt);
    float l = logf(dnum) - 2.f*logf(den);

    lad = inside ? l : 0.f;
    return inside ? y : xa;
}

// ---------------------------------------------------------------------------
// conv3 via mma.sync bf16 (m16n8k16) + fused RQS epilogue.
// CTA = one image row: M=128 px, N=288, K=576 in 18 stages of 32 (2 k16 each).
// 256 threads = 8 warps: warp = (px-block of 32) x (N-half 144).
// 4-slot cp.async ring: slot = A (128 px x 40 bf16, pitch 80 B = 10240 B)
//                            + B (fragment layout, 18432 B) = 28672 B.
// ---------------------------------------------------------------------------
#define SLOT 28672u

__device__ __forceinline__ void issue_stage(int st, int t, int b, int gr, uint32_t base){
    int tap = st >> 1, ih = st & 1;
    int kh = tap / 3;
    int dh = kh - 1;
    int dw = (tap - kh*3) - 1;
    uint32_t aslot = base + (uint32_t)(st & 3) * SLOT;
    int grs = gr + dh;
    bool rowok = (unsigned)grs < 128u;
    const __nv_bfloat16* h2row = g_h2h + (size_t)(b * 128 + (rowok ? grs : 0)) * 128 * 64;

    // A: 128 px rows x 64 B (32 bf16 ch slice), pitch 80 B, shifted by dw
    #pragma unroll
    for (int it = 0; it < 2; it++) {
        int id = it * 256 + t;
        int p = id >> 2, q = id & 3;
        int pw = p + dw;
        bool ok = rowok && ((unsigned)pw < 128u);
        const __nv_bfloat16* src = h2row + ((ok ? pw : 0) * 64 + ih * 32 + q * 8);
        cp16(aslot + (uint32_t)(p * 80 + q * 16), src, ok ? 16u : 0u);
    }
    // B: linear 18432 B from fragment-packed g_W3Bh
    const uint32_t* wb = g_W3Bh + (size_t)st * 4608;
    #pragma unroll
    for (int it = 0; it < 5; it++) {
        int i = it * 256 + t;
        if (i < 1152)
            cp16(aslot + 10240u + (uint32_t)(i * 16), wb + i * 4, 16u);
    }
    CP_COMMIT();
}

__global__ void __launch_bounds__(256, 1) k_conv3_mma(const float* __restrict__ x,
                                                      const float* __restrict__ b3,
                                                      float* __restrict__ out) {
    extern __shared__ float dyn[];
    __shared__ float s_b3[276];
    __shared__ float s_red[8];

    int b  = blockIdx.y;
    int gr = blockIdx.x;
    int t  = threadIdx.x;
    int w = t >> 5, lane = t & 31;
    int g = lane >> 2, tig = lane & 3;
    int px0 = (w & 3) * 32;      // two m16 tiles: rows px0..px0+31
    int hh  = w >> 2;            // N half: 0 or 1

    uint32_t base = s2u(dyn);

    for (int i = t; i < 276; i += 256) s_b3[i] = b3[i];

    // d[nt*8 + m*4 + j]
    float d[144];
    #pragma unroll
    for (int i = 0; i < 144; i++) d[i] = 0.f;

    issue_stage(0, t, b, gr, base);
    issue_stage(1, t, b, gr, base);
    issue_stage(2, t, b, gr, base);

    for (int s = 0; s < 18; s++) {
        if (s < 16)       asm volatile("cp.async.wait_group 2;" ::: "memory");
        else if (s == 16) asm volatile("cp.async.wait_group 1;" ::: "memory");
        else              asm volatile("cp.async.wait_group 0;" ::: "memory");
        __syncthreads();

        if (s < 15) issue_stage(s + 3, t, b, gr, base);

        const char* sAb = (const char*)dyn + (size_t)(s & 3) * SLOT;
        const char* sBb = sAb + 10240 + (size_t)hh * 18 * 256 + (size_t)lane * 8;

        #pragma unroll
        for (int kk = 0; kk < 2; kk++) {
            // A fragments: rows px0+g(+8,+16,+24), k halves 2tig(+1), +8
            const char* ar = sAb + (size_t)kk * 32 + (size_t)tig * 4;
            uint32_t a00 = *(const uint32_t*)(ar + (px0+g   )*80);
            uint32_t a01 = *(const uint32_t*)(ar + (px0+g+ 8)*80);
            uint32_t a02 = *(const uint32_t*)(ar + (px0+g   )*80 + 16);
            uint32_t a03 = *(const uint32_t*)(ar + (px0+g+ 8)*80 + 16);
            uint32_t a10 = *(const uint32_t*)(ar + (px0+g+16)*80);
            uint32_t a11 = *(const uint32_t*)(ar + (px0+g+24)*80);
            uint32_t a12 = *(const uint32_t*)(ar + (px0+g+16)*80 + 16);
            uint32_t a13 = *(const uint32_t*)(ar + (px0+g+24)*80 + 16);
            const char* bp = sBb + (size_t)kk * 9216;
            #pragma unroll
            for (int nt = 0; nt < 18; nt++) {
                uint2 bb = *(const uint2*)(bp + (size_t)nt * 256);
                mma_bf16(&d[nt*8],     a00, a01, a02, a03, bb.x, bb.y);
                mma_bf16(&d[nt*8 + 4], a10, a11, a12, a13, bb.x, bb.y);
            }
        }
    }

    // epilogue in two 64-px passes (sD = 64 x 289 floats = 73984 B < ring size)
    float ladsum = 0.f;
    #pragma unroll
    for (int pass = 0; pass < 2; pass++) {
        __syncthreads();
        if ((px0 >> 6) == pass) {
            float* sD = dyn;
            int rbase = px0 & 63;
            #pragma unroll
            for (int m = 0; m < 2; m++) {
                int row0 = rbase + m*16 + g;
                #pragma unroll
                for (int nt = 0; nt < 18; nt++) {
                    int col = hh*144 + nt*8 + 2*tig;
                    sD[ row0      * 289 + col    ] = d[nt*8 + m*4 + 0];
                    sD[ row0      * 289 + col + 1] = d[nt*8 + m*4 + 1];
                    sD[(row0 + 8) * 289 + col    ] = d[nt*8 + m*4 + 2];
                    sD[(row0 + 8) * 289 + col + 1] = d[nt*8 + m*4 + 3];
                }
            }
        }
        __syncthreads();

        // spline: 256 threads -> 64 px x 4 channel-groups of 3
        const float* sD = dyn;
        int px = pass*64 + (t & 63);
        int lrow = t & 63;
        int cbase = (t >> 6) * 3;
        int par = (gr + px) & 1;    // 1 => frozen
        #pragma unroll
        for (int cc = 0; cc < 3; cc++) {
            int c = cbase + cc;
            float p[23];
            #pragma unroll
            for (int sidx = 0; sidx < 23; sidx++)
                p[sidx] = sD[lrow*289 + c*24 + sidx] + s_b3[c*23 + sidx];

            size_t xbase = (((size_t)(b*12 + c)) << 14) + ((size_t)gr << 7) + px;
            float xv = x[xbase];
            float xa = par ? 0.f : xv;
            float xf = par ? xv : 0.f;
            float lad;
            float y = rqs_eval(p, xa, lad);
            out[xbase] = xf + y;
            ladsum += lad;
        }
    }
    #pragma unroll
    for (int o = 16; o > 0; o >>= 1)
        ladsum += __shfl_down_sync(0xffffffffu, ladsum, o);
    if (lane == 0) s_red[w] = ladsum;
    __syncthreads();
    if (t == 0) {
        float v = 0.f;
        #pragma unroll
        for (int i = 0; i < 8; i++) v += s_red[i];
        g_lad[b*128 + gr] = v;
    }
}

// ---------------------------------------------------------------------------
// Final logdet reduction: 128 row-partials per image + input logdet.
// ---------------------------------------------------------------------------
__global__ void k_red(const float* __restrict__ logdet_in, float* __restrict__ out) {
    __shared__ float s[4];
    int b = blockIdx.x, t = threadIdx.x;
    float v = g_lad[b*128 + t];
    #pragma unroll
    for (int o = 16; o > 0; o >>= 1) v += __shfl_down_sync(0xffffffffu, v, o);
    if ((t & 31) == 0) s[t >> 5] = v;
    __syncthreads();
    if (t == 0) out[XOUT_SIZE + b] = logdet_in[b] + s[0] + s[1] + s[2] + s[3];
}

// ---------------------------------------------------------------------------
extern "C" void kernel_launch(void* const* d_in, const int* in_sizes, int n_in,
                              void* d_out, int out_size) {
    const float* x      = (const float*)d_in[0];
    const float* logdet = (const float*)d_in[1];
    const float* cond   = (const float*)d_in[2];
    const float* W1     = (const float*)d_in[3];
    const float* b1     = (const float*)d_in[4];
    const float* W2     = (const float*)d_in[5];
    const float* b2     = (const float*)d_in[6];
    const float* W3     = (const float*)d_in[7];
    const float* b3     = (const float*)d_in[8];
    float* out = (float*)d_out;

    const int smem1 = (9792 + 9216) * 4;     // 76,032 B
    const int smem3 = 4 * SLOT;              // 114,688 B
    cudaFuncSetAttribute(k_conv1, cudaFuncAttributeMaxDynamicSharedMemorySize, smem1);
    cudaFuncSetAttribute(k_conv3_mma, cudaFuncAttributeMaxDynamicSharedMemorySize, smem3);

    k_trans<<<700, 256>>>(W1, W2, W3);
    k_conv1<<<dim3(32, 16), 256, smem1>>>(x, cond, b1);
    k_conv2<<<1024, 256>>>(b2);
    k_conv3_mma<<<dim3(128, 16), 256, smem3>>>(x, b3, out);
    k_red<<<16, 128>>>(logdet, out);
}

// round 7
// speedup vs baseline: 4.1799x; 1.1308x over previous
#include <cuda_runtime.h>
#include <cuda_bf16.h>
#include <math.h>
#include <stdint.h>

// Problem constants
#define XOUT_SIZE (16*12*128*128)

// Scratch (device globals — no cudaMalloc allowed)
__device__ __align__(16) float g_h1[16*64*128*128];          // conv1 out [b][ch][h][w]
__device__ __align__(16) __nv_bfloat16 g_h2h[16*128*128*64]; // conv2 out [b][h][w][ch] bf16
__device__ float g_W1t[144*64];                              // [k][oc]
__device__ float g_W2t[64*64];                               // [ic][oc]
__device__ __align__(16) uint32_t g_W3Bh[18*2*2*18*64];      // [st][hh][kk][nt][lane*2+reg]
__device__ float g_lad[16*256];                              // per-(image,row,half) logdet partials

// ---------------------------------------------------------------------------
// helpers
// ---------------------------------------------------------------------------
__device__ __forceinline__ uint32_t s2u(const void* p){
    uint32_t a;
    asm("{ .reg .u64 t; cvta.to.shared.u64 t, %1; cvt.u32.u64 %0, t; }" : "=r"(a) : "l"(p));
    return a;
}
__device__ __forceinline__ void cp16(uint32_t dst, const void* src, uint32_t sz){
    asm volatile("cp.async.cg.shared.global [%0], [%1], 16, %2;"
                 :: "r"(dst), "l"(src), "r"(sz) : "memory");
}
#define CP_COMMIT() asm volatile("cp.async.commit_group;" ::: "memory")

__device__ __forceinline__ void mma_bf16(float* d, uint32_t a0, uint32_t a1,
                                         uint32_t a2, uint32_t a3,
                                         uint32_t b0, uint32_t b1){
    asm volatile(
        "mma.sync.aligned.m16n8k16.row.col.f32.bf16.bf16.f32 "
        "{%0,%1,%2,%3}, {%4,%5,%6,%7}, {%8,%9}, {%0,%1,%2,%3};"
        : "+f"(d[0]), "+f"(d[1]), "+f"(d[2]), "+f"(d[3])
        : "r"(a0), "r"(a1), "r"(a2), "r"(a3), "r"(b0), "r"(b1));
}

// ---------------------------------------------------------------------------
// Weight transposes. W3 packed into per-half m16n8k16 bf16 B-fragment layout:
// word[st][hh][kk][nt][lane][reg] = bf16x2 of
//   W3[n = hh*144 + nt*8 + (lane>>2)][ic = ih*32 + kk*16 + 2*(lane&3) + reg*8 + {0,1}][tap]
// so each N-half CTA loads a contiguous 9216 B block per stage.
// ---------------------------------------------------------------------------
__global__ void k_trans(const float* __restrict__ W1,
                        const float* __restrict__ W2,
                        const float* __restrict__ W3) {
    int i = blockIdx.x * 256 + threadIdx.x;
    if (i < 144*64) {
        int k = i >> 6, oc = i & 63;
        g_W1t[i] = W1[oc*144 + k];
    }
    int j = i - 144*64;
    if (j >= 0 && j < 64*64) {
        int ic = j >> 6, oc = j & 63;
        g_W2t[j] = W2[oc*64 + ic];
    }
    int m = j - 64*64;
    if (m >= 0 && m < 18*4608) {
        int st = m / 4608;  int r1 = m - st*4608;
        int hh = r1 / 2304; int r2 = r1 - hh*2304;
        int kk = r2 / 1152; int r3 = r2 - kk*1152;
        int nt = r3 >> 6;   int l2 = r3 & 63;
        int lane = l2 >> 1, reg = l2 & 1;
        int n   = hh*144 + nt*8 + (lane >> 2);
        int tap = st >> 1, ih = st & 1;
        int ic0 = ih*32 + kk*16 + 2*(lane & 3) + reg*8;
        int c   = n / 24, s = n - c*24;
        float lo = 0.f, hi = 0.f;
        if (s < 23) {
            lo = W3[(c*23 + s)*576 + ic0*9 + tap];
            hi = W3[(c*23 + s)*576 + (ic0+1)*9 + tap];
        }
        __nv_bfloat162 w = __floats2bfloat162_rn(lo, hi);
        g_W3Bh[m] = *(uint32_t*)&w;
    }
}

// ---------------------------------------------------------------------------
// conv1 (16 -> 64, 3x3, pad 1) + ReLU (validated in R1)
// ---------------------------------------------------------------------------
__global__ void __launch_bounds__(256) k_conv1(const float* __restrict__ x,
                                               const float* __restrict__ cond,
                                               const float* __restrict__ b1) {
    extern __shared__ float sm[];
    float* sIn = sm;          // 16 * 612 (18x34 halo tile)
    float* sW  = sm + 9792;   // 144 * 64

    int b = blockIdx.y;
    int tile = blockIdx.x;
    int r0 = (tile >> 2) << 4;
    int c0 = (tile & 3) << 5;
    int t = threadIdx.x;

    {
        const float4* src = (const float4*)g_W1t;
        float4* dst = (float4*)sW;
        for (int i = t; i < 9216/4; i += 256) dst[i] = src[i];
    }
    for (int i = t; i < 16*612; i += 256) {
        int ch = i / 612; int rem = i - ch*612;
        int lr = rem / 34; int lc = rem - lr*34;
        int gr = r0 + lr - 1, gc = c0 + lc - 1;
        float v = 0.f;
        if ((unsigned)gr < 128u && (unsigned)gc < 128u) {
            if (ch < 12)
                v = ((gr + gc) & 1) ? x[(((b*12 + ch) << 7) + gr)*128 + gc] : 0.f;
            else
                v = cond[(((b*4 + (ch-12)) << 7) + gr)*128 + gc];
        }
        sIn[i] = v;
    }
    __syncthreads();

    int r = t >> 4, cx = (t & 15) << 1;
    int gr = r0 + r, gc = c0 + cx;

    #pragma unroll
    for (int half = 0; half < 2; half++) {
        float a0[32], a1[32];
        #pragma unroll
        for (int s = 0; s < 32; s++) { float bb = b1[half*32 + s]; a0[s] = bb; a1[s] = bb; }
        for (int ic = 0; ic < 16; ic++) {
            #pragma unroll
            for (int kh = 0; kh < 3; kh++) {
                const float* inr = &sIn[ic*612 + (r + kh)*34 + cx];
                #pragma unroll
                for (int kw = 0; kw < 3; kw++) {
                    float v0 = inr[kw];
                    float v1 = inr[kw + 1];
                    const float4* wr = (const float4*)&sW[((ic*3 + kh)*3 + kw)*64 + half*32];
                    #pragma unroll
                    for (int q = 0; q < 8; q++) {
                        float4 w = wr[q];
                        a0[q*4+0] = fmaf(w.x, v0, a0[q*4+0]); a1[q*4+0] = fmaf(w.x, v1, a1[q*4+0]);
                        a0[q*4+1] = fmaf(w.y, v0, a0[q*4+1]); a1[q*4+1] = fmaf(w.y, v1, a1[q*4+1]);
                        a0[q*4+2] = fmaf(w.z, v0, a0[q*4+2]); a1[q*4+2] = fmaf(w.z, v1, a1[q*4+2]);
                        a0[q*4+3] = fmaf(w.w, v0, a0[q*4+3]); a1[q*4+3] = fmaf(w.w, v1, a1[q*4+3]);
                    }
                }
            }
        }
        #pragma unroll
        for (int s = 0; s < 32; s++) {
            int oc = half*32 + s;
            float2 o; o.x = fmaxf(a0[s], 0.f); o.y = fmaxf(a1[s], 0.f);
            *(float2*)&g_h1[(((b*64 + oc) << 7) + gr)*128 + gc] = o;
        }
    }
}

// ---------------------------------------------------------------------------
// conv2 (64 -> 64, 1x1) + ReLU -> transposed [b][pix][ch] layout, bf16
// ---------------------------------------------------------------------------
__global__ void __launch_bounds__(256) k_conv2(const float* __restrict__ b2) {
    __shared__ float sW[64*64];
    __shared__ float sB[64];
    int t = threadIdx.x;
    for (int i = t; i < 4096/4; i += 256) ((float4*)sW)[i] = ((const float4*)g_W2t)[i];
    if (t < 64) sB[t] = b2[t];
    __syncthreads();

    int pix = blockIdx.x * 256 + t;
    int b = pix >> 14; int p = pix & 16383;
    const float* in = g_h1 + ((size_t)b << 20) + p;

    float acc[64];
    #pragma unroll
    for (int oc = 0; oc < 64; oc++) acc[oc] = sB[oc];

    #pragma unroll 4
    for (int ic = 0; ic < 64; ic++) {
        float v = in[ic << 14];
        const float4* wr = (const float4*)&sW[ic*64];
        #pragma unroll
        for (int q = 0; q < 16; q++) {
            float4 w = wr[q];
            acc[q*4+0] = fmaf(w.x, v, acc[q*4+0]);
            acc[q*4+1] = fmaf(w.y, v, acc[q*4+1]);
            acc[q*4+2] = fmaf(w.z, v, acc[q*4+2]);
            acc[q*4+3] = fmaf(w.w, v, acc[q*4+3]);
        }
    }
    __nv_bfloat162* outp = (__nv_bfloat162*)(g_h2h + (size_t)pix * 64);
    #pragma unroll
    for (int q = 0; q < 32; q++) {
        outp[q] = __floats2bfloat162_rn(fmaxf(acc[q*2+0], 0.f),
                                        fmaxf(acc[q*2+1], 0.f));
    }
}

// ---------------------------------------------------------------------------
// RQS spline (register-resident 8-bin scan) — validated in R1
// ---------------------------------------------------------------------------
__device__ __forceinline__ float rqs_eval(const float* p, float xa, float& lad) {
    bool inside = (xa >= -3.f) && (xa <= 3.f);
    float xc = fminf(fmaxf(xa, -3.f), 3.f);

    float mw = p[0], mh = p[8];
    #pragma unroll
    for (int k = 1; k < 8; k++) { mw = fmaxf(mw, p[k]); mh = fmaxf(mh, p[8+k]); }
    float ew[8], eh[8]; float sw = 0.f, sh = 0.f;
    #pragma unroll
    for (int k = 0; k < 8; k++) {
        ew[k] = expf(p[k] - mw);   sw += ew[k];
        eh[k] = expf(p[8+k] - mh); sh += eh[k];
    }
    float rw = (1.f - 0.008f) / sw;
    float rh = (1.f - 0.008f) / sh;

    float sp[7];
    #pragma unroll
    for (int k = 0; k < 7; k++) {
        float u = p[16 + k];
        sp[k] = (u > 15.f) ? u : log1pf(expf(u));
    }

    float cw = -3.f, ch = -3.f, cumw = 0.f, cumh = 0.f, dprev = 1.f;
    float icw = -3.f, iw = 1.f, ich = -3.f, ih = 1.f, id0 = 1.f, id1 = 1.f;
    #pragma unroll
    for (int k = 0; k < 8; k++) {
        cumw += 0.001f + ew[k]*rw;
        cumh += 0.001f + eh[k]*rh;
        float cwn = (k == 7) ? 3.f : fmaf(6.f, cumw, -3.f);
        float chn = (k == 7) ? 3.f : fmaf(6.f, cumh, -3.f);
        float dn  = (k == 7) ? 1.f : (0.001f + sp[k]);
        if (xc >= cw) { icw = cw; iw = cwn - cw; ich = ch; ih = chn - ch; id0 = dprev; id1 = dn; }
        cw = cwn; ch = chn; dprev = dn;
    }

    float riw   = 1.f / iw;
    float delta = ih * riw;
    float theta = (xc - icw) * riw;
    float omt = 1.f - theta;
    float t1  = theta * omt;
    float th2 = theta * theta;
    float num = ih * (delta*th2 + id0*t1);
    float den = delta + (id0 + id1 - 2.f*delta)*t1;
    float y   = ich + num / den;
    float dnum = delta*delta*(id1*th2 + 2.f*delta*t1 + id0*omt*omt);
    float l = logf(dnum) - 2.f*logf(den);

    lad = inside ? l : 0.f;
    return inside ? y : xa;
}

// ---------------------------------------------------------------------------
// conv3 via mma.sync bf16 (m16n8k16) + fused RQS epilogue.
// CTA = (image row, N-half): M=128 px, N=144 (6 channels), K=576 in 18 stages.
// 256 threads = 8 warps: warp = (px-block of 32) x (N-quarter 72).
// 4-slot cp.async ring: slot = A (128 px x 40 bf16, pitch 80 B = 10240 B)
//                            + B (per-half fragment block, 9216 B) = 19456 B.
// 2 CTAs co-resident per SM (77824 B smem each, <=128 regs) -> 16 warps/SM
// with independent barriers.
// ---------------------------------------------------------------------------
#define SLOT 19456u

__device__ __forceinline__ void issue_stage(int st, int t, int b, int gr, int hh,
                                            uint32_t base){
    int tap = st >> 1, ih = st & 1;
    int kh = tap / 3;
    int dh = kh - 1;
    int dw = (tap - kh*3) - 1;
    uint32_t aslot = base + (uint32_t)(st & 3) * SLOT;
    int grs = gr + dh;
    bool rowok = (unsigned)grs < 128u;
    const __nv_bfloat16* h2row = g_h2h + (size_t)(b * 128 + (rowok ? grs : 0)) * 128 * 64;

    // A: 128 px rows x 64 B (32 bf16 ch slice), pitch 80 B, shifted by dw
    #pragma unroll
    for (int it = 0; it < 2; it++) {
        int id = it * 256 + t;
        int p = id >> 2, q = id & 3;
        int pw = p + dw;
        bool ok = rowok && ((unsigned)pw < 128u);
        const __nv_bfloat16* src = h2row + ((ok ? pw : 0) * 64 + ih * 32 + q * 8);
        cp16(aslot + (uint32_t)(p * 80 + q * 16), src, ok ? 16u : 0u);
    }
    // B: linear 9216 B (this CTA's N-half) from fragment-packed g_W3Bh
    const uint32_t* wb = g_W3Bh + (size_t)st * 4608 + (size_t)hh * 2304;
    #pragma unroll
    for (int it = 0; it < 3; it++) {
        int i = it * 256 + t;
        if (i < 576)
            cp16(aslot + 10240u + (uint32_t)(i * 16), wb + i * 4, 16u);
    }
    CP_COMMIT();
}

__global__ void __launch_bounds__(256, 2) k_conv3_mma(const float* __restrict__ x,
                                                      const float* __restrict__ b3,
                                                      float* __restrict__ out) {
    extern __shared__ float dyn[];
    __shared__ float s_b3[276];
    __shared__ float s_red[8];

    int b  = blockIdx.y;
    int bx = blockIdx.x;
    int gr = bx >> 1;            // image row
    int hh = bx & 1;             // N half (channels hh*6 .. hh*6+5)
    int t  = threadIdx.x;
    int w = t >> 5, lane = t & 31;
    int g = lane >> 2, tig = lane & 3;
    int px0 = (w & 3) * 32;      // two m16 tiles: rows px0..px0+31
    int qq  = w >> 2;            // N quarter within half: 0 or 1

    uint32_t base = s2u(dyn);

    for (int i = t; i < 276; i += 256) s_b3[i] = b3[i];

    // d[nt*8 + m*4 + j]: nt 0..8 within this warp's 72-col quarter
    float d[72];
    #pragma unroll
    for (int i = 0; i < 72; i++) d[i] = 0.f;

    issue_stage(0, t, b, gr, hh, base);
    issue_stage(1, t, b, gr, hh, base);
    issue_stage(2, t, b, gr, hh, base);

    for (int s = 0; s < 18; s++) {
        if (s < 16)       asm volatile("cp.async.wait_group 2;" ::: "memory");
        else if (s == 16) asm volatile("cp.async.wait_group 1;" ::: "memory");
        else              asm volatile("cp.async.wait_group 0;" ::: "memory");
        __syncthreads();

        if (s < 15) issue_stage(s + 3, t, b, gr, hh, base);

        const char* sAb = (const char*)dyn + (size_t)(s & 3) * SLOT;
        const char* sBb = sAb + 10240 + (size_t)lane * 8;

        #pragma unroll
        for (int kk = 0; kk < 2; kk++) {
            const char* ar = sAb + (size_t)kk * 32 + (size_t)tig * 4;
            uint32_t a00 = *(const uint32_t*)(ar + (px0+g   )*80);
            uint32_t a01 = *(const uint32_t*)(ar + (px0+g+ 8)*80);
            uint32_t a02 = *(const uint32_t*)(ar + (px0+g   )*80 + 16);
            uint32_t a03 = *(const uint32_t*)(ar + (px0+g+ 8)*80 + 16);
            uint32_t a10 = *(const uint32_t*)(ar + (px0+g+16)*80);
            uint32_t a11 = *(const uint32_t*)(ar + (px0+g+24)*80);
            uint32_t a12 = *(const uint32_t*)(ar + (px0+g+16)*80 + 16);
            uint32_t a13 = *(const uint32_t*)(ar + (px0+g+24)*80 + 16);
            const char* bp = sBb + (size_t)kk * 4608 + (size_t)(qq * 9) * 256;
            #pragma unroll
            for (int nt = 0; nt < 9; nt++) {
                uint2 bb = *(const uint2*)(bp + (size_t)nt * 256);
                mma_bf16(&d[nt*8],     a00, a01, a02, a03, bb.x, bb.y);
                mma_bf16(&d[nt*8 + 4], a10, a11, a12, a13, bb.x, bb.y);
            }
        }
    }

    // store accumulators to smem: 128 px x 145 floats (74240 B <= ring)
    __syncthreads();
    {
        float* sD = dyn;
        #pragma unroll
        for (int m = 0; m < 2; m++) {
            int row0 = px0 + m*16 + g;
            #pragma unroll
            for (int nt = 0; nt < 9; nt++) {
                int col = qq*72 + nt*8 + 2*tig;
                sD[ row0      * 145 + col    ] = d[nt*8 + m*4 + 0];
                sD[ row0      * 145 + col + 1] = d[nt*8 + m*4 + 1];
                sD[(row0 + 8) * 145 + col    ] = d[nt*8 + m*4 + 2];
                sD[(row0 + 8) * 145 + col + 1] = d[nt*8 + m*4 + 3];
            }
        }
    }
    __syncthreads();

    // spline: 256 threads -> 128 px x 2 channel-groups of 3 (this half's 6 ch)
    float ladsum = 0.f;
    {
        const float* sD = dyn;
        int px = t & 127;
        int clbase = (t >> 7) * 3;
        int par = (gr + px) & 1;    // 1 => frozen
        #pragma unroll
        for (int cc = 0; cc < 3; cc++) {
            int cl = clbase + cc;        // local channel 0..5
            int c  = hh*6 + cl;          // global channel
            float p[23];
            #pragma unroll
            for (int sidx = 0; sidx < 23; sidx++)
                p[sidx] = sD[px*145 + cl*24 + sidx] + s_b3[c*23 + sidx];

            size_t xbase = (((size_t)(b*12 + c)) << 14) + ((size_t)gr << 7) + px;
            float xv = x[xbase];
            float xa = par ? 0.f : xv;
            float xf = par ? xv : 0.f;
            float lad;
            float y = rqs_eval(p, xa, lad);
            out[xbase] = xf + y;
            ladsum += lad;
        }
    }
    #pragma unroll
    for (int o = 16; o > 0; o >>= 1)
        ladsum += __shfl_down_sync(0xffffffffu, ladsum, o);
    if (lane == 0) s_red[w] = ladsum;
    __syncthreads();
    if (t == 0) {
        float v = 0.f;
        #pragma unroll
        for (int i = 0; i < 8; i++) v += s_red[i];
        g_lad[b*256 + bx] = v;
    }
}

// ---------------------------------------------------------------------------
// Final logdet reduction: 256 partials per image + input logdet.
// ---------------------------------------------------------------------------
__global__ void k_red(const float* __restrict__ logdet_in, float* __restrict__ out) {
    __shared__ float s[8];
    int b = blockIdx.x, t = threadIdx.x;
    float v = g_lad[b*256 + t];
    #pragma unroll
    for (int o = 16; o > 0; o >>= 1) v += __shfl_down_sync(0xffffffffu, v, o);
    if ((t & 31) == 0) s[t >> 5] = v;
    __syncthreads();
    if (t == 0) {
        float r = logdet_in[b];
        #pragma unroll
        for (int i = 0; i < 8; i++) r += s[i];
        out[XOUT_SIZE + b] = r;
    }
}

// ---------------------------------------------------------------------------
extern "C" void kernel_launch(void* const* d_in, const int* in_sizes, int n_in,
                              void* d_out, int out_size) {
    const float* x      = (const float*)d_in[0];
    const float* logdet = (const float*)d_in[1];
    const float* cond   = (const float*)d_in[2];
    const float* W1     = (const float*)d_in[3];
    const float* b1     = (const float*)d_in[4];
    const float* W2     = (const float*)d_in[5];
    const float* b2     = (const float*)d_in[6];
    const float* W3     = (const float*)d_in[7];
    const float* b3     = (const float*)d_in[8];
    float* out = (float*)d_out;

    const int smem1 = (9792 + 9216) * 4;     // 76,032 B
    const int smem3 = 4 * SLOT;              // 77,824 B
    cudaFuncSetAttribute(k_conv1, cudaFuncAttributeMaxDynamicSharedMemorySize, smem1);
    cudaFuncSetAttribute(k_conv3_mma, cudaFuncAttributeMaxDynamicSharedMemorySize, smem3);

    k_trans<<<700, 256>>>(W1, W2, W3);
    k_conv1<<<dim3(32, 16), 256, smem1>>>(x, cond, b1);
    k_conv2<<<1024, 256>>>(b2);
    k_conv3_mma<<<dim3(256, 16), 256, smem3>>>(x, b3, out);
    k_red<<<16, 256>>>(logdet, out);
}

// round 8
// speedup vs baseline: 5.4950x; 1.3146x over previous
#include <cuda_runtime.h>
#include <cuda_bf16.h>
#include <math.h>
#include <stdint.h>

// Problem constants
#define XOUT_SIZE (16*12*128*128)

// Scratch (device globals — no cudaMalloc allowed)
__device__ __align__(16) __nv_bfloat16 g_h2h[16*128*128*64]; // conv2 out [b][h][w][ch] bf16
__device__ __align__(16) float g_W1F[18*8*64];               // conv1 tf32 B-frags [cc][nt][lane*2+j]
__device__ __align__(16) float g_W2F[8*8*64];                // conv2 tf32 B-frags [kk][nt][lane*2+j]
__device__ __align__(16) uint32_t g_W3Bh[18*2*2*18*64];      // [st][hh][kk][nt][lane*2+reg]
__device__ float g_lad[16*256];                              // per-(image,row,half) logdet partials

// ---------------------------------------------------------------------------
// helpers
// ---------------------------------------------------------------------------
__device__ __forceinline__ uint32_t s2u(const void* p){
    uint32_t a;
    asm("{ .reg .u64 t; cvta.to.shared.u64 t, %1; cvt.u32.u64 %0, t; }" : "=r"(a) : "l"(p));
    return a;
}
__device__ __forceinline__ void cp16(uint32_t dst, const void* src, uint32_t sz){
    asm volatile("cp.async.cg.shared.global [%0], [%1], 16, %2;"
                 :: "r"(dst), "l"(src), "r"(sz) : "memory");
}
#define CP_COMMIT() asm volatile("cp.async.commit_group;" ::: "memory")

__device__ __forceinline__ float rna(float v){
    uint32_t o;
    asm("cvt.rna.tf32.f32 %0, %1;" : "=r"(o) : "f"(v));
    return __uint_as_float(o);
}

__device__ __forceinline__ void mma_bf16(float* d, uint32_t a0, uint32_t a1,
                                         uint32_t a2, uint32_t a3,
                                         uint32_t b0, uint32_t b1){
    asm volatile(
        "mma.sync.aligned.m16n8k16.row.col.f32.bf16.bf16.f32 "
        "{%0,%1,%2,%3}, {%4,%5,%6,%7}, {%8,%9}, {%0,%1,%2,%3};"
        : "+f"(d[0]), "+f"(d[1]), "+f"(d[2]), "+f"(d[3])
        : "r"(a0), "r"(a1), "r"(a2), "r"(a3), "r"(b0), "r"(b1));
}

__device__ __forceinline__ void mma_tf32(float* d, uint32_t a0, uint32_t a1,
                                         uint32_t a2, uint32_t a3,
                                         uint32_t b0, uint32_t b1){
    asm volatile(
        "mma.sync.aligned.m16n8k8.row.col.f32.tf32.tf32.f32 "
        "{%0,%1,%2,%3}, {%4,%5,%6,%7}, {%8,%9}, {%0,%1,%2,%3};"
        : "+f"(d[0]), "+f"(d[1]), "+f"(d[2]), "+f"(d[3])
        : "r"(a0), "r"(a1), "r"(a2), "r"(a3), "r"(b0), "r"(b1));
}

// ---------------------------------------------------------------------------
// Weight packing.
// W1F[cc=tap*2+kk][nt][lane][j] = rna(W1[oc=nt*8+(lane>>2)][ic=kk*8+(lane&3)+4j][kh][kw])
// W2F[kk][nt][lane][j]          = rna(W2[oc=nt*8+(lane>>2)][ic=kk*8+(lane&3)+4j])
// W3Bh: per-half bf16 m16n8k16 fragments (validated R7).
// ---------------------------------------------------------------------------
__global__ void k_trans(const float* __restrict__ W1,
                        const float* __restrict__ W2,
                        const float* __restrict__ W3) {
    int i = blockIdx.x * 256 + threadIdx.x;
    if (i < 9216) {
        int cc = i >> 9;  int r = i & 511;
        int nt = r >> 6;  int l2 = r & 63;
        int lane = l2 >> 1, jj = l2 & 1;
        int tap = cc >> 1, kk = cc & 1;
        int oc = nt*8 + (lane >> 2);
        int ic = kk*8 + (lane & 3) + 4*jj;
        int kh = tap / 3, kw = tap - kh*3;
        g_W1F[i] = rna(W1[oc*144 + ic*9 + kh*3 + kw]);
    }
    int j = i - 9216;
    if (j >= 0 && j < 4096) {
        int kk = j >> 9;  int r = j & 511;
        int nt = r >> 6;  int l2 = r & 63;
        int lane = l2 >> 1, jj = l2 & 1;
        int oc = nt*8 + (lane >> 2);
        int ic = kk*8 + (lane & 3) + 4*jj;
        g_W2F[j] = rna(W2[oc*64 + ic]);
    }
    int m = j - 4096;
    if (m >= 0 && m < 18*4608) {
        int st = m / 4608;  int r1 = m - st*4608;
        int hh = r1 / 2304; int r2 = r1 - hh*2304;
        int kk = r2 / 1152; int r3 = r2 - kk*1152;
        int nt = r3 >> 6;   int l2 = r3 & 63;
        int lane = l2 >> 1, reg = l2 & 1;
        int n   = hh*144 + nt*8 + (lane >> 2);
        int tap = st >> 1, ih = st & 1;
        int ic0 = ih*32 + kk*16 + 2*(lane & 3) + reg*8;
        int c   = n / 24, s = n - c*24;
        float lo = 0.f, hi = 0.f;
        if (s < 23) {
            lo = W3[(c*23 + s)*576 + ic0*9 + tap];
            hi = W3[(c*23 + s)*576 + (ic0+1)*9 + tap];
        }
        __nv_bfloat162 w = __floats2bfloat162_rn(lo, hi);
        g_W3Bh[m] = *(uint32_t*)&w;
    }
}

// ---------------------------------------------------------------------------
// Fused conv1 (16->64, 3x3) + ReLU + conv2 (64->64, 1x1) + ReLU, tf32 MMA.
// CTA = one image row. 256 threads = 8 warps: warp = (px-block 32) x (N-half 32).
// smem (floats): z [3][130][20] @0 (7800) | B1 frags @7800 (9216) | B2 @17016 (4096)
//   A2 [128][68] reuses @7800 (8704) ; bf16 out staging reuses @0 (4096 words)
// Total 21112 floats = 84448 B -> 2 CTAs/SM.
// ---------------------------------------------------------------------------
__global__ void __launch_bounds__(256, 2) k_conv12(const float* __restrict__ x,
                                                   const float* __restrict__ cond,
                                                   const float* __restrict__ b1,
                                                   const float* __restrict__ b2) {
    extern __shared__ float dyn[];
    __shared__ float s_b1[64], s_b2[64];

    int b  = blockIdx.y;
    int gr = blockIdx.x;
    int t  = threadIdx.x;
    int w = t >> 5, lane = t & 31;
    int g = lane >> 2, tig = lane & 3;
    int px0 = (w & 3) * 32;
    int nc0 = (w >> 2) * 32;     // N column block base (0 or 32)

    if (t < 64)       s_b1[t] = b1[t];
    else if (t < 128) s_b2[t-64] = b2[t-64];

    // cp.async weight fragments
    {
        uint32_t b1s = s2u(dyn + 7800);
        for (int i = t; i < 2304; i += 256) cp16(b1s + (uint32_t)(i*16), g_W1F + i*4, 16u);
        uint32_t b2s = s2u(dyn + 17016);
        for (int i = t; i < 1024; i += 256) cp16(b2s + (uint32_t)(i*16), g_W2F + i*4, 16u);
        CP_COMMIT();
    }

    // build z tile: [r=0..2][pp=0..129][ch=0..15], pitch 20, rna-rounded
    for (int i = t; i < 6240; i += 256) {
        int ch = i / 390; int slot = i - ch*390;
        int r = slot / 130; int pp = slot - r*130;
        int row = gr + r - 1, px = pp - 1;
        float v = 0.f;
        if ((unsigned)row < 128u && (unsigned)px < 128u) {
            if (ch < 12)
                v = ((row + px) & 1) ? x[((b*12 + ch) << 14) + (row << 7) + px] : 0.f;
            else
                v = cond[((b*4 + (ch-12)) << 14) + (row << 7) + px];
        }
        dyn[(r*130 + pp)*20 + ch] = rna(v);
    }
    asm volatile("cp.async.wait_group 0;" ::: "memory");
    __syncthreads();

    // ---- phase 1: h1 = relu(conv1(z)), M=128 N=64 K=144 ----
    float d1[32];
    #pragma unroll
    for (int i = 0; i < 32; i++) d1[i] = 0.f;

    #pragma unroll
    for (int tap = 0; tap < 9; tap++) {
        int kh = tap / 3;
        int dw = tap - kh*3 - 1;
        const float* zr = dyn + kh*2600 + (dw + 1)*20;
        #pragma unroll
        for (int kk = 0; kk < 2; kk++) {
            int cc = tap*2 + kk;
            uint32_t a[2][4];
            #pragma unroll
            for (int mm = 0; mm < 2; mm++) {
                const float* base0 = zr + (px0 + mm*16 + g)*20 + kk*8 + tig;
                a[mm][0] = __float_as_uint(base0[0]);
                a[mm][1] = __float_as_uint(base0[160]);
                a[mm][2] = __float_as_uint(base0[4]);
                a[mm][3] = __float_as_uint(base0[164]);
            }
            const float2* bB = (const float2*)(dyn + 7800) + cc*256 + (nc0 >> 3)*32 + lane;
            #pragma unroll
            for (int ntl = 0; ntl < 4; ntl++) {
                float2 bb = bB[ntl*32];
                uint32_t b0 = __float_as_uint(bb.x), bb1 = __float_as_uint(bb.y);
                mma_tf32(&d1[ntl*8],     a[0][0], a[0][1], a[0][2], a[0][3], b0, bb1);
                mma_tf32(&d1[ntl*8 + 4], a[1][0], a[1][1], a[1][2], a[1][3], b0, bb1);
            }
        }
    }

    // epilogue 1: relu+bias -> rna fp32 -> A2 [128][68] (overwrites B1 region)
    __syncthreads();
    {
        float* A2 = dyn + 7800;
        #pragma unroll
        for (int mm = 0; mm < 2; mm++) {
            int row = px0 + mm*16 + g;
            #pragma unroll
            for (int ntl = 0; ntl < 4; ntl++) {
                int col = nc0 + ntl*8 + 2*tig;
                float bb0 = s_b1[col], bb1 = s_b1[col+1];
                A2[ row     *68 + col    ] = rna(fmaxf(d1[ntl*8+mm*4+0] + bb0, 0.f));
                A2[ row     *68 + col + 1] = rna(fmaxf(d1[ntl*8+mm*4+1] + bb1, 0.f));
                A2[(row + 8)*68 + col    ] = rna(fmaxf(d1[ntl*8+mm*4+2] + bb0, 0.f));
                A2[(row + 8)*68 + col + 1] = rna(fmaxf(d1[ntl*8+mm*4+3] + bb1, 0.f));
            }
        }
    }
    __syncthreads();

    // ---- phase 2: h2 = relu(conv2(h1)), M=128 N=64 K=64 ----
    float d2[32];
    #pragma unroll
    for (int i = 0; i < 32; i++) d2[i] = 0.f;
    {
        const float* A2 = dyn + 7800;
        #pragma unroll
        for (int kk = 0; kk < 8; kk++) {
            uint32_t a[2][4];
            #pragma unroll
            for (int mm = 0; mm < 2; mm++) {
                const float* base0 = A2 + (px0 + mm*16 + g)*68 + kk*8 + tig;
                a[mm][0] = __float_as_uint(base0[0]);
                a[mm][1] = __float_as_uint(base0[544]);
                a[mm][2] = __float_as_uint(base0[4]);
                a[mm][3] = __float_as_uint(base0[548]);
            }
            const float2* bB = (const float2*)(dyn + 17016) + kk*256 + (nc0 >> 3)*32 + lane;
            #pragma unroll
            for (int ntl = 0; ntl < 4; ntl++) {
                float2 bb = bB[ntl*32];
                uint32_t b0 = __float_as_uint(bb.x), bb1 = __float_as_uint(bb.y);
                mma_tf32(&d2[ntl*8],     a[0][0], a[0][1], a[0][2], a[0][3], b0, bb1);
                mma_tf32(&d2[ntl*8 + 4], a[1][0], a[1][1], a[1][2], a[1][3], b0, bb1);
            }
        }
    }

    // epilogue 2: relu+bias -> bf16 staging (overwrites z region) -> gmem
    __syncthreads();
    {
        uint32_t* stg = (uint32_t*)dyn;
        #pragma unroll
        for (int mm = 0; mm < 2; mm++) {
            int row = px0 + mm*16 + g;
            #pragma unroll
            for (int ntl = 0; ntl < 4; ntl++) {
                int col = nc0 + ntl*8 + 2*tig;
                float bb0 = s_b2[col], bb1 = s_b2[col+1];
                __nv_bfloat162 h0 = __floats2bfloat162_rn(
                    fmaxf(d2[ntl*8+mm*4+0] + bb0, 0.f),
                    fmaxf(d2[ntl*8+mm*4+1] + bb1, 0.f));
                __nv_bfloat162 h1v = __floats2bfloat162_rn(
                    fmaxf(d2[ntl*8+mm*4+2] + bb0, 0.f),
                    fmaxf(d2[ntl*8+mm*4+3] + bb1, 0.f));
                stg[ row     *32 + (col >> 1)] = *(uint32_t*)&h0;
                stg[(row + 8)*32 + (col >> 1)] = *(uint32_t*)&h1v;
            }
        }
    }
    __syncthreads();
    {
        const uint4* s4 = (const uint4*)dyn;
        uint4* dst = (uint4*)(g_h2h + ((size_t)(b*128 + gr) * 128) * 64);
        #pragma unroll
        for (int i = t; i < 1024; i += 256) dst[i] = s4[i];
    }
}

// ---------------------------------------------------------------------------
// RQS spline (register-resident 8-bin scan) — validated in R1
// ---------------------------------------------------------------------------
__device__ __forceinline__ float rqs_eval(const float* p, float xa, float& lad) {
    bool inside = (xa >= -3.f) && (xa <= 3.f);
    float xc = fminf(fmaxf(xa, -3.f), 3.f);

    float mw = p[0], mh = p[8];
    #pragma unroll
    for (int k = 1; k < 8; k++) { mw = fmaxf(mw, p[k]); mh = fmaxf(mh, p[8+k]); }
    float ew[8], eh[8]; float sw = 0.f, sh = 0.f;
    #pragma unroll
    for (int k = 0; k < 8; k++) {
        ew[k] = expf(p[k] - mw);   sw += ew[k];
        eh[k] = expf(p[8+k] - mh); sh += eh[k];
    }
    float rw = (1.f - 0.008f) / sw;
    float rh = (1.f - 0.008f) / sh;

    float sp[7];
    #pragma unroll
    for (int k = 0; k < 7; k++) {
        float u = p[16 + k];
        sp[k] = (u > 15.f) ? u : log1pf(expf(u));
    }

    float cw = -3.f, ch = -3.f, cumw = 0.f, cumh = 0.f, dprev = 1.f;
    float icw = -3.f, iw = 1.f, ich = -3.f, ih = 1.f, id0 = 1.f, id1 = 1.f;
    #pragma unroll
    for (int k = 0; k < 8; k++) {
        cumw += 0.001f + ew[k]*rw;
        cumh += 0.001f + eh[k]*rh;
        float cwn = (k == 7) ? 3.f : fmaf(6.f, cumw, -3.f);
        float chn = (k == 7) ? 3.f : fmaf(6.f, cumh, -3.f);
        float dn  = (k == 7) ? 1.f : (0.001f + sp[k]);
        if (xc >= cw) { icw = cw; iw = cwn - cw; ich = ch; ih = chn - ch; id0 = dprev; id1 = dn; }
        cw = cwn; ch = chn; dprev = dn;
    }

    float riw   = 1.f / iw;
    float delta = ih * riw;
    float theta = (xc - icw) * riw;
    float omt = 1.f - theta;
    float t1  = theta * omt;
    float th2 = theta * theta;
    float num = ih * (delta*th2 + id0*t1);
    float den = delta + (id0 + id1 - 2.f*delta)*t1;
    float y   = ich + num / den;
    float dnum = delta*delta*(id1*th2 + 2.f*delta*t1 + id0*omt*omt);
    float l = logf(dnum) - 2.f*logf(den);

    lad = inside ? l : 0.f;
    return inside ? y : xa;
}

// ---------------------------------------------------------------------------
// conv3 via mma.sync bf16 (m16n8k16) + fused RQS epilogue (validated R7).
// CTA = (image row, N-half): M=128 px, N=144, K=576 in 18 stages.
// ---------------------------------------------------------------------------
#define SLOT 19456u

__device__ __forceinline__ void issue_stage(int st, int t, int b, int gr, int hh,
                                            uint32_t base){
    int tap = st >> 1, ih = st & 1;
    int kh = tap / 3;
    int dh = kh - 1;
    int dw = (tap - kh*3) - 1;
    uint32_t aslot = base + (uint32_t)(st & 3) * SLOT;
    int grs = gr + dh;
    bool rowok = (unsigned)grs < 128u;
    const __nv_bfloat16* h2row = g_h2h + (size_t)(b * 128 + (rowok ? grs : 0)) * 128 * 64;

    #pragma unroll
    for (int it = 0; it < 2; it++) {
        int id = it * 256 + t;
        int p = id >> 2, q = id & 3;
        int pw = p + dw;
        bool ok = rowok && ((unsigned)pw < 128u);
        const __nv_bfloat16* src = h2row + ((ok ? pw : 0) * 64 + ih * 32 + q * 8);
        cp16(aslot + (uint32_t)(p * 80 + q * 16), src, ok ? 16u : 0u);
    }
    const uint32_t* wb = g_W3Bh + (size_t)st * 4608 + (size_t)hh * 2304;
    #pragma unroll
    for (int it = 0; it < 3; it++) {
        int i = it * 256 + t;
        if (i < 576)
            cp16(aslot + 10240u + (uint32_t)(i * 16), wb + i * 4, 16u);
    }
    CP_COMMIT();
}

__global__ void __launch_bounds__(256, 2) k_conv3_mma(const float* __restrict__ x,
                                                      const float* __restrict__ b3,
                                                      float* __restrict__ out) {
    extern __shared__ float dyn[];
    __shared__ float s_b3[276];
    __shared__ float s_red[8];

    int b  = blockIdx.y;
    int bx = blockIdx.x;
    int gr = bx >> 1;
    int hh = bx & 1;
    int t  = threadIdx.x;
    int w = t >> 5, lane = t & 31;
    int g = lane >> 2, tig = lane & 3;
    int px0 = (w & 3) * 32;
    int qq  = w >> 2;

    uint32_t base = s2u(dyn);

    for (int i = t; i < 276; i += 256) s_b3[i] = b3[i];

    float d[72];
    #pragma unroll
    for (int i = 0; i < 72; i++) d[i] = 0.f;

    issue_stage(0, t, b, gr, hh, base);
    issue_stage(1, t, b, gr, hh, base);
    issue_stage(2, t, b, gr, hh, base);

    for (int s = 0; s < 18; s++) {
        if (s < 16)       asm volatile("cp.async.wait_group 2;" ::: "memory");
        else if (s == 16) asm volatile("cp.async.wait_group 1;" ::: "memory");
        else              asm volatile("cp.async.wait_group 0;" ::: "memory");
        __syncthreads();

        if (s < 15) issue_stage(s + 3, t, b, gr, hh, base);

        const char* sAb = (const char*)dyn + (size_t)(s & 3) * SLOT;
        const char* sBb = sAb + 10240 + (size_t)lane * 8;

        #pragma unroll
        for (int kk = 0; kk < 2; kk++) {
            const char* ar = sAb + (size_t)kk * 32 + (size_t)tig * 4;
            uint32_t a00 = *(const uint32_t*)(ar + (px0+g   )*80);
            uint32_t a01 = *(const uint32_t*)(ar + (px0+g+ 8)*80);
            uint32_t a02 = *(const uint32_t*)(ar + (px0+g   )*80 + 16);
            uint32_t a03 = *(const uint32_t*)(ar + (px0+g+ 8)*80 + 16);
            uint32_t a10 = *(const uint32_t*)(ar + (px0+g+16)*80);
            uint32_t a11 = *(const uint32_t*)(ar + (px0+g+24)*80);
            uint32_t a12 = *(const uint32_t*)(ar + (px0+g+16)*80 + 16);
            uint32_t a13 = *(const uint32_t*)(ar + (px0+g+24)*80 + 16);
            const char* bp = sBb + (size_t)kk * 4608 + (size_t)(qq * 9) * 256;
            #pragma unroll
            for (int nt = 0; nt < 9; nt++) {
                uint2 bb = *(const uint2*)(bp + (size_t)nt * 256);
                mma_bf16(&d[nt*8],     a00, a01, a02, a03, bb.x, bb.y);
                mma_bf16(&d[nt*8 + 4], a10, a11, a12, a13, bb.x, bb.y);
            }
        }
    }

    __syncthreads();
    {
        float* sD = dyn;
        #pragma unroll
        for (int m = 0; m < 2; m++) {
            int row0 = px0 + m*16 + g;
            #pragma unroll
            for (int nt = 0; nt < 9; nt++) {
                int col = qq*72 + nt*8 + 2*tig;
                sD[ row0      * 145 + col    ] = d[nt*8 + m*4 + 0];
                sD[ row0      * 145 + col + 1] = d[nt*8 + m*4 + 1];
                sD[(row0 + 8) * 145 + col    ] = d[nt*8 + m*4 + 2];
                sD[(row0 + 8) * 145 + col + 1] = d[nt*8 + m*4 + 3];
            }
        }
    }
    __syncthreads();

    float ladsum = 0.f;
    {
        const float* sD = dyn;
        int px = t & 127;
        int clbase = (t >> 7) * 3;
        int par = (gr + px) & 1;
        #pragma unroll
        for (int cc = 0; cc < 3; cc++) {
            int cl = clbase + cc;
            int c  = hh*6 + cl;
            float p[23];
            #pragma unroll
            for (int sidx = 0; sidx < 23; sidx++)
                p[sidx] = sD[px*145 + cl*24 + sidx] + s_b3[c*23 + sidx];

            size_t xbase = (((size_t)(b*12 + c)) << 14) + ((size_t)gr << 7) + px;
            float xv = x[xbase];
            float xa = par ? 0.f : xv;
            float xf = par ? xv : 0.f;
            float lad;
            float y = rqs_eval(p, xa, lad);
            out[xbase] = xf + y;
            ladsum += lad;
        }
    }
    #pragma unroll
    for (int o = 16; o > 0; o >>= 1)
        ladsum += __shfl_down_sync(0xffffffffu, ladsum, o);
    if (lane == 0) s_red[w] = ladsum;
    __syncthreads();
    if (t == 0) {
        float v = 0.f;
        #pragma unroll
        for (int i = 0; i < 8; i++) v += s_red[i];
        g_lad[b*256 + bx] = v;
    }
}

// ---------------------------------------------------------------------------
// Final logdet reduction: 256 partials per image + input logdet.
// ---------------------------------------------------------------------------
__global__ void k_red(const float* __restrict__ logdet_in, float* __restrict__ out) {
    __shared__ float s[8];
    int b = blockIdx.x, t = threadIdx.x;
    float v = g_lad[b*256 + t];
    #pragma unroll
    for (int o = 16; o > 0; o >>= 1) v += __shfl_down_sync(0xffffffffu, v, o);
    if ((t & 31) == 0) s[t >> 5] = v;
    __syncthreads();
    if (t == 0) {
        float r = logdet_in[b];
        #pragma unroll
        for (int i = 0; i < 8; i++) r += s[i];
        out[XOUT_SIZE + b] = r;
    }
}

// ---------------------------------------------------------------------------
extern "C" void kernel_launch(void* const* d_in, const int* in_sizes, int n_in,
                              void* d_out, int out_size) {
    const float* x      = (const float*)d_in[0];
    const float* logdet = (const float*)d_in[1];
    const float* cond   = (const float*)d_in[2];
    const float* W1     = (const float*)d_in[3];
    const float* b1     = (const float*)d_in[4];
    const float* W2     = (const float*)d_in[5];
    const float* b2     = (const float*)d_in[6];
    const float* W3     = (const float*)d_in[7];
    const float* b3     = (const float*)d_in[8];
    float* out = (float*)d_out;

    const int smem12 = 21112 * 4;            // 84,448 B
    const int smem3  = 4 * SLOT;             // 77,824 B
    cudaFuncSetAttribute(k_conv12, cudaFuncAttributeMaxDynamicSharedMemorySize, smem12);
    cudaFuncSetAttribute(k_conv3_mma, cudaFuncAttributeMaxDynamicSharedMemorySize, smem3);

    k_trans<<<376, 256>>>(W1, W2, W3);
    k_conv12<<<dim3(128, 16), 256, smem12>>>(x, cond, b1, b2);
    k_conv3_mma<<<dim3(256, 16), 256, smem3>>>(x, b3, out);
    k_red<<<16, 256>>>(logdet, out);
}

// round 9
// speedup vs baseline: 5.8856x; 1.0711x over previous
#include <cuda_runtime.h>
#include <cuda_bf16.h>
#include <math.h>
#include <stdint.h>

// Problem constants
#define XOUT_SIZE (16*12*128*128)

// Scratch (device globals — no cudaMalloc allowed)
__device__ __align__(16) __nv_bfloat16 g_h2h[16*128*128*64]; // conv2 out [b][h][w][ch] bf16
__device__ __align__(16) float g_W1F[18*8*64];               // conv1 tf32 B-frags
__device__ __align__(16) float g_W2F[8*8*64];                // conv2 tf32 B-frags
__device__ __align__(16) uint32_t g_W3Bh[18*2*2*18*64];      // [st][hh][kk][nt][lane*2+reg]
__device__ float g_lad[16*256];                              // per-(image,row,half) logdet partials

// ---------------------------------------------------------------------------
// helpers
// ---------------------------------------------------------------------------
__device__ __forceinline__ uint32_t s2u(const void* p){
    uint32_t a;
    asm("{ .reg .u64 t; cvta.to.shared.u64 t, %1; cvt.u32.u64 %0, t; }" : "=r"(a) : "l"(p));
    return a;
}
__device__ __forceinline__ void cp16(uint32_t dst, const void* src, uint32_t sz){
    asm volatile("cp.async.cg.shared.global [%0], [%1], 16, %2;"
                 :: "r"(dst), "l"(src), "r"(sz) : "memory");
}
#define CP_COMMIT() asm volatile("cp.async.commit_group;" ::: "memory")

__device__ __forceinline__ float rna(float v){
    uint32_t o;
    asm("cvt.rna.tf32.f32 %0, %1;" : "=r"(o) : "f"(v));
    return __uint_as_float(o);
}

__device__ __forceinline__ void mma_bf16(float* d, uint32_t a0, uint32_t a1,
                                         uint32_t a2, uint32_t a3,
                                         uint32_t b0, uint32_t b1){
    asm volatile(
        "mma.sync.aligned.m16n8k16.row.col.f32.bf16.bf16.f32 "
        "{%0,%1,%2,%3}, {%4,%5,%6,%7}, {%8,%9}, {%0,%1,%2,%3};"
        : "+f"(d[0]), "+f"(d[1]), "+f"(d[2]), "+f"(d[3])
        : "r"(a0), "r"(a1), "r"(a2), "r"(a3), "r"(b0), "r"(b1));
}

__device__ __forceinline__ void mma_tf32(float* d, uint32_t a0, uint32_t a1,
                                         uint32_t a2, uint32_t a3,
                                         uint32_t b0, uint32_t b1){
    asm volatile(
        "mma.sync.aligned.m16n8k8.row.col.f32.tf32.tf32.f32 "
        "{%0,%1,%2,%3}, {%4,%5,%6,%7}, {%8,%9}, {%0,%1,%2,%3};"
        : "+f"(d[0]), "+f"(d[1]), "+f"(d[2]), "+f"(d[3])
        : "r"(a0), "r"(a1), "r"(a2), "r"(a3), "r"(b0), "r"(b1));
}

// ---------------------------------------------------------------------------
// Weight packing (validated R8)
// ---------------------------------------------------------------------------
__global__ void k_trans(const float* __restrict__ W1,
                        const float* __restrict__ W2,
                        const float* __restrict__ W3) {
    int i = blockIdx.x * 256 + threadIdx.x;
    if (i < 9216) {
        int cc = i >> 9;  int r = i & 511;
        int nt = r >> 6;  int l2 = r & 63;
        int lane = l2 >> 1, jj = l2 & 1;
        int tap = cc >> 1, kk = cc & 1;
        int oc = nt*8 + (lane >> 2);
        int ic = kk*8 + (lane & 3) + 4*jj;
        int kh = tap / 3, kw = tap - kh*3;
        g_W1F[i] = rna(W1[oc*144 + ic*9 + kh*3 + kw]);
    }
    int j = i - 9216;
    if (j >= 0 && j < 4096) {
        int kk = j >> 9;  int r = j & 511;
        int nt = r >> 6;  int l2 = r & 63;
        int lane = l2 >> 1, jj = l2 & 1;
        int oc = nt*8 + (lane >> 2);
        int ic = kk*8 + (lane & 3) + 4*jj;
        g_W2F[j] = rna(W2[oc*64 + ic]);
    }
    int m = j - 4096;
    if (m >= 0 && m < 18*4608) {
        int st = m / 4608;  int r1 = m - st*4608;
        int hh = r1 / 2304; int r2 = r1 - hh*2304;
        int kk = r2 / 1152; int r3 = r2 - kk*1152;
        int nt = r3 >> 6;   int l2 = r3 & 63;
        int lane = l2 >> 1, reg = l2 & 1;
        int n   = hh*144 + nt*8 + (lane >> 2);
        int tap = st >> 1, ih = st & 1;
        int ic0 = ih*32 + kk*16 + 2*(lane & 3) + reg*8;
        int c   = n / 24, s = n - c*24;
        float lo = 0.f, hi = 0.f;
        if (s < 23) {
            lo = W3[(c*23 + s)*576 + ic0*9 + tap];
            hi = W3[(c*23 + s)*576 + (ic0+1)*9 + tap];
        }
        __nv_bfloat162 w = __floats2bfloat162_rn(lo, hi);
        g_W3Bh[m] = *(uint32_t*)&w;
    }
}

// ---------------------------------------------------------------------------
// Fused conv1+conv2 tf32 MMA (validated R8)
// ---------------------------------------------------------------------------
__global__ void __launch_bounds__(256, 2) k_conv12(const float* __restrict__ x,
                                                   const float* __restrict__ cond,
                                                   const float* __restrict__ b1,
                                                   const float* __restrict__ b2) {
    extern __shared__ float dyn[];
    __shared__ float s_b1[64], s_b2[64];

    int b  = blockIdx.y;
    int gr = blockIdx.x;
    int t  = threadIdx.x;
    int w = t >> 5, lane = t & 31;
    int g = lane >> 2, tig = lane & 3;
    int px0 = (w & 3) * 32;
    int nc0 = (w >> 2) * 32;

    if (t < 64)       s_b1[t] = b1[t];
    else if (t < 128) s_b2[t-64] = b2[t-64];

    {
        uint32_t b1s = s2u(dyn + 7800);
        for (int i = t; i < 2304; i += 256) cp16(b1s + (uint32_t)(i*16), g_W1F + i*4, 16u);
        uint32_t b2s = s2u(dyn + 17016);
        for (int i = t; i < 1024; i += 256) cp16(b2s + (uint32_t)(i*16), g_W2F + i*4, 16u);
        CP_COMMIT();
    }

    for (int i = t; i < 6240; i += 256) {
        int ch = i / 390; int slot = i - ch*390;
        int r = slot / 130; int pp = slot - r*130;
        int row = gr + r - 1, px = pp - 1;
        float v = 0.f;
        if ((unsigned)row < 128u && (unsigned)px < 128u) {
            if (ch < 12)
                v = ((row + px) & 1) ? x[((b*12 + ch) << 14) + (row << 7) + px] : 0.f;
            else
                v = cond[((b*4 + (ch-12)) << 14) + (row << 7) + px];
        }
        dyn[(r*130 + pp)*20 + ch] = rna(v);
    }
    asm volatile("cp.async.wait_group 0;" ::: "memory");
    __syncthreads();

    float d1[32];
    #pragma unroll
    for (int i = 0; i < 32; i++) d1[i] = 0.f;

    #pragma unroll
    for (int tap = 0; tap < 9; tap++) {
        int kh = tap / 3;
        int dw = tap - kh*3 - 1;
        const float* zr = dyn + kh*2600 + (dw + 1)*20;
        #pragma unroll
        for (int kk = 0; kk < 2; kk++) {
            int cc = tap*2 + kk;
            uint32_t a[2][4];
            #pragma unroll
            for (int mm = 0; mm < 2; mm++) {
                const float* base0 = zr + (px0 + mm*16 + g)*20 + kk*8 + tig;
                a[mm][0] = __float_as_uint(base0[0]);
                a[mm][1] = __float_as_uint(base0[160]);
                a[mm][2] = __float_as_uint(base0[4]);
                a[mm][3] = __float_as_uint(base0[164]);
            }
            const float2* bB = (const float2*)(dyn + 7800) + cc*256 + (nc0 >> 3)*32 + lane;
            #pragma unroll
            for (int ntl = 0; ntl < 4; ntl++) {
                float2 bb = bB[ntl*32];
                uint32_t b0 = __float_as_uint(bb.x), bb1 = __float_as_uint(bb.y);
                mma_tf32(&d1[ntl*8],     a[0][0], a[0][1], a[0][2], a[0][3], b0, bb1);
                mma_tf32(&d1[ntl*8 + 4], a[1][0], a[1][1], a[1][2], a[1][3], b0, bb1);
            }
        }
    }

    __syncthreads();
    {
        float* A2 = dyn + 7800;
        #pragma unroll
        for (int mm = 0; mm < 2; mm++) {
            int row = px0 + mm*16 + g;
            #pragma unroll
            for (int ntl = 0; ntl < 4; ntl++) {
                int col = nc0 + ntl*8 + 2*tig;
                float bb0 = s_b1[col], bb1 = s_b1[col+1];
                A2[ row     *68 + col    ] = rna(fmaxf(d1[ntl*8+mm*4+0] + bb0, 0.f));
                A2[ row     *68 + col + 1] = rna(fmaxf(d1[ntl*8+mm*4+1] + bb1, 0.f));
                A2[(row + 8)*68 + col    ] = rna(fmaxf(d1[ntl*8+mm*4+2] + bb0, 0.f));
                A2[(row + 8)*68 + col + 1] = rna(fmaxf(d1[ntl*8+mm*4+3] + bb1, 0.f));
            }
        }
    }
    __syncthreads();

    float d2[32];
    #pragma unroll
    for (int i = 0; i < 32; i++) d2[i] = 0.f;
    {
        const float* A2 = dyn + 7800;
        #pragma unroll
        for (int kk = 0; kk < 8; kk++) {
            uint32_t a[2][4];
            #pragma unroll
            for (int mm = 0; mm < 2; mm++) {
                const float* base0 = A2 + (px0 + mm*16 + g)*68 + kk*8 + tig;
                a[mm][0] = __float_as_uint(base0[0]);
                a[mm][1] = __float_as_uint(base0[544]);
                a[mm][2] = __float_as_uint(base0[4]);
                a[mm][3] = __float_as_uint(base0[548]);
            }
            const float2* bB = (const float2*)(dyn + 17016) + kk*256 + (nc0 >> 3)*32 + lane;
            #pragma unroll
            for (int ntl = 0; ntl < 4; ntl++) {
                float2 bb = bB[ntl*32];
                uint32_t b0 = __float_as_uint(bb.x), bb1 = __float_as_uint(bb.y);
                mma_tf32(&d2[ntl*8],     a[0][0], a[0][1], a[0][2], a[0][3], b0, bb1);
                mma_tf32(&d2[ntl*8 + 4], a[1][0], a[1][1], a[1][2], a[1][3], b0, bb1);
            }
        }
    }

    __syncthreads();
    {
        uint32_t* stg = (uint32_t*)dyn;
        #pragma unroll
        for (int mm = 0; mm < 2; mm++) {
            int row = px0 + mm*16 + g;
            #pragma unroll
            for (int ntl = 0; ntl < 4; ntl++) {
                int col = nc0 + ntl*8 + 2*tig;
                float bb0 = s_b2[col], bb1 = s_b2[col+1];
                __nv_bfloat162 h0 = __floats2bfloat162_rn(
                    fmaxf(d2[ntl*8+mm*4+0] + bb0, 0.f),
                    fmaxf(d2[ntl*8+mm*4+1] + bb1, 0.f));
                __nv_bfloat162 h1v = __floats2bfloat162_rn(
                    fmaxf(d2[ntl*8+mm*4+2] + bb0, 0.f),
                    fmaxf(d2[ntl*8+mm*4+3] + bb1, 0.f));
                stg[ row     *32 + (col >> 1)] = *(uint32_t*)&h0;
                stg[(row + 8)*32 + (col >> 1)] = *(uint32_t*)&h1v;
            }
        }
    }
    __syncthreads();
    {
        const uint4* s4 = (const uint4*)dyn;
        uint4* dst = (uint4*)(g_h2h + ((size_t)(b*128 + gr) * 128) * 64);
        #pragma unroll
        for (int i = t; i < 1024; i += 256) dst[i] = s4[i];
    }
}

// ---------------------------------------------------------------------------
// RQS spline (validated R1)
// ---------------------------------------------------------------------------
__device__ __forceinline__ float rqs_eval(const float* p, float xa, float& lad) {
    bool inside = (xa >= -3.f) && (xa <= 3.f);
    float xc = fminf(fmaxf(xa, -3.f), 3.f);

    float mw = p[0], mh = p[8];
    #pragma unroll
    for (int k = 1; k < 8; k++) { mw = fmaxf(mw, p[k]); mh = fmaxf(mh, p[8+k]); }
    float ew[8], eh[8]; float sw = 0.f, sh = 0.f;
    #pragma unroll
    for (int k = 0; k < 8; k++) {
        ew[k] = expf(p[k] - mw);   sw += ew[k];
        eh[k] = expf(p[8+k] - mh); sh += eh[k];
    }
    float rw = (1.f - 0.008f) / sw;
    float rh = (1.f - 0.008f) / sh;

    float sp[7];
    #pragma unroll
    for (int k = 0; k < 7; k++) {
        float u = p[16 + k];
        sp[k] = (u > 15.f) ? u : log1pf(expf(u));
    }

    float cw = -3.f, ch = -3.f, cumw = 0.f, cumh = 0.f, dprev = 1.f;
    float icw = -3.f, iw = 1.f, ich = -3.f, ih = 1.f, id0 = 1.f, id1 = 1.f;
    #pragma unroll
    for (int k = 0; k < 8; k++) {
        cumw += 0.001f + ew[k]*rw;
        cumh += 0.001f + eh[k]*rh;
        float cwn = (k == 7) ? 3.f : fmaf(6.f, cumw, -3.f);
        float chn = (k == 7) ? 3.f : fmaf(6.f, cumh, -3.f);
        float dn  = (k == 7) ? 1.f : (0.001f + sp[k]);
        if (xc >= cw) { icw = cw; iw = cwn - cw; ich = ch; ih = chn - ch; id0 = dprev; id1 = dn; }
        cw = cwn; ch = chn; dprev = dn;
    }

    float riw   = 1.f / iw;
    float delta = ih * riw;
    float theta = (xc - icw) * riw;
    float omt = 1.f - theta;
    float t1  = theta * omt;
    float th2 = theta * theta;
    float num = ih * (delta*th2 + id0*t1);
    float den = delta + (id0 + id1 - 2.f*delta)*t1;
    float y   = ich + num / den;
    float dnum = delta*delta*(id1*th2 + 2.f*delta*t1 + id0*omt*omt);
    float l = logf(dnum) - 2.f*logf(den);

    lad = inside ? l : 0.f;
    return inside ? y : xa;
}

// ---------------------------------------------------------------------------
// conv3 bf16 MMA with RESIDENT A: 3 h2 rows (130 px x 64 ch, pitch 144 B)
// loaded once; only B streams through a 4-slot ring (9216 B/stage).
// CTA = (image row, N-half). smem = 56160 (A) + 36864 (B) = 93024 B.
// Epilogue sD (74240 B) reuses the A region.
// ---------------------------------------------------------------------------
#define A_BYTES   56160u
#define A_ROWPITCH 18720   // 130 * 144
#define BSLOT 9216u

__device__ __forceinline__ void issue_B(int st, int t, int hh, uint32_t baseB){
    uint32_t dst = baseB + (uint32_t)(st & 3) * BSLOT;
    const uint32_t* wb = g_W3Bh + (size_t)st * 4608 + (size_t)hh * 2304;
    #pragma unroll
    for (int it = 0; it < 3; it++) {
        int i = it * 256 + t;
        if (i < 576)
            cp16(dst + (uint32_t)(i * 16), wb + i * 4, 16u);
    }
    CP_COMMIT();
}

__global__ void __launch_bounds__(256, 2) k_conv3_mma(const float* __restrict__ x,
                                                      const float* __restrict__ b3,
                                                      float* __restrict__ out) {
    extern __shared__ float dyn[];
    __shared__ float s_b3[276];
    __shared__ float s_red[8];

    int b  = blockIdx.y;
    int bx = blockIdx.x;
    int gr = bx >> 1;
    int hh = bx & 1;
    int t  = threadIdx.x;
    int w = t >> 5, lane = t & 31;
    int g = lane >> 2, tig = lane & 3;
    int px0 = (w & 3) * 32;
    int qq  = w >> 2;

    char* sA = (char*)dyn;
    uint32_t baseB = s2u(dyn) + A_BYTES;

    for (int i = t; i < 276; i += 256) s_b3[i] = b3[i];

    // zero boundary px entries (px index 0 and 129) for all 3 rows
    if (t < 48) {
        int r = t >> 4; int rem = t & 15;
        int e = (rem >> 3) ? 129 : 0;
        int q = rem & 7;
        *(uint4*)(sA + r*A_ROWPITCH + e*144 + q*16) = make_uint4(0,0,0,0);
    }
    // resident A: rows gr-1, gr, gr+1 (OOB rows zeroed)
    #pragma unroll
    for (int r = 0; r < 3; r++) {
        int row = gr + r - 1;
        if ((unsigned)row < 128u) {
            const __nv_bfloat16* src = g_h2h + (size_t)(b*128 + row) * 128 * 64;
            #pragma unroll
            for (int it = 0; it < 4; it++) {
                int i = it * 256 + t;
                int px = i >> 3, q = i & 7;
                cp16(s2u(sA) + (uint32_t)(r*A_ROWPITCH + (px+1)*144 + q*16),
                     src + px*64 + q*8, 16u);
            }
        } else {
            #pragma unroll
            for (int it = 0; it < 5; it++) {
                int i = it * 256 + t;
                if (i < 1040) {
                    int e = i >> 3, q = i & 7;
                    *(uint4*)(sA + r*A_ROWPITCH + e*144 + q*16) = make_uint4(0,0,0,0);
                }
            }
        }
    }
    CP_COMMIT();   // A group

    float d[72];
    #pragma unroll
    for (int i = 0; i < 72; i++) d[i] = 0.f;

    issue_B(0, t, hh, baseB);
    issue_B(1, t, hh, baseB);
    issue_B(2, t, hh, baseB);

    for (int s = 0; s < 18; s++) {
        if (s < 16)       asm volatile("cp.async.wait_group 2;" ::: "memory");
        else if (s == 16) asm volatile("cp.async.wait_group 1;" ::: "memory");
        else              asm volatile("cp.async.wait_group 0;" ::: "memory");
        __syncthreads();

        if (s < 15) issue_B(s + 3, t, hh, baseB);

        int tap = s >> 1, ih = s & 1;
        int kh = tap / 3;
        int dw = tap - kh*3 - 1;
        const char* arow = sA + kh*A_ROWPITCH + (px0 + g + 1 + dw)*144 + ih*64;
        const char* sBb = (const char*)dyn + A_BYTES + (size_t)(s & 3)*BSLOT
                          + (size_t)lane * 8;

        #pragma unroll
        for (int kk = 0; kk < 2; kk++) {
            const char* ar = arow + kk*32 + tig*4;
            uint32_t a00 = *(const uint32_t*)(ar);
            uint32_t a01 = *(const uint32_t*)(ar + 8*144);
            uint32_t a02 = *(const uint32_t*)(ar + 16);
            uint32_t a03 = *(const uint32_t*)(ar + 8*144 + 16);
            uint32_t a10 = *(const uint32_t*)(ar + 16*144);
            uint32_t a11 = *(const uint32_t*)(ar + 24*144);
            uint32_t a12 = *(const uint32_t*)(ar + 16*144 + 16);
            uint32_t a13 = *(const uint32_t*)(ar + 24*144 + 16);
            const char* bp = sBb + (size_t)kk * 4608 + (size_t)(qq * 9) * 256;
            #pragma unroll
            for (int nt = 0; nt < 9; nt++) {
                uint2 bb = *(const uint2*)(bp + (size_t)nt * 256);
                mma_bf16(&d[nt*8],     a00, a01, a02, a03, bb.x, bb.y);
                mma_bf16(&d[nt*8 + 4], a10, a11, a12, a13, bb.x, bb.y);
            }
        }
    }

    // epilogue: accumulators -> sD (reuses A region) -> spline
    __syncthreads();
    {
        float* sD = dyn;
        #pragma unroll
        for (int m = 0; m < 2; m++) {
            int row0 = px0 + m*16 + g;
            #pragma unroll
            for (int nt = 0; nt < 9; nt++) {
                int col = qq*72 + nt*8 + 2*tig;
                sD[ row0      * 145 + col    ] = d[nt*8 + m*4 + 0];
                sD[ row0      * 145 + col + 1] = d[nt*8 + m*4 + 1];
                sD[(row0 + 8) * 145 + col    ] = d[nt*8 + m*4 + 2];
                sD[(row0 + 8) * 145 + col + 1] = d[nt*8 + m*4 + 3];
            }
        }
    }
    __syncthreads();

    float ladsum = 0.f;
    {
        const float* sD = dyn;
        int px = t & 127;
        int clbase = (t >> 7) * 3;
        int par = (gr + px) & 1;
        #pragma unroll
        for (int cc = 0; cc < 3; cc++) {
            int cl = clbase + cc;
            int c  = hh*6 + cl;
            float p[23];
            #pragma unroll
            for (int sidx = 0; sidx < 23; sidx++)
                p[sidx] = sD[px*145 + cl*24 + sidx] + s_b3[c*23 + sidx];

            size_t xbase = (((size_t)(b*12 + c)) << 14) + ((size_t)gr << 7) + px;
            float xv = x[xbase];
            float xa = par ? 0.f : xv;
            float xf = par ? xv : 0.f;
            float lad;
            float y = rqs_eval(p, xa, lad);
            out[xbase] = xf + y;
            ladsum += lad;
        }
    }
    #pragma unroll
    for (int o = 16; o > 0; o >>= 1)
        ladsum += __shfl_down_sync(0xffffffffu, ladsum, o);
    if (lane == 0) s_red[w] = ladsum;
    __syncthreads();
    if (t == 0) {
        float v = 0.f;
        #pragma unroll
        for (int i = 0; i < 8; i++) v += s_red[i];
        g_lad[b*256 + bx] = v;
    }
}

// ---------------------------------------------------------------------------
// Final logdet reduction
// ---------------------------------------------------------------------------
__global__ void k_red(const float* __restrict__ logdet_in, float* __restrict__ out) {
    __shared__ float s[8];
    int b = blockIdx.x, t = threadIdx.x;
    float v = g_lad[b*256 + t];
    #pragma unroll
    for (int o = 16; o > 0; o >>= 1) v += __shfl_down_sync(0xffffffffu, v, o);
    if ((t & 31) == 0) s[t >> 5] = v;
    __syncthreads();
    if (t == 0) {
        float r = logdet_in[b];
        #pragma unroll
        for (int i = 0; i < 8; i++) r += s[i];
        out[XOUT_SIZE + b] = r;
    }
}

// ---------------------------------------------------------------------------
extern "C" void kernel_launch(void* const* d_in, const int* in_sizes, int n_in,
                              void* d_out, int out_size) {
    const float* x      = (const float*)d_in[0];
    const float* logdet = (const float*)d_in[1];
    const float* cond   = (const float*)d_in[2];
    const float* W1     = (const float*)d_in[3];
    const float* b1     = (const float*)d_in[4];
    const float* W2     = (const float*)d_in[5];
    const float* b2     = (const float*)d_in[6];
    const float* W3     = (const float*)d_in[7];
    const float* b3     = (const float*)d_in[8];
    float* out = (float*)d_out;

    const int smem12 = 21112 * 4;                 // 84,448 B
    const int smem3  = A_BYTES + 4 * BSLOT;       // 93,024 B
    cudaFuncSetAttribute(k_conv12, cudaFuncAttributeMaxDynamicSharedMemorySize, smem12);
    cudaFuncSetAttribute(k_conv3_mma, cudaFuncAttributeMaxDynamicSharedMemorySize, smem3);

    k_trans<<<376, 256>>>(W1, W2, W3);
    k_conv12<<<dim3(128, 16), 256, smem12>>>(x, cond, b1, b2);
    k_conv3_mma<<<dim3(256, 16), 256, smem3>>>(x, b3, out);
    k_red<<<16, 256>>>(logdet, out);
}

// round 10
// speedup vs baseline: 6.1014x; 1.0367x over previous
#include <cuda_runtime.h>
#include <cuda_bf16.h>
#include <math.h>
#include <stdint.h>

// Problem constants
#define XOUT_SIZE (16*12*128*128)

// Scratch (device globals — no cudaMalloc allowed)
__device__ __align__(16) __nv_bfloat16 g_h2h[16*128*128*64]; // conv2 out [b][h][w][ch] bf16
__device__ __align__(16) float g_W1F[18*8*64];               // conv1 tf32 B-frags
__device__ __align__(16) float g_W2F[8*8*64];                // conv2 tf32 B-frags
__device__ __align__(16) uint32_t g_W3Bh[18*2*2*18*64];      // [st][hh][kk][nt][lane*2+reg]
__device__ float g_lad[16*256];                              // per-(image,row,half) logdet partials

// ---------------------------------------------------------------------------
// helpers
// ---------------------------------------------------------------------------
__device__ __forceinline__ uint32_t s2u(const void* p){
    uint32_t a;
    asm("{ .reg .u64 t; cvta.to.shared.u64 t, %1; cvt.u32.u64 %0, t; }" : "=r"(a) : "l"(p));
    return a;
}
__device__ __forceinline__ void cp16(uint32_t dst, const void* src, uint32_t sz){
    asm volatile("cp.async.cg.shared.global [%0], [%1], 16, %2;"
                 :: "r"(dst), "l"(src), "r"(sz) : "memory");
}
#define CP_COMMIT() asm volatile("cp.async.commit_group;" ::: "memory")

__device__ __forceinline__ float rna(float v){
    uint32_t o;
    asm("cvt.rna.tf32.f32 %0, %1;" : "=r"(o) : "f"(v));
    return __uint_as_float(o);
}

__device__ __forceinline__ void mma_bf16(float* d, uint32_t a0, uint32_t a1,
                                         uint32_t a2, uint32_t a3,
                                         uint32_t b0, uint32_t b1){
    asm volatile(
        "mma.sync.aligned.m16n8k16.row.col.f32.bf16.bf16.f32 "
        "{%0,%1,%2,%3}, {%4,%5,%6,%7}, {%8,%9}, {%0,%1,%2,%3};"
        : "+f"(d[0]), "+f"(d[1]), "+f"(d[2]), "+f"(d[3])
        : "r"(a0), "r"(a1), "r"(a2), "r"(a3), "r"(b0), "r"(b1));
}

__device__ __forceinline__ void mma_tf32(float* d, uint32_t a0, uint32_t a1,
                                         uint32_t a2, uint32_t a3,
                                         uint32_t b0, uint32_t b1){
    asm volatile(
        "mma.sync.aligned.m16n8k8.row.col.f32.tf32.tf32.f32 "
        "{%0,%1,%2,%3}, {%4,%5,%6,%7}, {%8,%9}, {%0,%1,%2,%3};"
        : "+f"(d[0]), "+f"(d[1]), "+f"(d[2]), "+f"(d[3])
        : "r"(a0), "r"(a1), "r"(a2), "r"(a3), "r"(b0), "r"(b1));
}

// ---------------------------------------------------------------------------
// Weight packing (validated R8)
// ---------------------------------------------------------------------------
__global__ void k_trans(const float* __restrict__ W1,
                        const float* __restrict__ W2,
                        const float* __restrict__ W3) {
    int i = blockIdx.x * 256 + threadIdx.x;
    if (i < 9216) {
        int cc = i >> 9;  int r = i & 511;
        int nt = r >> 6;  int l2 = r & 63;
        int lane = l2 >> 1, jj = l2 & 1;
        int tap = cc >> 1, kk = cc & 1;
        int oc = nt*8 + (lane >> 2);
        int ic = kk*8 + (lane & 3) + 4*jj;
        int kh = tap / 3, kw = tap - kh*3;
        g_W1F[i] = rna(W1[oc*144 + ic*9 + kh*3 + kw]);
    }
    int j = i - 9216;
    if (j >= 0 && j < 4096) {
        int kk = j >> 9;  int r = j & 511;
        int nt = r >> 6;  int l2 = r & 63;
        int lane = l2 >> 1, jj = l2 & 1;
        int oc = nt*8 + (lane >> 2);
        int ic = kk*8 + (lane & 3) + 4*jj;
        g_W2F[j] = rna(W2[oc*64 + ic]);
    }
    int m = j - 4096;
    if (m >= 0 && m < 18*4608) {
        int st = m / 4608;  int r1 = m - st*4608;
        int hh = r1 / 2304; int r2 = r1 - hh*2304;
        int kk = r2 / 1152; int r3 = r2 - kk*1152;
        int nt = r3 >> 6;   int l2 = r3 & 63;
        int lane = l2 >> 1, reg = l2 & 1;
        int n   = hh*144 + nt*8 + (lane >> 2);
        int tap = st >> 1, ih = st & 1;
        int ic0 = ih*32 + kk*16 + 2*(lane & 3) + reg*8;
        int c   = n / 24, s = n - c*24;
        float lo = 0.f, hi = 0.f;
        if (s < 23) {
            lo = W3[(c*23 + s)*576 + ic0*9 + tap];
            hi = W3[(c*23 + s)*576 + (ic0+1)*9 + tap];
        }
        __nv_bfloat162 w = __floats2bfloat162_rn(lo, hi);
        g_W3Bh[m] = *(uint32_t*)&w;
    }
}

// ---------------------------------------------------------------------------
// Fused conv1+conv2 tf32 MMA (validated R8)
// ---------------------------------------------------------------------------
__global__ void __launch_bounds__(256, 2) k_conv12(const float* __restrict__ x,
                                                   const float* __restrict__ cond,
                                                   const float* __restrict__ b1,
                                                   const float* __restrict__ b2) {
    extern __shared__ float dyn[];
    __shared__ float s_b1[64], s_b2[64];

    int b  = blockIdx.y;
    int gr = blockIdx.x;
    int t  = threadIdx.x;
    int w = t >> 5, lane = t & 31;
    int g = lane >> 2, tig = lane & 3;
    int px0 = (w & 3) * 32;
    int nc0 = (w >> 2) * 32;

    if (t < 64)       s_b1[t] = b1[t];
    else if (t < 128) s_b2[t-64] = b2[t-64];

    {
        uint32_t b1s = s2u(dyn + 7800);
        for (int i = t; i < 2304; i += 256) cp16(b1s + (uint32_t)(i*16), g_W1F + i*4, 16u);
        uint32_t b2s = s2u(dyn + 17016);
        for (int i = t; i < 1024; i += 256) cp16(b2s + (uint32_t)(i*16), g_W2F + i*4, 16u);
        CP_COMMIT();
    }

    for (int i = t; i < 6240; i += 256) {
        int ch = i / 390; int slot = i - ch*390;
        int r = slot / 130; int pp = slot - r*130;
        int row = gr + r - 1, px = pp - 1;
        float v = 0.f;
        if ((unsigned)row < 128u && (unsigned)px < 128u) {
            if (ch < 12)
                v = ((row + px) & 1) ? x[((b*12 + ch) << 14) + (row << 7) + px] : 0.f;
            else
                v = cond[((b*4 + (ch-12)) << 14) + (row << 7) + px];
        }
        dyn[(r*130 + pp)*20 + ch] = rna(v);
    }
    asm volatile("cp.async.wait_group 0;" ::: "memory");
    __syncthreads();

    float d1[32];
    #pragma unroll
    for (int i = 0; i < 32; i++) d1[i] = 0.f;

    #pragma unroll
    for (int tap = 0; tap < 9; tap++) {
        int kh = tap / 3;
        int dw = tap - kh*3 - 1;
        const float* zr = dyn + kh*2600 + (dw + 1)*20;
        #pragma unroll
        for (int kk = 0; kk < 2; kk++) {
            int cc = tap*2 + kk;
            uint32_t a[2][4];
            #pragma unroll
            for (int mm = 0; mm < 2; mm++) {
                const float* base0 = zr + (px0 + mm*16 + g)*20 + kk*8 + tig;
                a[mm][0] = __float_as_uint(base0[0]);
                a[mm][1] = __float_as_uint(base0[160]);
                a[mm][2] = __float_as_uint(base0[4]);
                a[mm][3] = __float_as_uint(base0[164]);
            }
            const float2* bB = (const float2*)(dyn + 7800) + cc*256 + (nc0 >> 3)*32 + lane;
            #pragma unroll
            for (int ntl = 0; ntl < 4; ntl++) {
                float2 bb = bB[ntl*32];
                uint32_t b0 = __float_as_uint(bb.x), bb1 = __float_as_uint(bb.y);
                mma_tf32(&d1[ntl*8],     a[0][0], a[0][1], a[0][2], a[0][3], b0, bb1);
                mma_tf32(&d1[ntl*8 + 4], a[1][0], a[1][1], a[1][2], a[1][3], b0, bb1);
            }
        }
    }

    __syncthreads();
    {
        float* A2 = dyn + 7800;
        #pragma unroll
        for (int mm = 0; mm < 2; mm++) {
            int row = px0 + mm*16 + g;
            #pragma unroll
            for (int ntl = 0; ntl < 4; ntl++) {
                int col = nc0 + ntl*8 + 2*tig;
                float bb0 = s_b1[col], bb1 = s_b1[col+1];
                A2[ row     *68 + col    ] = rna(fmaxf(d1[ntl*8+mm*4+0] + bb0, 0.f));
                A2[ row     *68 + col + 1] = rna(fmaxf(d1[ntl*8+mm*4+1] + bb1, 0.f));
                A2[(row + 8)*68 + col    ] = rna(fmaxf(d1[ntl*8+mm*4+2] + bb0, 0.f));
                A2[(row + 8)*68 + col + 1] = rna(fmaxf(d1[ntl*8+mm*4+3] + bb1, 0.f));
            }
        }
    }
    __syncthreads();

    float d2[32];
    #pragma unroll
    for (int i = 0; i < 32; i++) d2[i] = 0.f;
    {
        const float* A2 = dyn + 7800;
        #pragma unroll
        for (int kk = 0; kk < 8; kk++) {
            uint32_t a[2][4];
            #pragma unroll
            for (int mm = 0; mm < 2; mm++) {
                const float* base0 = A2 + (px0 + mm*16 + g)*68 + kk*8 + tig;
                a[mm][0] = __float_as_uint(base0[0]);
                a[mm][1] = __float_as_uint(base0[544]);
                a[mm][2] = __float_as_uint(base0[4]);
                a[mm][3] = __float_as_uint(base0[548]);
            }
            const float2* bB = (const float2*)(dyn + 17016) + kk*256 + (nc0 >> 3)*32 + lane;
            #pragma unroll
            for (int ntl = 0; ntl < 4; ntl++) {
                float2 bb = bB[ntl*32];
                uint32_t b0 = __float_as_uint(bb.x), bb1 = __float_as_uint(bb.y);
                mma_tf32(&d2[ntl*8],     a[0][0], a[0][1], a[0][2], a[0][3], b0, bb1);
                mma_tf32(&d2[ntl*8 + 4], a[1][0], a[1][1], a[1][2], a[1][3], b0, bb1);
            }
        }
    }

    __syncthreads();
    {
        uint32_t* stg = (uint32_t*)dyn;
        #pragma unroll
        for (int mm = 0; mm < 2; mm++) {
            int row = px0 + mm*16 + g;
            #pragma unroll
            for (int ntl = 0; ntl < 4; ntl++) {
                int col = nc0 + ntl*8 + 2*tig;
                float bb0 = s_b2[col], bb1 = s_b2[col+1];
                __nv_bfloat162 h0 = __floats2bfloat162_rn(
                    fmaxf(d2[ntl*8+mm*4+0] + bb0, 0.f),
                    fmaxf(d2[ntl*8+mm*4+1] + bb1, 0.f));
                __nv_bfloat162 h1v = __floats2bfloat162_rn(
                    fmaxf(d2[ntl*8+mm*4+2] + bb0, 0.f),
                    fmaxf(d2[ntl*8+mm*4+3] + bb1, 0.f));
                stg[ row     *32 + (col >> 1)] = *(uint32_t*)&h0;
                stg[(row + 8)*32 + (col >> 1)] = *(uint32_t*)&h1v;
            }
        }
    }
    __syncthreads();
    {
        const uint4* s4 = (const uint4*)dyn;
        uint4* dst = (uint4*)(g_h2h + ((size_t)(b*128 + gr) * 128) * 64);
        #pragma unroll
        for (int i = t; i < 1024; i += 256) dst[i] = s4[i];
    }
}

// ---------------------------------------------------------------------------
// RQS spline (validated R1)
// ---------------------------------------------------------------------------
__device__ __forceinline__ float rqs_eval(const float* p, float xa, float& lad) {
    bool inside = (xa >= -3.f) && (xa <= 3.f);
    float xc = fminf(fmaxf(xa, -3.f), 3.f);

    float mw = p[0], mh = p[8];
    #pragma unroll
    for (int k = 1; k < 8; k++) { mw = fmaxf(mw, p[k]); mh = fmaxf(mh, p[8+k]); }
    float ew[8], eh[8]; float sw = 0.f, sh = 0.f;
    #pragma unroll
    for (int k = 0; k < 8; k++) {
        ew[k] = expf(p[k] - mw);   sw += ew[k];
        eh[k] = expf(p[8+k] - mh); sh += eh[k];
    }
    float rw = (1.f - 0.008f) / sw;
    float rh = (1.f - 0.008f) / sh;

    float sp[7];
    #pragma unroll
    for (int k = 0; k < 7; k++) {
        float u = p[16 + k];
        sp[k] = (u > 15.f) ? u : log1pf(expf(u));
    }

    float cw = -3.f, ch = -3.f, cumw = 0.f, cumh = 0.f, dprev = 1.f;
    float icw = -3.f, iw = 1.f, ich = -3.f, ih = 1.f, id0 = 1.f, id1 = 1.f;
    #pragma unroll
    for (int k = 0; k < 8; k++) {
        cumw += 0.001f + ew[k]*rw;
        cumh += 0.001f + eh[k]*rh;
        float cwn = (k == 7) ? 3.f : fmaf(6.f, cumw, -3.f);
        float chn = (k == 7) ? 3.f : fmaf(6.f, cumh, -3.f);
        float dn  = (k == 7) ? 1.f : (0.001f + sp[k]);
        if (xc >= cw) { icw = cw; iw = cwn - cw; ich = ch; ih = chn - ch; id0 = dprev; id1 = dn; }
        cw = cwn; ch = chn; dprev = dn;
    }

    float riw   = 1.f / iw;
    float delta = ih * riw;
    float theta = (xc - icw) * riw;
    float omt = 1.f - theta;
    float t1  = theta * omt;
    float th2 = theta * theta;
    float num = ih * (delta*th2 + id0*t1);
    float den = delta + (id0 + id1 - 2.f*delta)*t1;
    float y   = ich + num / den;
    float dnum = delta*delta*(id1*th2 + 2.f*delta*t1 + id0*omt*omt);
    float l = logf(dnum) - 2.f*logf(den);

    lad = inside ? l : 0.f;
    return inside ? y : xa;
}

// ---------------------------------------------------------------------------
// conv3 bf16 MMA, resident A + per-tap B stages (K=64/stage, 9 stages).
// 3-slot lead-2 B ring (18432 B/slot). 9 syncs instead of 18.
// CTA = (image row, N-half). smem = 56160 (A) + 55296 (B) = 111,456 B
// -> 2 CTAs/SM. Epilogue sD (74240 B) reuses the A region.
// ---------------------------------------------------------------------------
#define A_BYTES   56160u
#define A_ROWPITCH 18720   // 130 * 144
#define TSLOT 18432u

__device__ __forceinline__ void issue_tap(int tap, int t, int hh, uint32_t baseB){
    uint32_t dst = baseB + (uint32_t)(tap % 3) * TSLOT;
    const uint32_t* wb = g_W3Bh + (size_t)(2*tap) * 4608 + (size_t)hh * 2304;
    #pragma unroll
    for (int it = 0; it < 5; it++) {
        int i = it * 256 + t;
        if (i < 1152) {
            int ih = (i >= 576) ? 1 : 0;
            int ii = i - ih*576;
            cp16(dst + (uint32_t)(ih*9216 + ii*16), wb + (size_t)ih*4608 + ii*4, 16u);
        }
    }
    CP_COMMIT();
}

__global__ void __launch_bounds__(256, 2) k_conv3_mma(const float* __restrict__ x,
                                                      const float* __restrict__ b3,
                                                      float* __restrict__ out) {
    extern __shared__ float dyn[];
    __shared__ float s_b3[276];
    __shared__ float s_red[8];

    int b  = blockIdx.y;
    int bx = blockIdx.x;
    int gr = bx >> 1;
    int hh = bx & 1;
    int t  = threadIdx.x;
    int w = t >> 5, lane = t & 31;
    int g = lane >> 2, tig = lane & 3;
    int px0 = (w & 3) * 32;
    int qq  = w >> 2;

    char* sA = (char*)dyn;
    uint32_t baseB = s2u(dyn) + A_BYTES;

    for (int i = t; i < 276; i += 256) s_b3[i] = b3[i];

    // zero boundary px entries (px 0 and 129) for all 3 rows
    if (t < 48) {
        int r = t >> 4; int rem = t & 15;
        int e = (rem >> 3) ? 129 : 0;
        int q = rem & 7;
        *(uint4*)(sA + r*A_ROWPITCH + e*144 + q*16) = make_uint4(0,0,0,0);
    }
    // resident A: rows gr-1, gr, gr+1 (OOB rows zeroed)
    #pragma unroll
    for (int r = 0; r < 3; r++) {
        int row = gr + r - 1;
        if ((unsigned)row < 128u) {
            const __nv_bfloat16* src = g_h2h + (size_t)(b*128 + row) * 128 * 64;
            #pragma unroll
            for (int it = 0; it < 4; it++) {
                int i = it * 256 + t;
                int px = i >> 3, q = i & 7;
                cp16(s2u(sA) + (uint32_t)(r*A_ROWPITCH + (px+1)*144 + q*16),
                     src + px*64 + q*8, 16u);
            }
        } else {
            #pragma unroll
            for (int it = 0; it < 5; it++) {
                int i = it * 256 + t;
                if (i < 1040) {
                    int e = i >> 3, q = i & 7;
                    *(uint4*)(sA + r*A_ROWPITCH + e*144 + q*16) = make_uint4(0,0,0,0);
                }
            }
        }
    }
    CP_COMMIT();   // A group

    float d[72];
    #pragma unroll
    for (int i = 0; i < 72; i++) d[i] = 0.f;

    issue_tap(0, t, hh, baseB);
    issue_tap(1, t, hh, baseB);

    for (int tp = 0; tp < 9; tp++) {
        if (tp < 8) asm volatile("cp.async.wait_group 1;" ::: "memory");
        else        asm volatile("cp.async.wait_group 0;" ::: "memory");
        __syncthreads();

        if (tp < 7) issue_tap(tp + 2, t, hh, baseB);

        int kh = tp / 3;
        int dw = tp - kh*3 - 1;
        const char* arow = sA + kh*A_ROWPITCH + (px0 + g + 1 + dw)*144;
        const char* sBb = (const char*)dyn + A_BYTES + (size_t)(tp % 3)*TSLOT
                          + (size_t)(qq * 9) * 256 + (size_t)lane * 8;

        #pragma unroll
        for (int ih = 0; ih < 2; ih++) {
            #pragma unroll
            for (int kk = 0; kk < 2; kk++) {
                const char* ar = arow + ih*64 + kk*32 + tig*4;
                uint32_t a00 = *(const uint32_t*)(ar);
                uint32_t a01 = *(const uint32_t*)(ar + 8*144);
                uint32_t a02 = *(const uint32_t*)(ar + 16);
                uint32_t a03 = *(const uint32_t*)(ar + 8*144 + 16);
                uint32_t a10 = *(const uint32_t*)(ar + 16*144);
                uint32_t a11 = *(const uint32_t*)(ar + 24*144);
                uint32_t a12 = *(const uint32_t*)(ar + 16*144 + 16);
                uint32_t a13 = *(const uint32_t*)(ar + 24*144 + 16);
                const char* bp = sBb + (size_t)ih * 9216 + (size_t)kk * 4608;
                #pragma unroll
                for (int nt = 0; nt < 9; nt++) {
                    uint2 bb = *(const uint2*)(bp + (size_t)nt * 256);
                    mma_bf16(&d[nt*8],     a00, a01, a02, a03, bb.x, bb.y);
                    mma_bf16(&d[nt*8 + 4], a10, a11, a12, a13, bb.x, bb.y);
                }
            }
        }
    }

    // epilogue: accumulators -> sD (reuses A region) -> spline
    __syncthreads();
    {
        float* sD = dyn;
        #pragma unroll
        for (int m = 0; m < 2; m++) {
            int row0 = px0 + m*16 + g;
            #pragma unroll
            for (int nt = 0; nt < 9; nt++) {
                int col = qq*72 + nt*8 + 2*tig;
                sD[ row0      * 145 + col    ] = d[nt*8 + m*4 + 0];
                sD[ row0      * 145 + col + 1] = d[nt*8 + m*4 + 1];
                sD[(row0 + 8) * 145 + col    ] = d[nt*8 + m*4 + 2];
                sD[(row0 + 8) * 145 + col + 1] = d[nt*8 + m*4 + 3];
            }
        }
    }
    __syncthreads();

    float ladsum = 0.f;
    {
        const float* sD = dyn;
        int px = t & 127;
        int clbase = (t >> 7) * 3;
        int par = (gr + px) & 1;
        #pragma unroll
        for (int cc = 0; cc < 3; cc++) {
            int cl = clbase + cc;
            int c  = hh*6 + cl;
            float p[23];
            #pragma unroll
            for (int sidx = 0; sidx < 23; sidx++)
                p[sidx] = sD[px*145 + cl*24 + sidx] + s_b3[c*23 + sidx];

            size_t xbase = (((size_t)(b*12 + c)) << 14) + ((size_t)gr << 7) + px;
            float xv = x[xbase];
            float xa = par ? 0.f : xv;
            float xf = par ? xv : 0.f;
            float lad;
            float y = rqs_eval(p, xa, lad);
            out[xbase] = xf + y;
            ladsum += lad;
        }
    }
    #pragma unroll
    for (int o = 16; o > 0; o >>= 1)
        ladsum += __shfl_down_sync(0xffffffffu, ladsum, o);
    if (lane == 0) s_red[w] = ladsum;
    __syncthreads();
    if (t == 0) {
        float v = 0.f;
        #pragma unroll
        for (int i = 0; i < 8; i++) v += s_red[i];
        g_lad[b*256 + bx] = v;
    }
}

// ---------------------------------------------------------------------------
// Final logdet reduction
// ---------------------------------------------------------------------------
__global__ void k_red(const float* __restrict__ logdet_in, float* __restrict__ out) {
    __shared__ float s[8];
    int b = blockIdx.x, t = threadIdx.x;
    float v = g_lad[b*256 + t];
    #pragma unroll
    for (int o = 16; o > 0; o >>= 1) v += __shfl_down_sync(0xffffffffu, v, o);
    if ((t & 31) == 0) s[t >> 5] = v;
    __syncthreads();
    if (t == 0) {
        float r = logdet_in[b];
        #pragma unroll
        for (int i = 0; i < 8; i++) r += s[i];
        out[XOUT_SIZE + b] = r;
    }
}

// ---------------------------------------------------------------------------
extern "C" void kernel_launch(void* const* d_in, const int* in_sizes, int n_in,
                              void* d_out, int out_size) {
    const float* x      = (const float*)d_in[0];
    const float* logdet = (const float*)d_in[1];
    const float* cond   = (const float*)d_in[2];
    const float* W1     = (const float*)d_in[3];
    const float* b1     = (const float*)d_in[4];
    const float* W2     = (const float*)d_in[5];
    const float* b2     = (const float*)d_in[6];
    const float* W3     = (const float*)d_in[7];
    const float* b3     = (const float*)d_in[8];
    float* out = (float*)d_out;

    const int smem12 = 21112 * 4;                 // 84,448 B
    const int smem3  = A_BYTES + 3 * TSLOT;       // 111,456 B
    cudaFuncSetAttribute(k_conv12, cudaFuncAttributeMaxDynamicSharedMemorySize, smem12);
    cudaFuncSetAttribute(k_conv3_mma, cudaFuncAttributeMaxDynamicSharedMemorySize, smem3);

    k_trans<<<376, 256>>>(W1, W2, W3);
    k_conv12<<<dim3(128, 16), 256, smem12>>>(x, cond, b1, b2);
    k_conv3_mma<<<dim3(256, 16), 256, smem3>>>(x, b3, out);
    k_red<<<16, 256>>>(logdet, out);
}

// round 11
// speedup vs baseline: 6.2023x; 1.0165x over previous
#include <cuda_runtime.h>
#include <cuda_bf16.h>
#include <math.h>
#include <stdint.h>

// Problem constants
#define XOUT_SIZE (16*12*128*128)

// Scratch (device globals — no cudaMalloc allowed)
__device__ __align__(16) __nv_bfloat16 g_h2h[16*128*128*64]; // conv2 out [b][h][w][ch] bf16
__device__ __align__(16) float g_W1F[18*8*64];               // conv1 tf32 B-frags
__device__ __align__(16) float g_W2F[8*8*64];                // conv2 tf32 B-frags
__device__ __align__(16) uint32_t g_W3Bh[18*2*2*2*576];      // [st][hh][kk][qq][packed 576w]
__device__ float g_lad[16*256];                              // per-(image,row,half) logdet partials

// ---------------------------------------------------------------------------
// helpers
// ---------------------------------------------------------------------------
__device__ __forceinline__ uint32_t s2u(const void* p){
    uint32_t a;
    asm("{ .reg .u64 t; cvta.to.shared.u64 t, %1; cvt.u32.u64 %0, t; }" : "=r"(a) : "l"(p));
    return a;
}
__device__ __forceinline__ void cp16(uint32_t dst, const void* src, uint32_t sz){
    asm volatile("cp.async.cg.shared.global [%0], [%1], 16, %2;"
                 :: "r"(dst), "l"(src), "r"(sz) : "memory");
}
#define CP_COMMIT() asm volatile("cp.async.commit_group;" ::: "memory")

__device__ __forceinline__ float rna(float v){
    uint32_t o;
    asm("cvt.rna.tf32.f32 %0, %1;" : "=r"(o) : "f"(v));
    return __uint_as_float(o);
}

__device__ __forceinline__ void mma_bf16(float* d, uint32_t a0, uint32_t a1,
                                         uint32_t a2, uint32_t a3,
                                         uint32_t b0, uint32_t b1){
    asm volatile(
        "mma.sync.aligned.m16n8k16.row.col.f32.bf16.bf16.f32 "
        "{%0,%1,%2,%3}, {%4,%5,%6,%7}, {%8,%9}, {%0,%1,%2,%3};"
        : "+f"(d[0]), "+f"(d[1]), "+f"(d[2]), "+f"(d[3])
        : "r"(a0), "r"(a1), "r"(a2), "r"(a3), "r"(b0), "r"(b1));
}

__device__ __forceinline__ void mma_tf32(float* d, uint32_t a0, uint32_t a1,
                                         uint32_t a2, uint32_t a3,
                                         uint32_t b0, uint32_t b1){
    asm volatile(
        "mma.sync.aligned.m16n8k8.row.col.f32.tf32.tf32.f32 "
        "{%0,%1,%2,%3}, {%4,%5,%6,%7}, {%8,%9}, {%0,%1,%2,%3};"
        : "+f"(d[0]), "+f"(d[1]), "+f"(d[2]), "+f"(d[3])
        : "r"(a0), "r"(a1), "r"(a2), "r"(a3), "r"(b0), "r"(b1));
}

__device__ __forceinline__ void ldsm4(uint32_t& r0, uint32_t& r1,
                                      uint32_t& r2, uint32_t& r3, uint32_t addr){
    asm volatile("ldmatrix.sync.aligned.m8n8.x4.shared.b16 {%0,%1,%2,%3}, [%4];"
        : "=r"(r0), "=r"(r1), "=r"(r2), "=r"(r3) : "r"(addr));
}

// ---------------------------------------------------------------------------
// Weight packing. W1F/W2F as R8. W3 packed so (nt,nt+1) register pairs are
// lane-adjacent for LDS.128:
//   g_W3Bh[st][hh][kk][qq][r4] with, for r4<512: pp=r4>>7, lane=(r4&127)>>2,
//   w=r4&3 -> ntl=2pp+(w>>1), reg=w&1 ; for r4>=512: lane=(r4-512)>>1,
//   reg=(r4-512)&1, ntl=8.   nt = qq*9+ntl.
// value = bf16x2 of W3[n=hh*144+nt*8+(lane>>2)][ic=ih*32+kk*16+2(lane&3)+reg*8+{0,1}][tap]
// ---------------------------------------------------------------------------
__global__ void k_trans(const float* __restrict__ W1,
                        const float* __restrict__ W2,
                        const float* __restrict__ W3) {
    int i = blockIdx.x * 256 + threadIdx.x;
    if (i < 9216) {
        int cc = i >> 9;  int r = i & 511;
        int nt = r >> 6;  int l2 = r & 63;
        int lane = l2 >> 1, jj = l2 & 1;
        int tap = cc >> 1, kk = cc & 1;
        int oc = nt*8 + (lane >> 2);
        int ic = kk*8 + (lane & 3) + 4*jj;
        int kh = tap / 3, kw = tap - kh*3;
        g_W1F[i] = rna(W1[oc*144 + ic*9 + kh*3 + kw]);
    }
    int j = i - 9216;
    if (j >= 0 && j < 4096) {
        int kk = j >> 9;  int r = j & 511;
        int nt = r >> 6;  int l2 = r & 63;
        int lane = l2 >> 1, jj = l2 & 1;
        int oc = nt*8 + (lane >> 2);
        int ic = kk*8 + (lane & 3) + 4*jj;
        g_W2F[j] = rna(W2[oc*64 + ic]);
    }
    int m = j - 4096;
    if (m >= 0 && m < 18*4608) {
        int st = m / 4608;  int r1 = m - st*4608;
        int hh = r1 / 2304; int r2 = r1 - hh*2304;
        int kk = r2 / 1152; int r3 = r2 - kk*1152;
        int qq = r3 / 576;  int r4 = r3 - qq*576;
        int lane, reg, ntl;
        if (r4 < 512) {
            int pp = r4 >> 7; int ww = r4 & 127;
            lane = ww >> 2; int wsel = ww & 3;
            ntl = 2*pp + (wsel >> 1); reg = wsel & 1;
        } else {
            int r5 = r4 - 512;
            lane = r5 >> 1; reg = r5 & 1; ntl = 8;
        }
        int nt  = qq*9 + ntl;
        int n   = hh*144 + nt*8 + (lane >> 2);
        int tap = st >> 1, ih = st & 1;
        int ic0 = ih*32 + kk*16 + 2*(lane & 3) + reg*8;
        int c   = n / 24, s = n - c*24;
        float lo = 0.f, hi = 0.f;
        if (s < 23) {
            lo = W3[(c*23 + s)*576 + ic0*9 + tap];
            hi = W3[(c*23 + s)*576 + (ic0+1)*9 + tap];
        }
        __nv_bfloat162 w = __floats2bfloat162_rn(lo, hi);
        g_W3Bh[m] = *(uint32_t*)&w;
    }
}

// ---------------------------------------------------------------------------
// Fused conv1+conv2 tf32 MMA (validated R8)
// ---------------------------------------------------------------------------
__global__ void __launch_bounds__(256, 2) k_conv12(const float* __restrict__ x,
                                                   const float* __restrict__ cond,
                                                   const float* __restrict__ b1,
                                                   const float* __restrict__ b2) {
    extern __shared__ float dyn[];
    __shared__ float s_b1[64], s_b2[64];

    int b  = blockIdx.y;
    int gr = blockIdx.x;
    int t  = threadIdx.x;
    int w = t >> 5, lane = t & 31;
    int g = lane >> 2, tig = lane & 3;
    int px0 = (w & 3) * 32;
    int nc0 = (w >> 2) * 32;

    if (t < 64)       s_b1[t] = b1[t];
    else if (t < 128) s_b2[t-64] = b2[t-64];

    {
        uint32_t b1s = s2u(dyn + 7800);
        for (int i = t; i < 2304; i += 256) cp16(b1s + (uint32_t)(i*16), g_W1F + i*4, 16u);
        uint32_t b2s = s2u(dyn + 17016);
        for (int i = t; i < 1024; i += 256) cp16(b2s + (uint32_t)(i*16), g_W2F + i*4, 16u);
        CP_COMMIT();
    }

    for (int i = t; i < 6240; i += 256) {
        int ch = i / 390; int slot = i - ch*390;
        int r = slot / 130; int pp = slot - r*130;
        int row = gr + r - 1, px = pp - 1;
        float v = 0.f;
        if ((unsigned)row < 128u && (unsigned)px < 128u) {
            if (ch < 12)
                v = ((row + px) & 1) ? x[((b*12 + ch) << 14) + (row << 7) + px] : 0.f;
            else
                v = cond[((b*4 + (ch-12)) << 14) + (row << 7) + px];
        }
        dyn[(r*130 + pp)*20 + ch] = rna(v);
    }
    asm volatile("cp.async.wait_group 0;" ::: "memory");
    __syncthreads();

    float d1[32];
    #pragma unroll
    for (int i = 0; i < 32; i++) d1[i] = 0.f;

    #pragma unroll
    for (int tap = 0; tap < 9; tap++) {
        int kh = tap / 3;
        int dw = tap - kh*3 - 1;
        const float* zr = dyn + kh*2600 + (dw + 1)*20;
        #pragma unroll
        for (int kk = 0; kk < 2; kk++) {
            int cc = tap*2 + kk;
            uint32_t a[2][4];
            #pragma unroll
            for (int mm = 0; mm < 2; mm++) {
                const float* base0 = zr + (px0 + mm*16 + g)*20 + kk*8 + tig;
                a[mm][0] = __float_as_uint(base0[0]);
                a[mm][1] = __float_as_uint(base0[160]);
                a[mm][2] = __float_as_uint(base0[4]);
                a[mm][3] = __float_as_uint(base0[164]);
            }
            const float2* bB = (const float2*)(dyn + 7800) + cc*256 + (nc0 >> 3)*32 + lane;
            #pragma unroll
            for (int ntl = 0; ntl < 4; ntl++) {
                float2 bb = bB[ntl*32];
                uint32_t b0 = __float_as_uint(bb.x), bb1 = __float_as_uint(bb.y);
                mma_tf32(&d1[ntl*8],     a[0][0], a[0][1], a[0][2], a[0][3], b0, bb1);
                mma_tf32(&d1[ntl*8 + 4], a[1][0], a[1][1], a[1][2], a[1][3], b0, bb1);
            }
        }
    }

    __syncthreads();
    {
        float* A2 = dyn + 7800;
        #pragma unroll
        for (int mm = 0; mm < 2; mm++) {
            int row = px0 + mm*16 + g;
            #pragma unroll
            for (int ntl = 0; ntl < 4; ntl++) {
                int col = nc0 + ntl*8 + 2*tig;
                float bb0 = s_b1[col], bb1 = s_b1[col+1];
                A2[ row     *68 + col    ] = rna(fmaxf(d1[ntl*8+mm*4+0] + bb0, 0.f));
                A2[ row     *68 + col + 1] = rna(fmaxf(d1[ntl*8+mm*4+1] + bb1, 0.f));
                A2[(row + 8)*68 + col    ] = rna(fmaxf(d1[ntl*8+mm*4+2] + bb0, 0.f));
                A2[(row + 8)*68 + col + 1] = rna(fmaxf(d1[ntl*8+mm*4+3] + bb1, 0.f));
            }
        }
    }
    __syncthreads();

    float d2[32];
    #pragma unroll
    for (int i = 0; i < 32; i++) d2[i] = 0.f;
    {
        const float* A2 = dyn + 7800;
        #pragma unroll
        for (int kk = 0; kk < 8; kk++) {
            uint32_t a[2][4];
            #pragma unroll
            for (int mm = 0; mm < 2; mm++) {
                const float* base0 = A2 + (px0 + mm*16 + g)*68 + kk*8 + tig;
                a[mm][0] = __float_as_uint(base0[0]);
                a[mm][1] = __float_as_uint(base0[544]);
                a[mm][2] = __float_as_uint(base0[4]);
                a[mm][3] = __float_as_uint(base0[548]);
            }
            const float2* bB = (const float2*)(dyn + 17016) + kk*256 + (nc0 >> 3)*32 + lane;
            #pragma unroll
            for (int ntl = 0; ntl < 4; ntl++) {
                float2 bb = bB[ntl*32];
                uint32_t b0 = __float_as_uint(bb.x), bb1 = __float_as_uint(bb.y);
                mma_tf32(&d2[ntl*8],     a[0][0], a[0][1], a[0][2], a[0][3], b0, bb1);
                mma_tf32(&d2[ntl*8 + 4], a[1][0], a[1][1], a[1][2], a[1][3], b0, bb1);
            }
        }
    }

    __syncthreads();
    {
        uint32_t* stg = (uint32_t*)dyn;
        #pragma unroll
        for (int mm = 0; mm < 2; mm++) {
            int row = px0 + mm*16 + g;
            #pragma unroll
            for (int ntl = 0; ntl < 4; ntl++) {
                int col = nc0 + ntl*8 + 2*tig;
                float bb0 = s_b2[col], bb1 = s_b2[col+1];
                __nv_bfloat162 h0 = __floats2bfloat162_rn(
                    fmaxf(d2[ntl*8+mm*4+0] + bb0, 0.f),
                    fmaxf(d2[ntl*8+mm*4+1] + bb1, 0.f));
                __nv_bfloat162 h1v = __floats2bfloat162_rn(
                    fmaxf(d2[ntl*8+mm*4+2] + bb0, 0.f),
                    fmaxf(d2[ntl*8+mm*4+3] + bb1, 0.f));
                stg[ row     *32 + (col >> 1)] = *(uint32_t*)&h0;
                stg[(row + 8)*32 + (col >> 1)] = *(uint32_t*)&h1v;
            }
        }
    }
    __syncthreads();
    {
        const uint4* s4 = (const uint4*)dyn;
        uint4* dst = (uint4*)(g_h2h + ((size_t)(b*128 + gr) * 128) * 64);
        #pragma unroll
        for (int i = t; i < 1024; i += 256) dst[i] = s4[i];
    }
}

// ---------------------------------------------------------------------------
// RQS spline (validated R1)
// ---------------------------------------------------------------------------
__device__ __forceinline__ float rqs_eval(const float* p, float xa, float& lad) {
    bool inside = (xa >= -3.f) && (xa <= 3.f);
    float xc = fminf(fmaxf(xa, -3.f), 3.f);

    float mw = p[0], mh = p[8];
    #pragma unroll
    for (int k = 1; k < 8; k++) { mw = fmaxf(mw, p[k]); mh = fmaxf(mh, p[8+k]); }
    float ew[8], eh[8]; float sw = 0.f, sh = 0.f;
    #pragma unroll
    for (int k = 0; k < 8; k++) {
        ew[k] = expf(p[k] - mw);   sw += ew[k];
        eh[k] = expf(p[8+k] - mh); sh += eh[k];
    }
    float rw = (1.f - 0.008f) / sw;
    float rh = (1.f - 0.008f) / sh;

    float sp[7];
    #pragma unroll
    for (int k = 0; k < 7; k++) {
        float u = p[16 + k];
        sp[k] = (u > 15.f) ? u : log1pf(expf(u));
    }

    float cw = -3.f, ch = -3.f, cumw = 0.f, cumh = 0.f, dprev = 1.f;
    float icw = -3.f, iw = 1.f, ich = -3.f, ih = 1.f, id0 = 1.f, id1 = 1.f;
    #pragma unroll
    for (int k = 0; k < 8; k++) {
        cumw += 0.001f + ew[k]*rw;
        cumh += 0.001f + eh[k]*rh;
        float cwn = (k == 7) ? 3.f : fmaf(6.f, cumw, -3.f);
        float chn = (k == 7) ? 3.f : fmaf(6.f, cumh, -3.f);
        float dn  = (k == 7) ? 1.f : (0.001f + sp[k]);
        if (xc >= cw) { icw = cw; iw = cwn - cw; ich = ch; ih = chn - ch; id0 = dprev; id1 = dn; }
        cw = cwn; ch = chn; dprev = dn;
    }

    float riw   = 1.f / iw;
    float delta = ih * riw;
    float theta = (xc - icw) * riw;
    float omt = 1.f - theta;
    float t1  = theta * omt;
    float th2 = theta * theta;
    float num = ih * (delta*th2 + id0*t1);
    float den = delta + (id0 + id1 - 2.f*delta)*t1;
    float y   = ich + num / den;
    float dnum = delta*delta*(id1*th2 + 2.f*delta*t1 + id0*omt*omt);
    float l = logf(dnum) - 2.f*logf(den);

    lad = inside ? l : 0.f;
    return inside ? y : xa;
}

// ---------------------------------------------------------------------------
// conv3 bf16 MMA: resident A + per-tap B ring + ldmatrix A-frags +
// LDS.128-paired B-frags. CTA = (image row, N-half).
// smem = 56160 (A) + 3*18432 (B ring) = 111,456 B -> 2 CTAs/SM.
// ---------------------------------------------------------------------------
#define A_BYTES   56160u
#define A_ROWPITCH 18720   // 130 * 144
#define TSLOT 18432u

__device__ __forceinline__ void issue_tap(int tap, int t, int hh, uint32_t baseB){
    uint32_t dst = baseB + (uint32_t)(tap % 3) * TSLOT;
    const uint32_t* wb = g_W3Bh + (size_t)(2*tap) * 4608 + (size_t)hh * 2304;
    #pragma unroll
    for (int it = 0; it < 5; it++) {
        int i = it * 256 + t;
        if (i < 1152) {
            int ih = (i >= 576) ? 1 : 0;
            int ii = i - ih*576;
            cp16(dst + (uint32_t)(ih*9216 + ii*16), wb + (size_t)ih*4608 + ii*4, 16u);
        }
    }
    CP_COMMIT();
}

__global__ void __launch_bounds__(256, 2) k_conv3_mma(const float* __restrict__ x,
                                                      const float* __restrict__ b3,
                                                      float* __restrict__ out) {
    extern __shared__ float dyn[];
    __shared__ float s_b3[276];
    __shared__ float s_red[8];

    int b  = blockIdx.y;
    int bx = blockIdx.x;
    int gr = bx >> 1;
    int hh = bx & 1;
    int t  = threadIdx.x;
    int w = t >> 5, lane = t & 31;
    int g = lane >> 2, tig = lane & 3;
    int px0 = (w & 3) * 32;
    int qq  = w >> 2;

    char* sA = (char*)dyn;
    uint32_t baseB = s2u(dyn) + A_BYTES;

    for (int i = t; i < 276; i += 256) s_b3[i] = b3[i];

    // zero boundary px entries (px 0 and 129) for all 3 rows
    if (t < 48) {
        int r = t >> 4; int rem = t & 15;
        int e = (rem >> 3) ? 129 : 0;
        int q = rem & 7;
        *(uint4*)(sA + r*A_ROWPITCH + e*144 + q*16) = make_uint4(0,0,0,0);
    }
    // resident A: rows gr-1, gr, gr+1 (OOB rows zeroed)
    #pragma unroll
    for (int r = 0; r < 3; r++) {
        int row = gr + r - 1;
        if ((unsigned)row < 128u) {
            const __nv_bfloat16* src = g_h2h + (size_t)(b*128 + row) * 128 * 64;
            #pragma unroll
            for (int it = 0; it < 4; it++) {
                int i = it * 256 + t;
                int px = i >> 3, q = i & 7;
                cp16(s2u(sA) + (uint32_t)(r*A_ROWPITCH + (px+1)*144 + q*16),
                     src + px*64 + q*8, 16u);
            }
        } else {
            #pragma unroll
            for (int it = 0; it < 5; it++) {
                int i = it * 256 + t;
                if (i < 1040) {
                    int e = i >> 3, q = i & 7;
                    *(uint4*)(sA + r*A_ROWPITCH + e*144 + q*16) = make_uint4(0,0,0,0);
                }
            }
        }
    }
    CP_COMMIT();   // A group

    float d[72];
    #pragma unroll
    for (int i = 0; i < 72; i++) d[i] = 0.f;

    issue_tap(0, t, hh, baseB);
    issue_tap(1, t, hh, baseB);

    // per-lane ldmatrix base: row = 1 + px0 + (lane&7) + 8*((lane>>3)&1),
    // col halves selected by bit4 (k 8..15 -> +16 B)
    uint32_t aBase = s2u(sA)
        + (uint32_t)((1 + px0 + (lane & 7) + ((lane >> 3) & 1)*8) * 144
                     + ((lane >> 4) & 1)*16);

    for (int tp = 0; tp < 9; tp++) {
        if (tp < 8) asm volatile("cp.async.wait_group 1;" ::: "memory");
        else        asm volatile("cp.async.wait_group 0;" ::: "memory");
        __syncthreads();

        if (tp < 7) issue_tap(tp + 2, t, hh, baseB);

        int kh = tp / 3;
        int dw = tp - kh*3 - 1;
        uint32_t aTap = aBase + (uint32_t)(kh*A_ROWPITCH + dw*144);
        const char* sBq = (const char*)dyn + A_BYTES + (size_t)(tp % 3)*TSLOT
                          + (size_t)qq * 2304;

        #pragma unroll
        for (int ih = 0; ih < 2; ih++) {
            #pragma unroll
            for (int kk = 0; kk < 2; kk++) {
                uint32_t A0[4], A1[4];
                uint32_t ao = aTap + (uint32_t)(ih*64 + kk*32);
                ldsm4(A0[0], A0[1], A0[2], A0[3], ao);
                ldsm4(A1[0], A1[1], A1[2], A1[3], ao + 2304u);  // +16 rows
                const char* bp = sBq + (size_t)ih*9216 + (size_t)kk*4608;
                #pragma unroll
                for (int pp = 0; pp < 4; pp++) {
                    uint4 bb = *(const uint4*)(bp + pp*512 + lane*16);
                    int n0 = pp*16;           // d offset for nt=2pp
                    mma_bf16(&d[n0],      A0[0], A0[1], A0[2], A0[3], bb.x, bb.y);
                    mma_bf16(&d[n0 + 4],  A1[0], A1[1], A1[2], A1[3], bb.x, bb.y);
                    mma_bf16(&d[n0 + 8],  A0[0], A0[1], A0[2], A0[3], bb.z, bb.w);
                    mma_bf16(&d[n0 + 12], A1[0], A1[1], A1[2], A1[3], bb.z, bb.w);
                }
                uint2 b8 = *(const uint2*)(bp + 2048 + lane*8);
                mma_bf16(&d[64], A0[0], A0[1], A0[2], A0[3], b8.x, b8.y);
                mma_bf16(&d[68], A1[0], A1[1], A1[2], A1[3], b8.x, b8.y);
            }
        }
    }

    // epilogue: accumulators -> sD (reuses A region) -> spline
    __syncthreads();
    {
        float* sD = dyn;
        #pragma unroll
        for (int m = 0; m < 2; m++) {
            int row0 = px0 + m*16 + g;
            #pragma unroll
            for (int nt = 0; nt < 9; nt++) {
                int col = qq*72 + nt*8 + 2*tig;
                sD[ row0      * 145 + col    ] = d[nt*8 + m*4 + 0];
                sD[ row0      * 145 + col + 1] = d[nt*8 + m*4 + 1];
                sD[(row0 + 8) * 145 + col    ] = d[nt*8 + m*4 + 2];
                sD[(row0 + 8) * 145 + col + 1] = d[nt*8 + m*4 + 3];
            }
        }
    }
    __syncthreads();

    float ladsum = 0.f;
    {
        const float* sD = dyn;
        int px = t & 127;
        int clbase = (t >> 7) * 3;
        int par = (gr + px) & 1;
        #pragma unroll
        for (int cc = 0; cc < 3; cc++) {
            int cl = clbase + cc;
            int c  = hh*6 + cl;
            float p[23];
            #pragma unroll
            for (int sidx = 0; sidx < 23; sidx++)
                p[sidx] = sD[px*145 + cl*24 + sidx] + s_b3[c*23 + sidx];

            size_t xbase = (((size_t)(b*12 + c)) << 14) + ((size_t)gr << 7) + px;
            float xv = x[xbase];
            float xa = par ? 0.f : xv;
            float xf = par ? xv : 0.f;
            float lad;
            float y = rqs_eval(p, xa, lad);
            out[xbase] = xf + y;
            ladsum += lad;
        }
    }
    #pragma unroll
    for (int o = 16; o > 0; o >>= 1)
        ladsum += __shfl_down_sync(0xffffffffu, ladsum, o);
    if (lane == 0) s_red[w] = ladsum;
    __syncthreads();
    if (t == 0) {
        float v = 0.f;
        #pragma unroll
        for (int i = 0; i < 8; i++) v += s_red[i];
        g_lad[b*256 + bx] = v;
    }
}

// ---------------------------------------------------------------------------
// Final logdet reduction
// ---------------------------------------------------------------------------
__global__ void k_red(const float* __restrict__ logdet_in, float* __restrict__ out) {
    __shared__ float s[8];
    int b = blockIdx.x, t = threadIdx.x;
    float v = g_lad[b*256 + t];
    #pragma unroll
    for (int o = 16; o > 0; o >>= 1) v += __shfl_down_sync(0xffffffffu, v, o);
    if ((t & 31) == 0) s[t >> 5] = v;
    __syncthreads();
    if (t == 0) {
        float r = logdet_in[b];
        #pragma unroll
        for (int i = 0; i < 8; i++) r += s[i];
        out[XOUT_SIZE + b] = r;
    }
}

// ---------------------------------------------------------------------------
extern "C" void kernel_launch(void* const* d_in, const int* in_sizes, int n_in,
                              void* d_out, int out_size) {
    const float* x      = (const float*)d_in[0];
    const float* logdet = (const float*)d_in[1];
    const float* cond   = (const float*)d_in[2];
    const float* W1     = (const float*)d_in[3];
    const float* b1     = (const float*)d_in[4];
    const float* W2     = (const float*)d_in[5];
    const float* b2     = (const float*)d_in[6];
    const float* W3     = (const float*)d_in[7];
    const float* b3     = (const float*)d_in[8];
    float* out = (float*)d_out;

    const int smem12 = 21112 * 4;                 // 84,448 B
    const int smem3  = A_BYTES + 3 * TSLOT;       // 111,456 B
    cudaFuncSetAttribute(k_conv12, cudaFuncAttributeMaxDynamicSharedMemorySize, smem12);
    cudaFuncSetAttribute(k_conv3_mma, cudaFuncAttributeMaxDynamicSharedMemorySize, smem3);

    k_trans<<<376, 256>>>(W1, W2, W3);
    k_conv12<<<dim3(128, 16), 256, smem12>>>(x, cond, b1, b2);
    k_conv3_mma<<<dim3(256, 16), 256, smem3>>>(x, b3, out);
    k_red<<<16, 256>>>(logdet, out);
}

// round 13
// speedup vs baseline: 6.7593x; 1.0898x over previous
#include <cuda_runtime.h>
#include <cuda_bf16.h>
#include <math.h>
#include <stdint.h>

// Problem constants
#define XOUT_SIZE (16*12*128*128)

// Scratch (device globals — no cudaMalloc allowed)
__device__ __align__(16) __nv_bfloat16 g_h2h[16*128*128*64]; // conv2 out [b][h][w][ch] bf16
__device__ __align__(16) uint32_t g_W1Fh[9*8*64];            // conv1 bf16 B-frags [tap][nt][lane*2+reg]
__device__ __align__(16) uint32_t g_W2Fh[4*8*64];            // conv2 bf16 B-frags [kk][nt][lane*2+reg]
__device__ __align__(16) uint32_t g_W3Bh[18*2*2*2*576];      // [st][hh][kk][qq][packed 576w]
__device__ float g_lad[16*256];                              // per-(image,row,half) logdet partials

// ---------------------------------------------------------------------------
// helpers
// ---------------------------------------------------------------------------
__device__ __forceinline__ uint32_t s2u(const void* p){
    uint32_t a;
    asm("{ .reg .u64 t; cvta.to.shared.u64 t, %1; cvt.u32.u64 %0, t; }" : "=r"(a) : "l"(p));
    return a;
}
__device__ __forceinline__ void cp16(uint32_t dst, const void* src, uint32_t sz){
    asm volatile("cp.async.cg.shared.global [%0], [%1], 16, %2;"
                 :: "r"(dst), "l"(src), "r"(sz) : "memory");
}
#define CP_COMMIT() asm volatile("cp.async.commit_group;" ::: "memory")

__device__ __forceinline__ void mma_bf16(float* d, uint32_t a0, uint32_t a1,
                                         uint32_t a2, uint32_t a3,
                                         uint32_t b0, uint32_t b1){
    asm volatile(
        "mma.sync.aligned.m16n8k16.row.col.f32.bf16.bf16.f32 "
        "{%0,%1,%2,%3}, {%4,%5,%6,%7}, {%8,%9}, {%0,%1,%2,%3};"
        : "+f"(d[0]), "+f"(d[1]), "+f"(d[2]), "+f"(d[3])
        : "r"(a0), "r"(a1), "r"(a2), "r"(a3), "r"(b0), "r"(b1));
}

__device__ __forceinline__ void ldsm4(uint32_t& r0, uint32_t& r1,
                                      uint32_t& r2, uint32_t& r3, uint32_t addr){
    asm volatile("ldmatrix.sync.aligned.m8n8.x4.shared.b16 {%0,%1,%2,%3}, [%4];"
        : "=r"(r0), "=r"(r1), "=r"(r2), "=r"(r3) : "r"(addr));
}

// ---------------------------------------------------------------------------
// Weight packing. W1/W2 -> bf16 m16n8k16 B-fragments:
//   word[tile][lane*2+reg] = bf16x2 of W[oc = nt*8 + (lane>>2)][ic0, ic0+1]
//   with ic0 = (chunk base) + 2*(lane&3) + reg*8.
// W3 packing unchanged (validated R11).
// ---------------------------------------------------------------------------
__global__ void k_trans(const float* __restrict__ W1,
                        const float* __restrict__ W2,
                        const float* __restrict__ W3) {
    int i = blockIdx.x * 256 + threadIdx.x;
    if (i < 4608) {
        int tile = i >> 6; int l2 = i & 63;
        int tap = tile >> 3, nt = tile & 7;
        int lane = l2 >> 1, reg = l2 & 1;
        int oc  = nt*8 + (lane >> 2);
        int ic0 = 2*(lane & 3) + reg*8;
        __nv_bfloat162 w = __floats2bfloat162_rn(
            W1[oc*144 + ic0*9 + tap], W1[oc*144 + (ic0+1)*9 + tap]);
        g_W1Fh[i] = *(uint32_t*)&w;
    }
    int j = i - 4608;
    if (j >= 0 && j < 2048) {
        int tile = j >> 6; int l2 = j & 63;
        int kk = tile >> 3, nt = tile & 7;
        int lane = l2 >> 1, reg = l2 & 1;
        int oc  = nt*8 + (lane >> 2);
        int ic0 = kk*16 + 2*(lane & 3) + reg*8;
        __nv_bfloat162 w = __floats2bfloat162_rn(W2[oc*64 + ic0], W2[oc*64 + ic0 + 1]);
        g_W2Fh[j] = *(uint32_t*)&w;
    }
    int m = j - 2048;
    if (m >= 0 && m < 18*4608) {
        int st = m / 4608;  int r1 = m - st*4608;
        int hh = r1 / 2304; int r2 = r1 - hh*2304;
        int kk = r2 / 1152; int r3 = r2 - kk*1152;
        int qq = r3 / 576;  int r4 = r3 - qq*576;
        int lane, reg, ntl;
        if (r4 < 512) {
            int pp = r4 >> 7; int ww = r4 & 127;
            lane = ww >> 2; int wsel = ww & 3;
            ntl = 2*pp + (wsel >> 1); reg = wsel & 1;
        } else {
            int r5 = r4 - 512;
            lane = r5 >> 1; reg = r5 & 1; ntl = 8;
        }
        int nt  = qq*9 + ntl;
        int n   = hh*144 + nt*8 + (lane >> 2);
        int tap = st >> 1, ih = st & 1;
        int ic0 = ih*32 + kk*16 + 2*(lane & 3) + reg*8;
        int c   = n / 24, s = n - c*24;
        float lo = 0.f, hi = 0.f;
        if (s < 23) {
            lo = W3[(c*23 + s)*576 + ic0*9 + tap];
            hi = W3[(c*23 + s)*576 + (ic0+1)*9 + tap];
        }
        __nv_bfloat162 w = __floats2bfloat162_rn(lo, hi);
        g_W3Bh[m] = *(uint32_t*)&w;
    }
}

// ---------------------------------------------------------------------------
// Fused conv1+conv2, all bf16 m16n8k16.
// CTA = one image row, 256 threads = 8 warps (px-block 32 x N-half 32).
// smem bytes: z [3][130] x 16ch bf16, pitch 48  @0      (18720)
//             B1 frags                          @18720  (18432)
//             B2 frags                          @37152  (8192)   total 45344
//   A2 (128 x 64ch bf16, PITCH 144 = 18432 B) reuses z region after phase 1.
//   bf16 out staging (16384 B) reuses B1 region. 3 CTAs/SM.
// ---------------------------------------------------------------------------
#define Z_PITCH 48
#define A2_PITCH 144
#define B1_OFF 18720u
#define B2_OFF 37152u
#define SM12_BYTES 45344

__global__ void __launch_bounds__(256, 3) k_conv12(const float* __restrict__ x,
                                                   const float* __restrict__ cond,
                                                   const float* __restrict__ b1,
                                                   const float* __restrict__ b2) {
    extern __shared__ float dyn[];
    __shared__ float s_b1[64], s_b2[64];

    int b  = blockIdx.y;
    int gr = blockIdx.x;
    int t  = threadIdx.x;
    int w = t >> 5, lane = t & 31;
    int g = lane >> 2, tig = lane & 3;
    int px0 = (w & 3) * 32;
    int nc0 = (w >> 2) * 32;
    int ntb = (w >> 2) * 4;          // n8-tile base
    int lanRow = (lane & 7) + ((lane >> 3) & 1) * 8;
    int lanCol = ((lane >> 4) & 1) * 16;

    char* sm = (char*)dyn;
    uint32_t smb = s2u(sm);

    if (t < 64)       s_b1[t] = b1[t];
    else if (t < 128) s_b2[t-64] = b2[t-64];

    // weight fragments
    for (int i = t; i < 1152; i += 256) cp16(smb + B1_OFF + (uint32_t)(i*16), g_W1Fh + i*4, 16u);
    for (int i = t; i < 512;  i += 256) cp16(smb + B2_OFF + (uint32_t)(i*16), g_W2Fh + i*4, 16u);
    CP_COMMIT();

    // build z tile bf16: [r][pp] 16 ch, pitch 48 B
    for (int i = t; i < 6240; i += 256) {
        int ch = i / 390; int slot = i - ch*390;
        int r = slot / 130; int pp = slot - r*130;
        int row = gr + r - 1, px = pp - 1;
        float v = 0.f;
        if ((unsigned)row < 128u && (unsigned)px < 128u) {
            if (ch < 12)
                v = ((row + px) & 1) ? x[((b*12 + ch) << 14) + (row << 7) + px] : 0.f;
            else
                v = cond[((b*4 + (ch-12)) << 14) + (row << 7) + px];
        }
        *(__nv_bfloat16*)(sm + slot*Z_PITCH + ch*2) = __float2bfloat16(v);
    }
    asm volatile("cp.async.wait_group 0;" ::: "memory");
    __syncthreads();

    // ---- phase 1: h1 = relu(conv1(z)), K=16 per tap ----
    float d1[32];
    #pragma unroll
    for (int i = 0; i < 32; i++) d1[i] = 0.f;

    #pragma unroll
    for (int tap = 0; tap < 9; tap++) {
        int kh = tap / 3;
        int dw = tap - kh*3 - 1;
        uint32_t A0[4], A1[4];
        uint32_t a0addr = smb + (uint32_t)((kh*130 + 1 + dw + px0 + lanRow)*Z_PITCH + lanCol);
        ldsm4(A0[0], A0[1], A0[2], A0[3], a0addr);
        ldsm4(A1[0], A1[1], A1[2], A1[3], a0addr + 16u*Z_PITCH);
        const uint32_t* bB = (const uint32_t*)(sm + B1_OFF) + (tap*8 + ntb)*64 + lane*2;
        #pragma unroll
        for (int ntl = 0; ntl < 4; ntl++) {
            uint2 bb = *(const uint2*)(bB + ntl*64);
            mma_bf16(&d1[ntl*8],     A0[0], A0[1], A0[2], A0[3], bb.x, bb.y);
            mma_bf16(&d1[ntl*8 + 4], A1[0], A1[1], A1[2], A1[3], bb.x, bb.y);
        }
    }

    // epilogue 1: relu+bias -> bf16 A2 (pitch 144 B, overwrites z)
    __syncthreads();
    #pragma unroll
    for (int mm = 0; mm < 2; mm++) {
        int row = px0 + mm*16 + g;
        #pragma unroll
        for (int ntl = 0; ntl < 4; ntl++) {
            int col = nc0 + ntl*8 + 2*tig;
            float bb0 = s_b1[col], bb1 = s_b1[col+1];
            __nv_bfloat162 v0 = __floats2bfloat162_rn(
                fmaxf(d1[ntl*8+mm*4+0] + bb0, 0.f), fmaxf(d1[ntl*8+mm*4+1] + bb1, 0.f));
            __nv_bfloat162 v1 = __floats2bfloat162_rn(
                fmaxf(d1[ntl*8+mm*4+2] + bb0, 0.f), fmaxf(d1[ntl*8+mm*4+3] + bb1, 0.f));
            *(uint32_t*)(sm +  row     *A2_PITCH + col*2) = *(uint32_t*)&v0;
            *(uint32_t*)(sm + (row + 8)*A2_PITCH + col*2) = *(uint32_t*)&v1;
        }
    }
    __syncthreads();

    // ---- phase 2: h2 = relu(conv2(h1)), K=64 = 4 chunks of 16 ----
    float d2[32];
    #pragma unroll
    for (int i = 0; i < 32; i++) d2[i] = 0.f;

    #pragma unroll
    for (int kk = 0; kk < 4; kk++) {
        uint32_t A0[4], A1[4];
        uint32_t aaddr = smb + (uint32_t)((px0 + lanRow)*A2_PITCH + kk*32 + lanCol);
        ldsm4(A0[0], A0[1], A0[2], A0[3], aaddr);
        ldsm4(A1[0], A1[1], A1[2], A1[3], aaddr + 16u*A2_PITCH);
        const uint32_t* bB = (const uint32_t*)(sm + B2_OFF) + (kk*8 + ntb)*64 + lane*2;
        #pragma unroll
        for (int ntl = 0; ntl < 4; ntl++) {
            uint2 bb = *(const uint2*)(bB + ntl*64);
            mma_bf16(&d2[ntl*8],     A0[0], A0[1], A0[2], A0[3], bb.x, bb.y);
            mma_bf16(&d2[ntl*8 + 4], A1[0], A1[1], A1[2], A1[3], bb.x, bb.y);
        }
    }

    // epilogue 2: relu+bias -> bf16 staging (B1 region) -> gmem
    __syncthreads();
    {
        uint32_t* stg = (uint32_t*)(sm + B1_OFF);
        #pragma unroll
        for (int mm = 0; mm < 2; mm++) {
            int row = px0 + mm*16 + g;
            #pragma unroll
            for (int ntl = 0; ntl < 4; ntl++) {
                int col = nc0 + ntl*8 + 2*tig;
                float bb0 = s_b2[col], bb1 = s_b2[col+1];
                __nv_bfloat162 h0 = __floats2bfloat162_rn(
                    fmaxf(d2[ntl*8+mm*4+0] + bb0, 0.f), fmaxf(d2[ntl*8+mm*4+1] + bb1, 0.f));
                __nv_bfloat162 h1v = __floats2bfloat162_rn(
                    fmaxf(d2[ntl*8+mm*4+2] + bb0, 0.f), fmaxf(d2[ntl*8+mm*4+3] + bb1, 0.f));
                stg[ row     *32 + (col >> 1)] = *(uint32_t*)&h0;
                stg[(row + 8)*32 + (col >> 1)] = *(uint32_t*)&h1v;
            }
        }
    }
    __syncthreads();
    {
        const uint4* s4 = (const uint4*)(sm + B1_OFF);
        uint4* dst = (uint4*)(g_h2h + ((size_t)(b*128 + gr) * 128) * 64);
        #pragma unroll
        for (int i = t; i < 1024; i += 256) dst[i] = s4[i];
    }
}

// ---------------------------------------------------------------------------
// RQS spline (validated R1)
// ---------------------------------------------------------------------------
__device__ __forceinline__ float rqs_eval(const float* p, float xa, float& lad) {
    bool inside = (xa >= -3.f) && (xa <= 3.f);
    float xc = fminf(fmaxf(xa, -3.f), 3.f);

    float mw = p[0], mh = p[8];
    #pragma unroll
    for (int k = 1; k < 8; k++) { mw = fmaxf(mw, p[k]); mh = fmaxf(mh, p[8+k]); }
    float ew[8], eh[8]; float sw = 0.f, sh = 0.f;
    #pragma unroll
    for (int k = 0; k < 8; k++) {
        ew[k] = expf(p[k] - mw);   sw += ew[k];
        eh[k] = expf(p[8+k] - mh); sh += eh[k];
    }
    float rw = (1.f - 0.008f) / sw;
    float rh = (1.f - 0.008f) / sh;

    float sp[7];
    #pragma unroll
    for (int k = 0; k < 7; k++) {
        float u = p[16 + k];
        sp[k] = (u > 15.f) ? u : log1pf(expf(u));
    }

    float cw = -3.f, ch = -3.f, cumw = 0.f, cumh = 0.f, dprev = 1.f;
    float icw = -3.f, iw = 1.f, ich = -3.f, ih = 1.f, id0 = 1.f, id1 = 1.f;
    #pragma unroll
    for (int k = 0; k < 8; k++) {
        cumw += 0.001f + ew[k]*rw;
        cumh += 0.001f + eh[k]*rh;
        float cwn = (k == 7) ? 3.f : fmaf(6.f, cumw, -3.f);
        float chn = (k == 7) ? 3.f : fmaf(6.f, cumh, -3.f);
        float dn  = (k == 7) ? 1.f : (0.001f + sp[k]);
        if (xc >= cw) { icw = cw; iw = cwn - cw; ich = ch; ih = chn - ch; id0 = dprev; id1 = dn; }
        cw = cwn; ch = chn; dprev = dn;
    }

    float riw   = 1.f / iw;
    float delta = ih * riw;
    float theta = (xc - icw) * riw;
    float omt = 1.f - theta;
    float t1  = theta * omt;
    float th2 = theta * theta;
    float num = ih * (delta*th2 + id0*t1);
    float den = delta + (id0 + id1 - 2.f*delta)*t1;
    float y   = ich + num / den;
    float dnum = delta*delta*(id1*th2 + 2.f*delta*t1 + id0*omt*omt);
    float l = logf(dnum) - 2.f*logf(den);

    lad = inside ? l : 0.f;
    return inside ? y : xa;
}

// ---------------------------------------------------------------------------
// conv3 bf16 MMA: resident A + per-tap B ring + ldmatrix A-frags +
// LDS.128-paired B-frags (validated R11). CTA = (image row, N-half).
// smem = 56160 (A) + 3*18432 (B ring) = 111,456 B -> 2 CTAs/SM.
// ---------------------------------------------------------------------------
#define A_BYTES   56160u
#define A_ROWPITCH 18720   // 130 * 144
#define TSLOT 18432u

__device__ __forceinline__ void issue_tap(int tap, int t, int hh, uint32_t baseB){
    uint32_t dst = baseB + (uint32_t)(tap % 3) * TSLOT;
    const uint32_t* wb = g_W3Bh + (size_t)(2*tap) * 4608 + (size_t)hh * 2304;
    #pragma unroll
    for (int it = 0; it < 5; it++) {
        int i = it * 256 + t;
        if (i < 1152) {
            int ih = (i >= 576) ? 1 : 0;
            int ii = i - ih*576;
            cp16(dst + (uint32_t)(ih*9216 + ii*16), wb + (size_t)ih*4608 + ii*4, 16u);
        }
    }
    CP_COMMIT();
}

__global__ void __launch_bounds__(256, 2) k_conv3_mma(const float* __restrict__ x,
                                                      const float* __restrict__ b3,
                                                      float* __restrict__ out) {
    extern __shared__ float dyn[];
    __shared__ float s_b3[276];
    __shared__ float s_red[8];

    int b  = blockIdx.y;
    int bx = blockIdx.x;
    int gr = bx >> 1;
    int hh = bx & 1;
    int t  = threadIdx.x;
    int w = t >> 5, lane = t & 31;
    int g = lane >> 2, tig = lane & 3;
    int px0 = (w & 3) * 32;
    int qq  = w >> 2;

    char* sA = (char*)dyn;
    uint32_t baseB = s2u(dyn) + A_BYTES;

    for (int i = t; i < 276; i += 256) s_b3[i] = b3[i];

    // zero boundary px entries (px 0 and 129) for all 3 rows
    if (t < 48) {
        int r = t >> 4; int rem = t & 15;
        int e = (rem >> 3) ? 129 : 0;
        int q = rem & 7;
        *(uint4*)(sA + r*A_ROWPITCH + e*144 + q*16) = make_uint4(0,0,0,0);
    }
    // resident A: rows gr-1, gr, gr+1 (OOB rows zeroed)
    #pragma unroll
    for (int r = 0; r < 3; r++) {
        int row = gr + r - 1;
        if ((unsigned)row < 128u) {
            const __nv_bfloat16* src = g_h2h + (size_t)(b*128 + row) * 128 * 64;
            #pragma unroll
            for (int it = 0; it < 4; it++) {
                int i = it * 256 + t;
                int px = i >> 3, q = i & 7;
                cp16(s2u(sA) + (uint32_t)(r*A_ROWPITCH + (px+1)*144 + q*16),
                     src + px*64 + q*8, 16u);
            }
        } else {
            #pragma unroll
            for (int it = 0; it < 5; it++) {
                int i = it * 256 + t;
                if (i < 1040) {
                    int e = i >> 3, q = i & 7;
                    *(uint4*)(sA + r*A_ROWPITCH + e*144 + q*16) = make_uint4(0,0,0,0);
                }
            }
        }
    }
    CP_COMMIT();   // A group

    float d[72];
    #pragma unroll
    for (int i = 0; i < 72; i++) d[i] = 0.f;

    issue_tap(0, t, hh, baseB);
    issue_tap(1, t, hh, baseB);

    uint32_t aBase = s2u(sA)
        + (uint32_t)((1 + px0 + (lane & 7) + ((lane >> 3) & 1)*8) * 144
                     + ((lane >> 4) & 1)*16);

    for (int tp = 0; tp < 9; tp++) {
        if (tp < 8) asm volatile("cp.async.wait_group 1;" ::: "memory");
        else        asm volatile("cp.async.wait_group 0;" ::: "memory");
        __syncthreads();

        if (tp < 7) issue_tap(tp + 2, t, hh, baseB);

        int kh = tp / 3;
        int dw = tp - kh*3 - 1;
        uint32_t aTap = aBase + (uint32_t)(kh*A_ROWPITCH + dw*144);
        const char* sBq = (const char*)dyn + A_BYTES + (size_t)(tp % 3)*TSLOT
                          + (size_t)qq * 2304;

        #pragma unroll
        for (int ih = 0; ih < 2; ih++) {
            #pragma unroll
            for (int kk = 0; kk < 2; kk++) {
                uint32_t A0[4], A1[4];
                uint32_t ao = aTap + (uint32_t)(ih*64 + kk*32);
                ldsm4(A0[0], A0[1], A0[2], A0[3], ao);
                ldsm4(A1[0], A1[1], A1[2], A1[3], ao + 2304u);  // +16 rows
                const char* bp = sBq + (size_t)ih*9216 + (size_t)kk*4608;
                #pragma unroll
                for (int pp = 0; pp < 4; pp++) {
                    uint4 bb = *(const uint4*)(bp + pp*512 + lane*16);
                    int n0 = pp*16;
                    mma_bf16(&d[n0],      A0[0], A0[1], A0[2], A0[3], bb.x, bb.y);
                    mma_bf16(&d[n0 + 4],  A1[0], A1[1], A1[2], A1[3], bb.x, bb.y);
                    mma_bf16(&d[n0 + 8],  A0[0], A0[1], A0[2], A0[3], bb.z, bb.w);
                    mma_bf16(&d[n0 + 12], A1[0], A1[1], A1[2], A1[3], bb.z, bb.w);
                }
                uint2 b8 = *(const uint2*)(bp + 2048 + lane*8);
                mma_bf16(&d[64], A0[0], A0[1], A0[2], A0[3], b8.x, b8.y);
                mma_bf16(&d[68], A1[0], A1[1], A1[2], A1[3], b8.x, b8.y);
            }
        }
    }

    // epilogue: accumulators -> sD (reuses A region) -> spline
    __syncthreads();
    {
        float* sD = dyn;
        #pragma unroll
        for (int m = 0; m < 2; m++) {
            int row0 = px0 + m*16 + g;
            #pragma unroll
            for (int nt = 0; nt < 9; nt++) {
                int col = qq*72 + nt*8 + 2*tig;
                sD[ row0      * 145 + col    ] = d[nt*8 + m*4 + 0];
                sD[ row0      * 145 + col + 1] = d[nt*8 + m*4 + 1];
                sD[(row0 + 8) * 145 + col    ] = d[nt*8 + m*4 + 2];
                sD[(row0 + 8) * 145 + col + 1] = d[nt*8 + m*4 + 3];
            }
        }
    }
    __syncthreads();

    float ladsum = 0.f;
    {
        const float* sD = dyn;
        int px = t & 127;
        int clbase = (t >> 7) * 3;
        int par = (gr + px) & 1;
        #pragma unroll
        for (int cc = 0; cc < 3; cc++) {
            int cl = clbase + cc;
            int c  = hh*6 + cl;
            float p[23];
            #pragma unroll
            for (int sidx = 0; sidx < 23; sidx++)
                p[sidx] = sD[px*145 + cl*24 + sidx] + s_b3[c*23 + sidx];

            size_t xbase = (((size_t)(b*12 + c)) << 14) + ((size_t)gr << 7) + px;
            float xv = x[xbase];
            float xa = par ? 0.f : xv;
            float xf = par ? xv : 0.f;
            float lad;
            float y = rqs_eval(p, xa, lad);
            out[xbase] = xf + y;
            ladsum += lad;
        }
    }
    #pragma unroll
    for (int o = 16; o > 0; o >>= 1)
        ladsum += __shfl_down_sync(0xffffffffu, ladsum, o);
    if (lane == 0) s_red[w] = ladsum;
    __syncthreads();
    if (t == 0) {
        float v = 0.f;
        #pragma unroll
        for (int i = 0; i < 8; i++) v += s_red[i];
        g_lad[b*256 + bx] = v;
    }
}

// ---------------------------------------------------------------------------
// Final logdet reduction
// ---------------------------------------------------------------------------
__global__ void k_red(const float* __restrict__ logdet_in, float* __restrict__ out) {
    __shared__ float s[8];
    int b = blockIdx.x, t = threadIdx.x;
    float v = g_lad[b*256 + t];
    #pragma unroll
    for (int o = 16; o > 0; o >>= 1) v += __shfl_down_sync(0xffffffffu, v, o);
    if ((t & 31) == 0) s[t >> 5] = v;
    __syncthreads();
    if (t == 0) {
        float r = logdet_in[b];
        #pragma unroll
        for (int i = 0; i < 8; i++) r += s[i];
        out[XOUT_SIZE + b] = r;
    }
}

// ---------------------------------------------------------------------------
extern "C" void kernel_launch(void* const* d_in, const int* in_sizes, int n_in,
                              void* d_out, int out_size) {
    const float* x      = (const float*)d_in[0];
    const float* logdet = (const float*)d_in[1];
    const float* cond   = (const float*)d_in[2];
    const float* W1     = (const float*)d_in[3];
    const float* b1     = (const float*)d_in[4];
    const float* W2     = (const float*)d_in[5];
    const float* b2     = (const float*)d_in[6];
    const float* W3     = (const float*)d_in[7];
    const float* b3     = (const float*)d_in[8];
    float* out = (float*)d_out;

    const int smem3 = A_BYTES + 3 * TSLOT;        // 111,456 B
    cudaFuncSetAttribute(k_conv12, cudaFuncAttributeMaxDynamicSharedMemorySize, SM12_BYTES);
    cudaFuncSetAttribute(k_conv3_mma, cudaFuncAttributeMaxDynamicSharedMemorySize, smem3);

    k_trans<<<350, 256>>>(W1, W2, W3);
    k_conv12<<<dim3(128, 16), 256, SM12_BYTES>>>(x, cond, b1, b2);
    k_conv3_mma<<<dim3(256, 16), 256, smem3>>>(x, b3, out);
    k_red<<<16, 256>>>(logdet, out);
}

// round 14
// speedup vs baseline: 7.1006x; 1.0505x over previous
#include <cuda_runtime.h>
#include <cuda_bf16.h>
#include <math.h>
#include <stdint.h>

// Problem constants
#define XOUT_SIZE (16*12*128*128)

// Scratch (device globals — no cudaMalloc allowed)
__device__ __align__(16) __nv_bfloat16 g_h2h[16*128*128*64]; // conv2 out [b][h][w][ch] bf16
__device__ __align__(16) uint32_t g_W1Fh[9*8*64];            // conv1 bf16 B-frags [tap][nt][lane*2+reg]
__device__ __align__(16) uint32_t g_W2Fh[4*8*64];            // conv2 bf16 B-frags [kk][nt][lane*2+reg]
__device__ __align__(16) uint32_t g_W3Bh[18*2*2*2*576];      // [st][hh][kk][qq][packed 576w]
__device__ float g_lad[16*256];                              // per-(image,row,half) logdet partials
__device__ unsigned g_tick[16];                              // per-image completion tickets

// ---------------------------------------------------------------------------
// helpers
// ---------------------------------------------------------------------------
__device__ __forceinline__ uint32_t s2u(const void* p){
    uint32_t a;
    asm("{ .reg .u64 t; cvta.to.shared.u64 t, %1; cvt.u32.u64 %0, t; }" : "=r"(a) : "l"(p));
    return a;
}
__device__ __forceinline__ void cp16(uint32_t dst, const void* src, uint32_t sz){
    asm volatile("cp.async.cg.shared.global [%0], [%1], 16, %2;"
                 :: "r"(dst), "l"(src), "r"(sz) : "memory");
}
#define CP_COMMIT() asm volatile("cp.async.commit_group;" ::: "memory")

__device__ __forceinline__ void mma_bf16(float* d, uint32_t a0, uint32_t a1,
                                         uint32_t a2, uint32_t a3,
                                         uint32_t b0, uint32_t b1){
    asm volatile(
        "mma.sync.aligned.m16n8k16.row.col.f32.bf16.bf16.f32 "
        "{%0,%1,%2,%3}, {%4,%5,%6,%7}, {%8,%9}, {%0,%1,%2,%3};"
        : "+f"(d[0]), "+f"(d[1]), "+f"(d[2]), "+f"(d[3])
        : "r"(a0), "r"(a1), "r"(a2), "r"(a3), "r"(b0), "r"(b1));
}

__device__ __forceinline__ void ldsm4(uint32_t& r0, uint32_t& r1,
                                      uint32_t& r2, uint32_t& r3, uint32_t addr){
    asm volatile("ldmatrix.sync.aligned.m8n8.x4.shared.b16 {%0,%1,%2,%3}, [%4];"
        : "=r"(r0), "=r"(r1), "=r"(r2), "=r"(r3) : "r"(addr));
}

// ---------------------------------------------------------------------------
// k_trans: W1/W2 bf16 fragment packing + per-image ticket reset.
// (W3 packing is distributed across k_conv12's threads.)
// ---------------------------------------------------------------------------
__global__ void k_trans(const float* __restrict__ W1,
                        const float* __restrict__ W2) {
    int i = blockIdx.x * 256 + threadIdx.x;
    if (i < 16) g_tick[i] = 0u;
    if (i < 4608) {
        int tile = i >> 6; int l2 = i & 63;
        int tap = tile >> 3, nt = tile & 7;
        int lane = l2 >> 1, reg = l2 & 1;
        int oc  = nt*8 + (lane >> 2);
        int ic0 = 2*(lane & 3) + reg*8;
        __nv_bfloat162 w = __floats2bfloat162_rn(
            W1[oc*144 + ic0*9 + tap], W1[oc*144 + (ic0+1)*9 + tap]);
        g_W1Fh[i] = *(uint32_t*)&w;
    }
    int j = i - 4608;
    if (j >= 0 && j < 2048) {
        int tile = j >> 6; int l2 = j & 63;
        int kk = tile >> 3, nt = tile & 7;
        int lane = l2 >> 1, reg = l2 & 1;
        int oc  = nt*8 + (lane >> 2);
        int ic0 = kk*16 + 2*(lane & 3) + reg*8;
        __nv_bfloat162 w = __floats2bfloat162_rn(W2[oc*64 + ic0], W2[oc*64 + ic0 + 1]);
        g_W2Fh[j] = *(uint32_t*)&w;
    }
}

// ---------------------------------------------------------------------------
// Fused conv1+conv2, all bf16 m16n8k16 (validated R13) + distributed W3 pack.
// CTA = one image row, 256 threads = 8 warps (px-block 32 x N-half 32).
// smem bytes: z [3][130] x 16ch bf16, pitch 48  @0      (18720)
//             B1 frags                          @18720  (18432)
//             B2 frags                          @37152  (8192)   total 45344
//   A2 (128 x 64ch bf16, pitch 144) reuses z region after phase 1.
//   bf16 out staging reuses B1 region. 3 CTAs/SM.
// ---------------------------------------------------------------------------
#define Z_PITCH 48
#define A2_PITCH 144
#define B1_OFF 18720u
#define B2_OFF 37152u
#define SM12_BYTES 45344

__global__ void __launch_bounds__(256, 3) k_conv12(const float* __restrict__ x,
                                                   const float* __restrict__ cond,
                                                   const float* __restrict__ b1,
                                                   const float* __restrict__ b2,
                                                   const float* __restrict__ W3) {
    extern __shared__ float dyn[];
    __shared__ float s_b1[64], s_b2[64];

    int b  = blockIdx.y;
    int gr = blockIdx.x;
    int t  = threadIdx.x;
    int w = t >> 5, lane = t & 31;
    int g = lane >> 2, tig = lane & 3;
    int px0 = (w & 3) * 32;
    int nc0 = (w >> 2) * 32;
    int ntb = (w >> 2) * 4;          // n8-tile base
    int lanRow = (lane & 7) + ((lane >> 3) & 1) * 8;
    int lanCol = ((lane >> 4) & 1) * 16;

    char* sm = (char*)dyn;
    uint32_t smb = s2u(sm);

    // ---- distributed W3 fragment packing (read by the LATER conv3 kernel) ----
    {
        int m = (b*128 + gr)*256 + t;
        if (m < 18*4608) {
            int st = m / 4608;  int r1 = m - st*4608;
            int hh = r1 / 2304; int r2 = r1 - hh*2304;
            int kk = r2 / 1152; int r3 = r2 - kk*1152;
            int qq = r3 / 576;  int r4 = r3 - qq*576;
            int lne, reg, ntl;
            if (r4 < 512) {
                int pp = r4 >> 7; int ww = r4 & 127;
                lne = ww >> 2; int wsel = ww & 3;
                ntl = 2*pp + (wsel >> 1); reg = wsel & 1;
            } else {
                int r5 = r4 - 512;
                lne = r5 >> 1; reg = r5 & 1; ntl = 8;
            }
            int nt  = qq*9 + ntl;
            int n   = hh*144 + nt*8 + (lne >> 2);
            int tap = st >> 1, ih = st & 1;
            int ic0 = ih*32 + kk*16 + 2*(lne & 3) + reg*8;
            int c   = n / 24, s = n - c*24;
            float lo = 0.f, hi = 0.f;
            if (s < 23) {
                lo = W3[(c*23 + s)*576 + ic0*9 + tap];
                hi = W3[(c*23 + s)*576 + (ic0+1)*9 + tap];
            }
            __nv_bfloat162 wv = __floats2bfloat162_rn(lo, hi);
            g_W3Bh[m] = *(uint32_t*)&wv;
        }
    }

    if (t < 64)       s_b1[t] = b1[t];
    else if (t < 128) s_b2[t-64] = b2[t-64];

    // weight fragments
    for (int i = t; i < 1152; i += 256) cp16(smb + B1_OFF + (uint32_t)(i*16), g_W1Fh + i*4, 16u);
    for (int i = t; i < 512;  i += 256) cp16(smb + B2_OFF + (uint32_t)(i*16), g_W2Fh + i*4, 16u);
    CP_COMMIT();

    // build z tile bf16: [r][pp] 16 ch, pitch 48 B
    for (int i = t; i < 6240; i += 256) {
        int ch = i / 390; int slot = i - ch*390;
        int r = slot / 130; int pp = slot - r*130;
        int row = gr + r - 1, px = pp - 1;
        float v = 0.f;
        if ((unsigned)row < 128u && (unsigned)px < 128u) {
            if (ch < 12)
                v = ((row + px) & 1) ? x[((b*12 + ch) << 14) + (row << 7) + px] : 0.f;
            else
                v = cond[((b*4 + (ch-12)) << 14) + (row << 7) + px];
        }
        *(__nv_bfloat16*)(sm + slot*Z_PITCH + ch*2) = __float2bfloat16(v);
    }
    asm volatile("cp.async.wait_group 0;" ::: "memory");
    __syncthreads();

    // ---- phase 1: h1 = relu(conv1(z)), K=16 per tap ----
    float d1[32];
    #pragma unroll
    for (int i = 0; i < 32; i++) d1[i] = 0.f;

    #pragma unroll
    for (int tap = 0; tap < 9; tap++) {
        int kh = tap / 3;
        int dw = tap - kh*3 - 1;
        uint32_t A0[4], A1[4];
        uint32_t a0addr = smb + (uint32_t)((kh*130 + 1 + dw + px0 + lanRow)*Z_PITCH + lanCol);
        ldsm4(A0[0], A0[1], A0[2], A0[3], a0addr);
        ldsm4(A1[0], A1[1], A1[2], A1[3], a0addr + 16u*Z_PITCH);
        const uint32_t* bB = (const uint32_t*)(sm + B1_OFF) + (tap*8 + ntb)*64 + lane*2;
        #pragma unroll
        for (int ntl = 0; ntl < 4; ntl++) {
            uint2 bb = *(const uint2*)(bB + ntl*64);
            mma_bf16(&d1[ntl*8],     A0[0], A0[1], A0[2], A0[3], bb.x, bb.y);
            mma_bf16(&d1[ntl*8 + 4], A1[0], A1[1], A1[2], A1[3], bb.x, bb.y);
        }
    }

    // epilogue 1: relu+bias -> bf16 A2 (pitch 144 B, overwrites z)
    __syncthreads();
    #pragma unroll
    for (int mm = 0; mm < 2; mm++) {
        int row = px0 + mm*16 + g;
        #pragma unroll
        for (int ntl = 0; ntl < 4; ntl++) {
            int col = nc0 + ntl*8 + 2*tig;
            float bb0 = s_b1[col], bb1 = s_b1[col+1];
            __nv_bfloat162 v0 = __floats2bfloat162_rn(
                fmaxf(d1[ntl*8+mm*4+0] + bb0, 0.f), fmaxf(d1[ntl*8+mm*4+1] + bb1, 0.f));
            __nv_bfloat162 v1 = __floats2bfloat162_rn(
                fmaxf(d1[ntl*8+mm*4+2] + bb0, 0.f), fmaxf(d1[ntl*8+mm*4+3] + bb1, 0.f));
            *(uint32_t*)(sm +  row     *A2_PITCH + col*2) = *(uint32_t*)&v0;
            *(uint32_t*)(sm + (row + 8)*A2_PITCH + col*2) = *(uint32_t*)&v1;
        }
    }
    __syncthreads();

    // ---- phase 2: h2 = relu(conv2(h1)), K=64 = 4 chunks of 16 ----
    float d2[32];
    #pragma unroll
    for (int i = 0; i < 32; i++) d2[i] = 0.f;

    #pragma unroll
    for (int kk = 0; kk < 4; kk++) {
        uint32_t A0[4], A1[4];
        uint32_t aaddr = smb + (uint32_t)((px0 + lanRow)*A2_PITCH + kk*32 + lanCol);
        ldsm4(A0[0], A0[1], A0[2], A0[3], aaddr);
        ldsm4(A1[0], A1[1], A1[2], A1[3], aaddr + 16u*A2_PITCH);
        const uint32_t* bB = (const uint32_t*)(sm + B2_OFF) + (kk*8 + ntb)*64 + lane*2;
        #pragma unroll
        for (int ntl = 0; ntl < 4; ntl++) {
            uint2 bb = *(const uint2*)(bB + ntl*64);
            mma_bf16(&d2[ntl*8],     A0[0], A0[1], A0[2], A0[3], bb.x, bb.y);
            mma_bf16(&d2[ntl*8 + 4], A1[0], A1[1], A1[2], A1[3], bb.x, bb.y);
        }
    }

    // epilogue 2: relu+bias -> bf16 staging (B1 region) -> gmem
    __syncthreads();
    {
        uint32_t* stg = (uint32_t*)(sm + B1_OFF);
        #pragma unroll
        for (int mm = 0; mm < 2; mm++) {
            int row = px0 + mm*16 + g;
            #pragma unroll
            for (int ntl = 0; ntl < 4; ntl++) {
                int col = nc0 + ntl*8 + 2*tig;
                float bb0 = s_b2[col], bb1 = s_b2[col+1];
                __nv_bfloat162 h0 = __floats2bfloat162_rn(
                    fmaxf(d2[ntl*8+mm*4+0] + bb0, 0.f), fmaxf(d2[ntl*8+mm*4+1] + bb1, 0.f));
                __nv_bfloat162 h1v = __floats2bfloat162_rn(
                    fmaxf(d2[ntl*8+mm*4+2] + bb0, 0.f), fmaxf(d2[ntl*8+mm*4+3] + bb1, 0.f));
                stg[ row     *32 + (col >> 1)] = *(uint32_t*)&h0;
                stg[(row + 8)*32 + (col >> 1)] = *(uint32_t*)&h1v;
            }
        }
    }
    __syncthreads();
    {
        const uint4* s4 = (const uint4*)(sm + B1_OFF);
        uint4* dst = (uint4*)(g_h2h + ((size_t)(b*128 + gr) * 128) * 64);
        #pragma unroll
        for (int i = t; i < 1024; i += 256) dst[i] = s4[i];
    }
}

// ---------------------------------------------------------------------------
// RQS spline (validated R1)
// ---------------------------------------------------------------------------
__device__ __forceinline__ float rqs_eval(const float* p, float xa, float& lad) {
    bool inside = (xa >= -3.f) && (xa <= 3.f);
    float xc = fminf(fmaxf(xa, -3.f), 3.f);

    float mw = p[0], mh = p[8];
    #pragma unroll
    for (int k = 1; k < 8; k++) { mw = fmaxf(mw, p[k]); mh = fmaxf(mh, p[8+k]); }
    float ew[8], eh[8]; float sw = 0.f, sh = 0.f;
    #pragma unroll
    for (int k = 0; k < 8; k++) {
        ew[k] = expf(p[k] - mw);   sw += ew[k];
        eh[k] = expf(p[8+k] - mh); sh += eh[k];
    }
    float rw = (1.f - 0.008f) / sw;
    float rh = (1.f - 0.008f) / sh;

    float sp[7];
    #pragma unroll
    for (int k = 0; k < 7; k++) {
        float u = p[16 + k];
        sp[k] = (u > 15.f) ? u : log1pf(expf(u));
    }

    float cw = -3.f, ch = -3.f, cumw = 0.f, cumh = 0.f, dprev = 1.f;
    float icw = -3.f, iw = 1.f, ich = -3.f, ih = 1.f, id0 = 1.f, id1 = 1.f;
    #pragma unroll
    for (int k = 0; k < 8; k++) {
        cumw += 0.001f + ew[k]*rw;
        cumh += 0.001f + eh[k]*rh;
        float cwn = (k == 7) ? 3.f : fmaf(6.f, cumw, -3.f);
        float chn = (k == 7) ? 3.f : fmaf(6.f, cumh, -3.f);
        float dn  = (k == 7) ? 1.f : (0.001f + sp[k]);
        if (xc >= cw) { icw = cw; iw = cwn - cw; ich = ch; ih = chn - ch; id0 = dprev; id1 = dn; }
        cw = cwn; ch = chn; dprev = dn;
    }

    float riw   = 1.f / iw;
    float delta = ih * riw;
    float theta = (xc - icw) * riw;
    float omt = 1.f - theta;
    float t1  = theta * omt;
    float th2 = theta * theta;
    float num = ih * (delta*th2 + id0*t1);
    float den = delta + (id0 + id1 - 2.f*delta)*t1;
    float y   = ich + num / den;
    float dnum = delta*delta*(id1*th2 + 2.f*delta*t1 + id0*omt*omt);
    float l = logf(dnum) - 2.f*logf(den);

    lad = inside ? l : 0.f;
    return inside ? y : xa;
}

// ---------------------------------------------------------------------------
// conv3 bf16 MMA: resident A + per-tap B ring + ldmatrix A-frags +
// LDS.128-paired B-frags (validated R11) + fused final logdet reduction.
// CTA = (image row, N-half). smem = 56160 (A) + 3*18432 (B) = 111,456 B.
// ---------------------------------------------------------------------------
#define A_BYTES   56160u
#define A_ROWPITCH 18720   // 130 * 144
#define TSLOT 18432u

__device__ __forceinline__ void issue_tap(int tap, int t, int hh, uint32_t baseB){
    uint32_t dst = baseB + (uint32_t)(tap % 3) * TSLOT;
    const uint32_t* wb = g_W3Bh + (size_t)(2*tap) * 4608 + (size_t)hh * 2304;
    #pragma unroll
    for (int it = 0; it < 5; it++) {
        int i = it * 256 + t;
        if (i < 1152) {
            int ih = (i >= 576) ? 1 : 0;
            int ii = i - ih*576;
            cp16(dst + (uint32_t)(ih*9216 + ii*16), wb + (size_t)ih*4608 + ii*4, 16u);
        }
    }
    CP_COMMIT();
}

__global__ void __launch_bounds__(256, 2) k_conv3_mma(const float* __restrict__ x,
                                                      const float* __restrict__ logdet_in,
                                                      const float* __restrict__ b3,
                                                      float* __restrict__ out) {
    extern __shared__ float dyn[];
    __shared__ float s_b3[276];
    __shared__ float s_red[8];
    __shared__ unsigned s_last;

    int b  = blockIdx.y;
    int bx = blockIdx.x;
    int gr = bx >> 1;
    int hh = bx & 1;
    int t  = threadIdx.x;
    int w = t >> 5, lane = t & 31;
    int g = lane >> 2, tig = lane & 3;
    int px0 = (w & 3) * 32;
    int qq  = w >> 2;

    char* sA = (char*)dyn;
    uint32_t baseB = s2u(dyn) + A_BYTES;

    for (int i = t; i < 276; i += 256) s_b3[i] = b3[i];

    // zero boundary px entries (px 0 and 129) for all 3 rows
    if (t < 48) {
        int r = t >> 4; int rem = t & 15;
        int e = (rem >> 3) ? 129 : 0;
        int q = rem & 7;
        *(uint4*)(sA + r*A_ROWPITCH + e*144 + q*16) = make_uint4(0,0,0,0);
    }
    // resident A: rows gr-1, gr, gr+1 (OOB rows zeroed)
    #pragma unroll
    for (int r = 0; r < 3; r++) {
        int row = gr + r - 1;
        if ((unsigned)row < 128u) {
            const __nv_bfloat16* src = g_h2h + (size_t)(b*128 + row) * 128 * 64;
            #pragma unroll
            for (int it = 0; it < 4; it++) {
                int i = it * 256 + t;
                int px = i >> 3, q = i & 7;
                cp16(s2u(sA) + (uint32_t)(r*A_ROWPITCH + (px+1)*144 + q*16),
                     src + px*64 + q*8, 16u);
            }
        } else {
            #pragma unroll
            for (int it = 0; it < 5; it++) {
                int i = it * 256 + t;
                if (i < 1040) {
                    int e = i >> 3, q = i & 7;
                    *(uint4*)(sA + r*A_ROWPITCH + e*144 + q*16) = make_uint4(0,0,0,0);
                }
            }
        }
    }
    CP_COMMIT();   // A group

    float d[72];
    #pragma unroll
    for (int i = 0; i < 72; i++) d[i] = 0.f;

    issue_tap(0, t, hh, baseB);
    issue_tap(1, t, hh, baseB);

    uint32_t aBase = s2u(sA)
        + (uint32_t)((1 + px0 + (lane & 7) + ((lane >> 3) & 1)*8) * 144
                     + ((lane >> 4) & 1)*16);

    for (int tp = 0; tp < 9; tp++) {
        if (tp < 8) asm volatile("cp.async.wait_group 1;" ::: "memory");
        else        asm volatile("cp.async.wait_group 0;" ::: "memory");
        __syncthreads();

        if (tp < 7) issue_tap(tp + 2, t, hh, baseB);

        int kh = tp / 3;
        int dw = tp - kh*3 - 1;
        uint32_t aTap = aBase + (uint32_t)(kh*A_ROWPITCH + dw*144);
        const char* sBq = (const char*)dyn + A_BYTES + (size_t)(tp % 3)*TSLOT
                          + (size_t)qq * 2304;

        #pragma unroll
        for (int ih = 0; ih < 2; ih++) {
            #pragma unroll
            for (int kk = 0; kk < 2; kk++) {
                uint32_t A0[4], A1[4];
                uint32_t ao = aTap + (uint32_t)(ih*64 + kk*32);
                ldsm4(A0[0], A0[1], A0[2], A0[3], ao);
                ldsm4(A1[0], A1[1], A1[2], A1[3], ao + 2304u);  // +16 rows
                const char* bp = sBq + (size_t)ih*9216 + (size_t)kk*4608;
                #pragma unroll
                for (int pp = 0; pp < 4; pp++) {
                    uint4 bb = *(const uint4*)(bp + pp*512 + lane*16);
                    int n0 = pp*16;
                    mma_bf16(&d[n0],      A0[0], A0[1], A0[2], A0[3], bb.x, bb.y);
                    mma_bf16(&d[n0 + 4],  A1[0], A1[1], A1[2], A1[3], bb.x, bb.y);
                    mma_bf16(&d[n0 + 8],  A0[0], A0[1], A0[2], A0[3], bb.z, bb.w);
                    mma_bf16(&d[n0 + 12], A1[0], A1[1], A1[2], A1[3], bb.z, bb.w);
                }
                uint2 b8 = *(const uint2*)(bp + 2048 + lane*8);
                mma_bf16(&d[64], A0[0], A0[1], A0[2], A0[3], b8.x, b8.y);
                mma_bf16(&d[68], A1[0], A1[1], A1[2], A1[3], b8.x, b8.y);
            }
        }
    }

    // epilogue: accumulators -> sD (reuses A region) -> spline
    __syncthreads();
    {
        float* sD = dyn;
        #pragma unroll
        for (int m = 0; m < 2; m++) {
            int row0 = px0 + m*16 + g;
            #pragma unroll
            for (int nt = 0; nt < 9; nt++) {
                int col = qq*72 + nt*8 + 2*tig;
                sD[ row0      * 145 + col    ] = d[nt*8 + m*4 + 0];
                sD[ row0      * 145 + col + 1] = d[nt*8 + m*4 + 1];
                sD[(row0 + 8) * 145 + col    ] = d[nt*8 + m*4 + 2];
                sD[(row0 + 8) * 145 + col + 1] = d[nt*8 + m*4 + 3];
            }
        }
    }
    __syncthreads();

    float ladsum = 0.f;
    {
        const float* sD = dyn;
        int px = t & 127;
        int clbase = (t >> 7) * 3;
        int par = (gr + px) & 1;
        #pragma unroll
        for (int cc = 0; cc < 3; cc++) {
            int cl = clbase + cc;
            int c  = hh*6 + cl;
            float p[23];
            #pragma unroll
            for (int sidx = 0; sidx < 23; sidx++)
                p[sidx] = sD[px*145 + cl*24 + sidx] + s_b3[c*23 + sidx];

            size_t xbase = (((size_t)(b*12 + c)) << 14) + ((size_t)gr << 7) + px;
            float xv = x[xbase];
            float xa = par ? 0.f : xv;
            float xf = par ? xv : 0.f;
            float lad;
            float y = rqs_eval(p, xa, lad);
            out[xbase] = xf + y;
            ladsum += lad;
        }
    }
    #pragma unroll
    for (int o = 16; o > 0; o >>= 1)
        ladsum += __shfl_down_sync(0xffffffffu, ladsum, o);
    if (lane == 0) s_red[w] = ladsum;
    __syncthreads();
    if (t == 0) {
        float v = 0.f;
        #pragma unroll
        for (int i = 0; i < 8; i++) v += s_red[i];
        g_lad[b*256 + bx] = v;
        __threadfence();
        unsigned old = atomicAdd(&g_tick[b], 1u);
        s_last = (old == 255u) ? 1u : 0u;
    }
    __syncthreads();

    // last CTA of this image performs the final logdet reduction (deterministic)
    if (s_last && w == 0) {
        __threadfence();
        float v = 0.f;
        #pragma unroll
        for (int i = 0; i < 8; i++) v += g_lad[b*256 + i*32 + lane];
        #pragma unroll
        for (int o = 16; o > 0; o >>= 1)
            v += __shfl_down_sync(0xffffffffu, v, o);
        if (lane == 0) out[XOUT_SIZE + b] = logdet_in[b] + v;
    }
}

// ---------------------------------------------------------------------------
extern "C" void kernel_launch(void* const* d_in, const int* in_sizes, int n_in,
                              void* d_out, int out_size) {
    const float* x      = (const float*)d_in[0];
    const float* logdet = (const float*)d_in[1];
    const float* cond   = (const float*)d_in[2];
    const float* W1     = (const float*)d_in[3];
    const float* b1     = (const float*)d_in[4];
    const float* W2     = (const float*)d_in[5];
    const float* b2     = (const float*)d_in[6];
    const float* W3     = (const float*)d_in[7];
    const float* b3     = (const float*)d_in[8];
    float* out = (float*)d_out;

    const int smem3 = A_BYTES + 3 * TSLOT;        // 111,456 B
    cudaFuncSetAttribute(k_conv12, cudaFuncAttributeMaxDynamicSharedMemorySize, SM12_BYTES);
    cudaFuncSetAttribute(k_conv3_mma, cudaFuncAttributeMaxDynamicSharedMemorySize, smem3);

    k_trans<<<26, 256>>>(W1, W2);
    k_conv12<<<dim3(128, 16), 256, SM12_BYTES>>>(x, cond, b1, b2, W3);
    k_conv3_mma<<<dim3(256, 16), 256, smem3>>>(x, logdet, b3, out);
}

// round 15
// speedup vs baseline: 7.6291x; 1.0744x over previous
#include <cuda_runtime.h>
#include <cuda_bf16.h>
#include <math.h>
#include <stdint.h>

// Problem constants
#define XOUT_SIZE (16*12*128*128)
#define A_ROW 18720                 // one padded h2 row: 130 entries x 144 B

// Scratch (device globals — no cudaMalloc allowed)
__device__ __align__(16) char g_h2p[16*128*A_ROW];       // conv2 out, PADDED rows
__device__ __align__(16) uint32_t g_W1Fh[9*8*64];        // conv1 bf16 B-frags
__device__ __align__(16) uint32_t g_W2Fh[4*8*64];        // conv2 bf16 B-frags
__device__ __align__(16) uint32_t g_W3Bh[9*2*2*2*2*576]; // [tap][hh][ih][kk][qq][576w]
__device__ float g_lad[16*256];                          // per-(image,row,half) partials
__device__ unsigned g_tick[16];                          // per-image tickets

// ---------------------------------------------------------------------------
// helpers
// ---------------------------------------------------------------------------
__device__ __forceinline__ uint32_t s2u(const void* p){
    uint32_t a;
    asm("{ .reg .u64 t; cvta.to.shared.u64 t, %1; cvt.u32.u64 %0, t; }" : "=r"(a) : "l"(p));
    return a;
}
__device__ __forceinline__ void cp16(uint32_t dst, const void* src, uint32_t sz){
    asm volatile("cp.async.cg.shared.global [%0], [%1], 16, %2;"
                 :: "r"(dst), "l"(src), "r"(sz) : "memory");
}
#define CP_COMMIT() asm volatile("cp.async.commit_group;" ::: "memory")

#define MBI(a,c)  asm volatile("mbarrier.init.shared.b64 [%0], %1;" :: "r"(a), "r"(c) : "memory")
#define METX(a,n) asm volatile("mbarrier.arrive.expect_tx.shared.b64 _, [%0], %1;" :: "r"(a), "r"(n) : "memory")
#define BULK_G2S(dst,src,sz,mb) \
    asm volatile("cp.async.bulk.shared::cluster.global.mbarrier::complete_tx::bytes [%0], [%1], %2, [%3];" \
                 :: "r"(dst), "l"(src), "r"(sz), "r"(mb) : "memory")

#define WAIT_PARITY(mbar, ph) do { \
    uint32_t _m=(uint32_t)(mbar), _p=(uint32_t)(ph), _d; \
    asm volatile("{\n\t.reg .pred p;\n\t" \
        "mbarrier.try_wait.parity.acquire.cta.shared::cta.b64 p, [%1], %2;\n\t" \
        "selp.b32 %0,1,0,p;\n\t}" : "=r"(_d) : "r"(_m), "r"(_p) : "memory"); \
    while(!_d){ \
        asm volatile("{\n\t.reg .pred p;\n\t" \
            "mbarrier.try_wait.parity.acquire.cta.shared::cta.b64 p, [%1], %2, 0x989680;\n\t" \
            "selp.b32 %0,1,0,p;\n\t}" : "=r"(_d) : "r"(_m), "r"(_p) : "memory"); } \
} while(0)

__device__ __forceinline__ void mma_bf16(float* d, uint32_t a0, uint32_t a1,
                                         uint32_t a2, uint32_t a3,
                                         uint32_t b0, uint32_t b1){
    asm volatile(
        "mma.sync.aligned.m16n8k16.row.col.f32.bf16.bf16.f32 "
        "{%0,%1,%2,%3}, {%4,%5,%6,%7}, {%8,%9}, {%0,%1,%2,%3};"
        : "+f"(d[0]), "+f"(d[1]), "+f"(d[2]), "+f"(d[3])
        : "r"(a0), "r"(a1), "r"(a2), "r"(a3), "r"(b0), "r"(b1));
}

__device__ __forceinline__ void ldsm4(uint32_t& r0, uint32_t& r1,
                                      uint32_t& r2, uint32_t& r3, uint32_t addr){
    asm volatile("ldmatrix.sync.aligned.m8n8.x4.shared.b16 {%0,%1,%2,%3}, [%4];"
        : "=r"(r0), "=r"(r1), "=r"(r2), "=r"(r3) : "r"(addr));
}

// ---------------------------------------------------------------------------
// k_trans: W1/W2 bf16 fragment packing + ticket reset.
// ---------------------------------------------------------------------------
__global__ void k_trans(const float* __restrict__ W1,
                        const float* __restrict__ W2) {
    int i = blockIdx.x * 256 + threadIdx.x;
    if (i < 16) g_tick[i] = 0u;
    if (i < 4608) {
        int tile = i >> 6; int l2 = i & 63;
        int tap = tile >> 3, nt = tile & 7;
        int lane = l2 >> 1, reg = l2 & 1;
        int oc  = nt*8 + (lane >> 2);
        int ic0 = 2*(lane & 3) + reg*8;
        __nv_bfloat162 w = __floats2bfloat162_rn(
            W1[oc*144 + ic0*9 + tap], W1[oc*144 + (ic0+1)*9 + tap]);
        g_W1Fh[i] = *(uint32_t*)&w;
    }
    int j = i - 4608;
    if (j >= 0 && j < 2048) {
        int tile = j >> 6; int l2 = j & 63;
        int kk = tile >> 3, nt = tile & 7;
        int lane = l2 >> 1, reg = l2 & 1;
        int oc  = nt*8 + (lane >> 2);
        int ic0 = kk*16 + 2*(lane & 3) + reg*8;
        __nv_bfloat162 w = __floats2bfloat162_rn(W2[oc*64 + ic0], W2[oc*64 + ic0 + 1]);
        g_W2Fh[j] = *(uint32_t*)&w;
    }
}

// ---------------------------------------------------------------------------
// Fused conv1+conv2 bf16 (validated R13/R14) + distributed W3 pack (new order)
// + PADDED h2 output rows (130 x 144 B, zero borders) for conv3 bulk loads.
// smem: z 18720 @0 | B1 18432 @18720 | B2 8192 @37152 ; A2 (pitch 144) and
// the 18720-B padded staging both reuse the z region. 3 CTAs/SM.
// ---------------------------------------------------------------------------
#define Z_PITCH 48
#define A2_PITCH 144
#define B1_OFF 18720u
#define B2_OFF 37152u
#define SM12_BYTES 45344

__global__ void __launch_bounds__(256, 3) k_conv12(const float* __restrict__ x,
                                                   const float* __restrict__ cond,
                                                   const float* __restrict__ b1,
                                                   const float* __restrict__ b2,
                                                   const float* __restrict__ W3) {
    extern __shared__ float dyn[];
    __shared__ float s_b1[64], s_b2[64];

    int b  = blockIdx.y;
    int gr = blockIdx.x;
    int t  = threadIdx.x;
    int w = t >> 5, lane = t & 31;
    int g = lane >> 2, tig = lane & 3;
    int px0 = (w & 3) * 32;
    int nc0 = (w >> 2) * 32;
    int ntb = (w >> 2) * 4;
    int lanRow = (lane & 7) + ((lane >> 3) & 1) * 8;
    int lanCol = ((lane >> 4) & 1) * 16;

    char* sm = (char*)dyn;
    uint32_t smb = s2u(sm);

    // ---- distributed W3 fragment packing (new [tap][hh][ih][kk][qq] order) ----
    {
        int m = (b*128 + gr)*256 + t;
        if (m < 9*9216) {
            int tap = m / 9216;  int r1 = m - tap*9216;
            int hh  = r1 / 4608; int r2 = r1 - hh*4608;
            int ih  = r2 / 2304; int r3 = r2 - ih*2304;
            int kk  = r3 / 1152; int r4a = r3 - kk*1152;
            int qq  = r4a / 576; int r4 = r4a - qq*576;
            int lne, reg, ntl;
            if (r4 < 512) {
                int pp = r4 >> 7; int ww = r4 & 127;
                lne = ww >> 2; int wsel = ww & 3;
                ntl = 2*pp + (wsel >> 1); reg = wsel & 1;
            } else {
                int r5 = r4 - 512;
                lne = r5 >> 1; reg = r5 & 1; ntl = 8;
            }
            int nt  = qq*9 + ntl;
            int n   = hh*144 + nt*8 + (lne >> 2);
            int ic0 = ih*32 + kk*16 + 2*(lne & 3) + reg*8;
            int c   = n / 24, s = n - c*24;
            float lo = 0.f, hi = 0.f;
            if (s < 23) {
                lo = W3[(c*23 + s)*576 + ic0*9 + tap];
                hi = W3[(c*23 + s)*576 + (ic0+1)*9 + tap];
            }
            __nv_bfloat162 wv = __floats2bfloat162_rn(lo, hi);
            g_W3Bh[m] = *(uint32_t*)&wv;
        }
    }

    if (t < 64)       s_b1[t] = b1[t];
    else if (t < 128) s_b2[t-64] = b2[t-64];

    for (int i = t; i < 1152; i += 256) cp16(smb + B1_OFF + (uint32_t)(i*16), g_W1Fh + i*4, 16u);
    for (int i = t; i < 512;  i += 256) cp16(smb + B2_OFF + (uint32_t)(i*16), g_W2Fh + i*4, 16u);
    CP_COMMIT();

    // build z tile bf16: [r][pp] 16 ch, pitch 48 B
    for (int i = t; i < 6240; i += 256) {
        int ch = i / 390; int slot = i - ch*390;
        int r = slot / 130; int pp = slot - r*130;
        int row = gr + r - 1, px = pp - 1;
        float v = 0.f;
        if ((unsigned)row < 128u && (unsigned)px < 128u) {
            if (ch < 12)
                v = ((row + px) & 1) ? x[((b*12 + ch) << 14) + (row << 7) + px] : 0.f;
            else
                v = cond[((b*4 + (ch-12)) << 14) + (row << 7) + px];
        }
        *(__nv_bfloat16*)(sm + slot*Z_PITCH + ch*2) = __float2bfloat16(v);
    }
    asm volatile("cp.async.wait_group 0;" ::: "memory");
    __syncthreads();

    // ---- phase 1: conv1 ----
    float d1[32];
    #pragma unroll
    for (int i = 0; i < 32; i++) d1[i] = 0.f;

    #pragma unroll
    for (int tap = 0; tap < 9; tap++) {
        int kh = tap / 3;
        int dw = tap - kh*3 - 1;
        uint32_t A0[4], A1[4];
        uint32_t a0addr = smb + (uint32_t)((kh*130 + 1 + dw + px0 + lanRow)*Z_PITCH + lanCol);
        ldsm4(A0[0], A0[1], A0[2], A0[3], a0addr);
        ldsm4(A1[0], A1[1], A1[2], A1[3], a0addr + 16u*Z_PITCH);
        const uint32_t* bB = (const uint32_t*)(sm + B1_OFF) + (tap*8 + ntb)*64 + lane*2;
        #pragma unroll
        for (int ntl = 0; ntl < 4; ntl++) {
            uint2 bb = *(const uint2*)(bB + ntl*64);
            mma_bf16(&d1[ntl*8],     A0[0], A0[1], A0[2], A0[3], bb.x, bb.y);
            mma_bf16(&d1[ntl*8 + 4], A1[0], A1[1], A1[2], A1[3], bb.x, bb.y);
        }
    }

    // epilogue 1: relu+bias -> bf16 A2 (pitch 144, overwrites z)
    __syncthreads();
    #pragma unroll
    for (int mm = 0; mm < 2; mm++) {
        int row = px0 + mm*16 + g;
        #pragma unroll
        for (int ntl = 0; ntl < 4; ntl++) {
            int col = nc0 + ntl*8 + 2*tig;
            float bb0 = s_b1[col], bb1 = s_b1[col+1];
            __nv_bfloat162 v0 = __floats2bfloat162_rn(
                fmaxf(d1[ntl*8+mm*4+0] + bb0, 0.f), fmaxf(d1[ntl*8+mm*4+1] + bb1, 0.f));
            __nv_bfloat162 v1 = __floats2bfloat162_rn(
                fmaxf(d1[ntl*8+mm*4+2] + bb0, 0.f), fmaxf(d1[ntl*8+mm*4+3] + bb1, 0.f));
            *(uint32_t*)(sm +  row     *A2_PITCH + col*2) = *(uint32_t*)&v0;
            *(uint32_t*)(sm + (row + 8)*A2_PITCH + col*2) = *(uint32_t*)&v1;
        }
    }
    __syncthreads();

    // ---- phase 2: conv2 ----
    float d2[32];
    #pragma unroll
    for (int i = 0; i < 32; i++) d2[i] = 0.f;

    #pragma unroll
    for (int kk = 0; kk < 4; kk++) {
        uint32_t A0[4], A1[4];
        uint32_t aaddr = smb + (uint32_t)((px0 + lanRow)*A2_PITCH + kk*32 + lanCol);
        ldsm4(A0[0], A0[1], A0[2], A0[3], aaddr);
        ldsm4(A1[0], A1[1], A1[2], A1[3], aaddr + 16u*A2_PITCH);
        const uint32_t* bB = (const uint32_t*)(sm + B2_OFF) + (kk*8 + ntb)*64 + lane*2;
        #pragma unroll
        for (int ntl = 0; ntl < 4; ntl++) {
            uint2 bb = *(const uint2*)(bB + ntl*64);
            mma_bf16(&d2[ntl*8],     A0[0], A0[1], A0[2], A0[3], bb.x, bb.y);
            mma_bf16(&d2[ntl*8 + 4], A1[0], A1[1], A1[2], A1[3], bb.x, bb.y);
        }
    }

    // epilogue 2: relu+bias -> PADDED bf16 staging (entries px+1, pitch 144)
    __syncthreads();
    if (t < 9)            *(uint4*)(sm + t*16) = make_uint4(0,0,0,0);          // entry 0
    else if (t < 18)      *(uint4*)(sm + 18576 + (t-9)*16) = make_uint4(0,0,0,0); // entry 129
    #pragma unroll
    for (int mm = 0; mm < 2; mm++) {
        int row = px0 + mm*16 + g;
        #pragma unroll
        for (int ntl = 0; ntl < 4; ntl++) {
            int col = nc0 + ntl*8 + 2*tig;
            float bb0 = s_b2[col], bb1 = s_b2[col+1];
            __nv_bfloat162 h0 = __floats2bfloat162_rn(
                fmaxf(d2[ntl*8+mm*4+0] + bb0, 0.f), fmaxf(d2[ntl*8+mm*4+1] + bb1, 0.f));
            __nv_bfloat162 h1v = __floats2bfloat162_rn(
                fmaxf(d2[ntl*8+mm*4+2] + bb0, 0.f), fmaxf(d2[ntl*8+mm*4+3] + bb1, 0.f));
            *(uint32_t*)(sm + (row + 1)*144 + col*2) = *(uint32_t*)&h0;
            *(uint32_t*)(sm + (row + 9)*144 + col*2) = *(uint32_t*)&h1v;
        }
    }
    __syncthreads();
    {
        const uint4* s4 = (const uint4*)sm;
        uint4* dst = (uint4*)(g_h2p + (size_t)(b*128 + gr) * A_ROW);
        for (int i = t; i < 1170; i += 256) dst[i] = s4[i];
    }
}

// ---------------------------------------------------------------------------
// RQS spline (validated R1)
// ---------------------------------------------------------------------------
__device__ __forceinline__ float rqs_eval(const float* p, float xa, float& lad) {
    bool inside = (xa >= -3.f) && (xa <= 3.f);
    float xc = fminf(fmaxf(xa, -3.f), 3.f);

    float mw = p[0], mh = p[8];
    #pragma unroll
    for (int k = 1; k < 8; k++) { mw = fmaxf(mw, p[k]); mh = fmaxf(mh, p[8+k]); }
    float ew[8], eh[8]; float sw = 0.f, sh = 0.f;
    #pragma unroll
    for (int k = 0; k < 8; k++) {
        ew[k] = expf(p[k] - mw);   sw += ew[k];
        eh[k] = expf(p[8+k] - mh); sh += eh[k];
    }
    float rw = (1.f - 0.008f) / sw;
    float rh = (1.f - 0.008f) / sh;

    float sp[7];
    #pragma unroll
    for (int k = 0; k < 7; k++) {
        float u = p[16 + k];
        sp[k] = (u > 15.f) ? u : log1pf(expf(u));
    }

    float cw = -3.f, ch = -3.f, cumw = 0.f, cumh = 0.f, dprev = 1.f;
    float icw = -3.f, iw = 1.f, ich = -3.f, ih = 1.f, id0 = 1.f, id1 = 1.f;
    #pragma unroll
    for (int k = 0; k < 8; k++) {
        cumw += 0.001f + ew[k]*rw;
        cumh += 0.001f + eh[k]*rh;
        float cwn = (k == 7) ? 3.f : fmaf(6.f, cumw, -3.f);
        float chn = (k == 7) ? 3.f : fmaf(6.f, cumh, -3.f);
        float dn  = (k == 7) ? 1.f : (0.001f + sp[k]);
        if (xc >= cw) { icw = cw; iw = cwn - cw; ich = ch; ih = chn - ch; id0 = dprev; id1 = dn; }
        cw = cwn; ch = chn; dprev = dn;
    }

    float riw   = 1.f / iw;
    float delta = ih * riw;
    float theta = (xc - icw) * riw;
    float omt = 1.f - theta;
    float t1  = theta * omt;
    float th2 = theta * theta;
    float num = ih * (delta*th2 + id0*t1);
    float den = delta + (id0 + id1 - 2.f*delta)*t1;
    float y   = ich + num / den;
    float dnum = delta*delta*(id1*th2 + 2.f*delta*t1 + id0*omt*omt);
    float l = logf(dnum) - 2.f*logf(den);

    lad = inside ? l : 0.f;
    return inside ? y : xa;
}

// ---------------------------------------------------------------------------
// conv3 bf16 MMA: bulk-loaded resident A + bulk per-tap B ring (mbarrier) +
// ldmatrix A-frags + LDS.128-paired B-frags + fused logdet reduction.
// CTA = (image row, N-half). smem = 56160 (A) + 3*18432 (B) = 111,456 B.
// ---------------------------------------------------------------------------
#define A_BYTES   56160u
#define TSLOT 18432u

__global__ void __launch_bounds__(256, 2) k_conv3_mma(const float* __restrict__ x,
                                                      const float* __restrict__ logdet_in,
                                                      const float* __restrict__ b3,
                                                      float* __restrict__ out) {
    extern __shared__ float dyn[];
    __shared__ __align__(8) uint64_t s_mbar[4];   // [0]=A, [1..3]=B slots
    __shared__ float s_b3[276];
    __shared__ float s_red[8];
    __shared__ unsigned s_last;

    int b  = blockIdx.y;
    int bx = blockIdx.x;
    int gr = bx >> 1;
    int hh = bx & 1;
    int t  = threadIdx.x;
    int w = t >> 5, lane = t & 31;
    int g = lane >> 2, tig = lane & 3;
    int px0 = (w & 3) * 32;
    int qq  = w >> 2;

    char* sA = (char*)dyn;
    uint32_t sAu = s2u(sA);
    uint32_t baseB = sAu + A_BYTES;
    uint32_t mA = s2u(&s_mbar[0]);

    for (int i = t; i < 276; i += 256) s_b3[i] = b3[i];

    if (t == 0) {
        MBI(mA, 1);
        MBI(s2u(&s_mbar[1]), 1);
        MBI(s2u(&s_mbar[2]), 1);
        MBI(s2u(&s_mbar[3]), 1);
    }
    __syncthreads();

    // A: bulk-load rows gr-1..gr+1 from padded gmem; OOB rows zero-filled
    int nvalid = 3 - (gr == 0) - (gr == 127);
    if (t == 0) {
        METX(mA, (uint32_t)(nvalid * A_ROW));
        #pragma unroll
        for (int r = 0; r < 3; r++) {
            int row = gr + r - 1;
            if ((unsigned)row < 128u)
                BULK_G2S(sAu + (uint32_t)(r * A_ROW),
                         g_h2p + (size_t)(b*128 + row) * A_ROW,
                         (uint32_t)A_ROW, mA);
        }
        // B taps 0..2
        #pragma unroll
        for (int tp = 0; tp < 3; tp++) {
            uint32_t mB = s2u(&s_mbar[1 + tp]);
            METX(mB, TSLOT);
            BULK_G2S(baseB + (uint32_t)tp * TSLOT,
                     (const char*)g_W3Bh + (size_t)(gr*0 + (2*tp + hh)) * 0 +
                         (size_t)(tp*2 + hh) * TSLOT,
                     TSLOT, mB);
        }
    }
    if (gr == 0) {
        uint4* z = (uint4*)sA;
        for (int i = t; i < 1170; i += 256) z[i] = make_uint4(0,0,0,0);
    } else if (gr == 127) {
        uint4* z = (uint4*)(sA + 2*A_ROW);
        for (int i = t; i < 1170; i += 256) z[i] = make_uint4(0,0,0,0);
    }
    WAIT_PARITY(mA, 0u);
    __syncthreads();

    float d[72];
    #pragma unroll
    for (int i = 0; i < 72; i++) d[i] = 0.f;

    uint32_t aBase = sAu
        + (uint32_t)((1 + px0 + (lane & 7) + ((lane >> 3) & 1)*8) * 144
                     + ((lane >> 4) & 1)*16);

    for (int tp = 0; tp < 9; tp++) {
        WAIT_PARITY(s2u(&s_mbar[1 + tp % 3]), (uint32_t)((tp / 3) & 1));

        int kh = tp / 3;
        int dw = tp - kh*3 - 1;
        uint32_t aTap = aBase + (uint32_t)(kh*A_ROW + dw*144);
        const char* sBq = (const char*)dyn + A_BYTES + (size_t)(tp % 3)*TSLOT
                          + (size_t)qq * 2304;

        #pragma unroll
        for (int ih = 0; ih < 2; ih++) {
            #pragma unroll
            for (int kk = 0; kk < 2; kk++) {
                uint32_t A0[4], A1[4];
                uint32_t ao = aTap + (uint32_t)(ih*64 + kk*32);
                ldsm4(A0[0], A0[1], A0[2], A0[3], ao);
                ldsm4(A1[0], A1[1], A1[2], A1[3], ao + 2304u);
                const char* bp = sBq + (size_t)ih*9216 + (size_t)kk*4608;
                #pragma unroll
                for (int pp = 0; pp < 4; pp++) {
                    uint4 bb = *(const uint4*)(bp + pp*512 + lane*16);
                    int n0 = pp*16;
                    mma_bf16(&d[n0],      A0[0], A0[1], A0[2], A0[3], bb.x, bb.y);
                    mma_bf16(&d[n0 + 4],  A1[0], A1[1], A1[2], A1[3], bb.x, bb.y);
                    mma_bf16(&d[n0 + 8],  A0[0], A0[1], A0[2], A0[3], bb.z, bb.w);
                    mma_bf16(&d[n0 + 12], A1[0], A1[1], A1[2], A1[3], bb.z, bb.w);
                }
                uint2 b8 = *(const uint2*)(bp + 2048 + lane*8);
                mma_bf16(&d[64], A0[0], A0[1], A0[2], A0[3], b8.x, b8.y);
                mma_bf16(&d[68], A1[0], A1[1], A1[2], A1[3], b8.x, b8.y);
            }
        }

        __syncthreads();   // all warps done with slot tp%3
        if (tp < 6 && t == 0) {
            int nt = tp + 3;
            uint32_t mB = s2u(&s_mbar[1 + tp % 3]);
            METX(mB, TSLOT);
            BULK_G2S(baseB + (uint32_t)(tp % 3) * TSLOT,
                     (const char*)g_W3Bh + (size_t)(nt*2 + hh) * TSLOT,
                     TSLOT, mB);
        }
    }

    // epilogue: accumulators -> sD (reuses A region) -> spline
    __syncthreads();
    {
        float* sD = dyn;
        #pragma unroll
        for (int m = 0; m < 2; m++) {
            int row0 = px0 + m*16 + g;
            #pragma unroll
            for (int nt = 0; nt < 9; nt++) {
                int col = qq*72 + nt*8 + 2*tig;
                sD[ row0      * 145 + col    ] = d[nt*8 + m*4 + 0];
                sD[ row0      * 145 + col + 1] = d[nt*8 + m*4 + 1];
                sD[(row0 + 8) * 145 + col    ] = d[nt*8 + m*4 + 2];
                sD[(row0 + 8) * 145 + col + 1] = d[nt*8 + m*4 + 3];
            }
        }
    }
    __syncthreads();

    float ladsum = 0.f;
    {
        const float* sD = dyn;
        int px = t & 127;
        int clbase = (t >> 7) * 3;
        int par = (gr + px) & 1;
        #pragma unroll
        for (int cc = 0; cc < 3; cc++) {
            int cl = clbase + cc;
            int c  = hh*6 + cl;
            float p[23];
            #pragma unroll
            for (int sidx = 0; sidx < 23; sidx++)
                p[sidx] = sD[px*145 + cl*24 + sidx] + s_b3[c*23 + sidx];

            size_t xbase = (((size_t)(b*12 + c)) << 14) + ((size_t)gr << 7) + px;
            float xv = x[xbase];
            float xa = par ? 0.f : xv;
            float xf = par ? xv : 0.f;
            float lad;
            float y = rqs_eval(p, xa, lad);
            out[xbase] = xf + y;
            ladsum += lad;
        }
    }
    #pragma unroll
    for (int o = 16; o > 0; o >>= 1)
        ladsum += __shfl_down_sync(0xffffffffu, ladsum, o);
    if (lane == 0) s_red[w] = ladsum;
    __syncthreads();
    if (t == 0) {
        float v = 0.f;
        #pragma unroll
        for (int i = 0; i < 8; i++) v += s_red[i];
        g_lad[b*256 + bx] = v;
        __threadfence();
        unsigned old = atomicAdd(&g_tick[b], 1u);
        s_last = (old == 255u) ? 1u : 0u;
    }
    __syncthreads();

    if (s_last && w == 0) {
        __threadfence();
        float v = 0.f;
        #pragma unroll
        for (int i = 0; i < 8; i++) v += g_lad[b*256 + i*32 + lane];
        #pragma unroll
        for (int o = 16; o > 0; o >>= 1)
            v += __shfl_down_sync(0xffffffffu, v, o);
        if (lane == 0) out[XOUT_SIZE + b] = logdet_in[b] + v;
    }
}

// ---------------------------------------------------------------------------
extern "C" void kernel_launch(void* const* d_in, const int* in_sizes, int n_in,
                              void* d_out, int out_size) {
    const float* x      = (const float*)d_in[0];
    const float* logdet = (const float*)d_in[1];
    const float* cond   = (const float*)d_in[2];
    const float* W1     = (const float*)d_in[3];
    const float* b1     = (const float*)d_in[4];
    const float* W2     = (const float*)d_in[5];
    const float* b2     = (const float*)d_in[6];
    const float* W3     = (const float*)d_in[7];
    const float* b3     = (const float*)d_in[8];
    float* out = (float*)d_out;

    const int smem3 = A_BYTES + 3 * TSLOT;        // 111,456 B
    cudaFuncSetAttribute(k_conv12, cudaFuncAttributeMaxDynamicSharedMemorySize, SM12_BYTES);
    cudaFuncSetAttribute(k_conv3_mma, cudaFuncAttributeMaxDynamicSharedMemorySize, smem3);

    k_trans<<<26, 256>>>(W1, W2);
    k_conv12<<<dim3(128, 16), 256, SM12_BYTES>>>(x, cond, b1, b2, W3);
    k_conv3_mma<<<dim3(256, 16), 256, smem3>>>(x, logdet, b3, out);
}